// round 11
// baseline (speedup 1.0000x reference)
#include <cuda_runtime.h>
#include <cuda_bf16.h>
#include <math.h>

#define B_ 16
#define T_ 2048
#define N_ 64

// Output layout (flattened tuple in order)
#define SEED_OFF 0
#define GCN_OFF  2097152
#define FREQ_OFF 4194304
#define IMP_OFF  6291456
#define COMP_OFF 8388608
#define GATE_OFF 10485760
#define ADJ_OFF  14680064

typedef unsigned long long u64;
typedef unsigned int u32;

// Scratch (static device arrays: allowed)
// Chunk-summary scratch TRANSPOSED: s = (b*64 + n)*64 + c
__device__ float  g_adj[N_ * N_];
__device__ float2 g_preb1p[32 * N_];
__device__ float  g_first[65536], g_last[65536];
__device__ unsigned char g_has[65536];
__device__ float  g_seedT[B_ * N_ * T_];        // [b][n][t]
__device__ float  g_freT[N_ * 1025];            // [n][k]
__device__ float  g_fimT[N_ * 1025];

// ---- packed f32x2 helpers ---------------------------------------------------
__device__ __forceinline__ u64 pk2(float lo, float hi) {
    u64 r; asm("mov.b64 %0, {%1, %2};" : "=l"(r) : "f"(lo), "f"(hi)); return r;
}
__device__ __forceinline__ void upk2(u64 v, float& lo, float& hi) {
    asm("mov.b64 {%0, %1}, %2;" : "=f"(lo), "=f"(hi) : "l"(v));
}
__device__ __forceinline__ u64 ffma2(u64 a, u64 b, u64 c) {
    u64 d; asm("fma.rn.f32x2 %0, %1, %2, %3;" : "=l"(d) : "l"(a), "l"(b), "l"(c)); return d;
}
__device__ __forceinline__ u64 mul2(u64 a, u64 b) {
    u64 d; asm("mul.rn.f32x2 %0, %1, %2;" : "=l"(d) : "l"(a), "l"(b)); return d;
}

__device__ __forceinline__ float tanh_ap(float x) {
    float t; asm("tanh.approx.f32 %0, %1;" : "=f"(t) : "f"(x)); return t;
}

// packed pairwise gelu
__device__ __forceinline__ u64 gelu2(u64 x) {
    const u64 C1 = pk2(0.035677408136f, 0.035677408136f);
    const u64 C0 = pk2(0.7978845608028654f, 0.7978845608028654f);
    const u64 H  = pk2(0.5f, 0.5f);
    u64 x2 = mul2(x, x);
    u64 inner = ffma2(x2, C1, C0);
    u64 b = mul2(x, inner);
    float b0, b1; upk2(b, b0, b1);
    u64 t = pk2(tanh_ap(b0), tanh_ap(b1));
    u64 hx = mul2(x, H);
    return ffma2(hx, t, hx);
}

__device__ __forceinline__ u32 to_tf32(float v) {
    u32 r; asm("cvt.rna.tf32.f32 %0, %1;" : "=r"(r) : "f"(v)); return r;
}

__device__ __forceinline__ void mma_tf32(float* d,
    u32 a0, u32 a1, u32 a2, u32 a3, u32 b0, u32 b1)
{
    asm("mma.sync.aligned.m16n8k8.row.col.f32.tf32.tf32.f32 "
        "{%0,%1,%2,%3}, {%4,%5,%6,%7}, {%8,%9}, {%0,%1,%2,%3};"
        : "+f"(d[0]), "+f"(d[1]), "+f"(d[2]), "+f"(d[3])
        : "r"(a0), "r"(a1), "r"(a2), "r"(a3), "r"(b0), "r"(b1));
}

#define BARP(id) asm volatile("bar.sync %0, %1;" :: "r"(id), "r"(64) : "memory")

// ---------------------------------------------------------------------------
// Kernel 0: prep = fill_sum (blk<256) + filter transpose (blk 256-319)
//                + adjacency/preb1 (blk 320). All independent.
// ---------------------------------------------------------------------------
__global__ void __launch_bounds__(256) prep_kernel(
    const float* __restrict__ x, const float* __restrict__ mask,
    const float* __restrict__ emb, const int* __restrict__ rate_id,
    const float* __restrict__ rate_table, const float* __restrict__ gw1,
    const float* __restrict__ gb1,
    const float* __restrict__ fre, const float* __restrict__ fim,
    float* __restrict__ out_adj)
{
    int blk = blockIdx.x;
    int tid = threadIdx.x;

    if (blk < 256) {
        int g = blk * 256 + tid;
        int n = g & 63;
        int c = (g >> 6) & 63;
        int b = g >> 12;
        int base = ((b * T_) + c * 32) * N_ + n;
        float first = 0.f, last = 0.f; bool has = false;
        #pragma unroll
        for (int t = 0; t < 32; ++t) {
            int idx = base + t * N_;
            float v = x[idx];
            bool obs = (mask[idx] == 0.f);
            if (obs) { if (!has) first = v; last = v; has = true; }
        }
        int s = ((b << 6) + n) * 64 + c;
        g_first[s] = first; g_last[s] = last; g_has[s] = (unsigned char)has;
        return;
    }

    if (blk < 320) {
        int n = blk - 256;
        for (int k = tid; k < 1025; k += 256) {
            g_freT[n * 1025 + k] = fre[(size_t)k * N_ + n];
            g_fimT[n * 1025 + k] = fim[(size_t)k * N_ + n];
        }
        return;
    }

    // adjacency + rate-embed pre-bias (threads 0-63)
    __shared__ float sE[64 * 32];
    for (int i = tid; i < 64 * 32; i += 256) sE[i] = emb[i];
    __syncthreads();
    if (tid >= 64) return;

    float sc[64];
    float mx = -1e30f;
    #pragma unroll
    for (int m = 0; m < 64; ++m) {
        float d = 0.f;
        #pragma unroll
        for (int h = 0; h < 32; ++h) d = fmaf(sE[tid * 32 + h], sE[m * 32 + h], d);
        d = fmaxf(d, 0.f);
        sc[m] = d; mx = fmaxf(mx, d);
    }
    float sum = 0.f;
    #pragma unroll
    for (int m = 0; m < 64; ++m) { float e = __expf(sc[m] - mx); sc[m] = e; sum += e; }
    float inv = 1.0f / sum;
    #pragma unroll
    for (int m = 0; m < 64; ++m) {
        float a = sc[m] * inv;
        g_adj[tid * 64 + m] = a;
        out_adj[tid * 64 + m] = a;
    }
    int rid = rate_id[tid];
    for (int j2 = 0; j2 < 32; ++j2) {
        float v0 = gb1[2 * j2], v1 = gb1[2 * j2 + 1];
        #pragma unroll
        for (int e = 0; e < 16; ++e) {
            float rt = rate_table[rid * 16 + e];
            v0 = fmaf(rt, gw1[(6 + e) * 64 + 2 * j2], v0);
            v1 = fmaf(rt, gw1[(6 + e) * 64 + 2 * j2 + 1], v1);
        }
        g_preb1p[j2 * 64 + tid] = make_float2(v0, v1);
    }
}

// ---------------------------------------------------------------------------
// Kernel 1: fill_out v2 — in-block scan + fill phase.
// ---------------------------------------------------------------------------
__global__ void __launch_bounds__(256) fill_out_kernel(
    const float* __restrict__ x, const float* __restrict__ mask,
    float* __restrict__ seed)
{
    __shared__ float sPr[256], sSu[256];
    __shared__ unsigned char sPrh[256], sSuh[256];

    int blk = blockIdx.x;
    int b = blk >> 4;
    int c0 = (blk & 15) * 4;
    int tid = threadIdx.x;

    if (tid < 64) {
        int bn = (b << 6) + tid;
        const float* fp = g_first + bn * 64;
        const float* lp = g_last + bn * 64;
        const unsigned char* hp = g_has + bn * 64;
        float pv = 0.f; bool ph = false;
        #pragma unroll 8
        for (int c = 0; c < 64; ++c) {
            unsigned d = (unsigned)(c - c0);
            if (d < 4u) { sPr[d * 64 + tid] = pv; sPrh[d * 64 + tid] = (unsigned char)ph; }
            if (hp[c]) { pv = lp[c]; ph = true; }
        }
        float sv = 0.f; bool sh = false;
        #pragma unroll 8
        for (int c = 63; c >= 0; --c) {
            unsigned d = (unsigned)(c - c0);
            if (d < 4u) { sSu[d * 64 + tid] = sv; sSuh[d * 64 + tid] = (unsigned char)sh; }
            if (hp[c]) { sv = fp[c]; sh = true; }
        }
    }
    __syncthreads();

    int n = tid & 63;
    int cl = tid >> 6;
    int c = c0 + cl;
    int base = ((b * T_) + c * 32) * N_ + n;
    float* tdst = g_seedT + ((size_t)(b * 64 + n)) * T_ + c * 32;

    float fv = sPr[cl * 64 + n]; bool fh = (bool)sPrh[cl * 64 + n];
    float vals[32];
    unsigned obsm = 0u, fam = 0u;
    #pragma unroll
    for (int t = 0; t < 32; ++t) {
        int idx = base + t * N_;
        float v = x[idx];
        bool obs = (mask[idx] == 0.f);
        if (obs) { fv = v; fh = true; obsm |= (1u << t); }
        vals[t] = fv;
        if (fh) fam |= (1u << t);
    }
    float bv = sSu[cl * 64 + n]; bool bh = (bool)sSuh[cl * 64 + n];
    #pragma unroll
    for (int t = 31; t >= 0; --t) {
        bool obs = (obsm >> t) & 1u;
        bool fa  = (fam  >> t) & 1u;
        float v = vals[t];
        if (obs) { bv = v; bh = true; }
        float out;
        if (obs)            out = v;
        else if (fa && bh)  out = 0.5f * (v + bv);
        else if (fa)        out = v;
        else if (bh)        out = bv;
        else                out = 0.f;
        seed[base + t * N_] = out;
        tdst[t] = out;
    }
}

// ---------------------------------------------------------------------------
// Kernel 2: packed-pair radix-2 FFT filter; coalesced loads
// ---------------------------------------------------------------------------
__global__ void __launch_bounds__(256) fft_kernel(
    float* __restrict__ xfreq)
{
    __shared__ float re[2048], im[2048], twr[1024], twi[1024];
    int tid = threadIdx.x;
    int b = blockIdx.x >> 5;
    int p = blockIdx.x & 31;
    int n0 = p * 2;
    const float* src0 = g_seedT + ((size_t)(b * 64 + n0)) * T_;
    const float* src1 = src0 + T_;

    for (int j = tid; j < 1024; j += 256) {
        float s, c;
        sincosf(-6.28318530717958647692f * (float)j * (1.0f / 2048.0f), &s, &c);
        twr[j] = c; twi[j] = s;
    }
    for (int t = tid; t < 2048; t += 256) {
        re[t] = src0[t];
        im[t] = src1[t];
    }

    for (int s = 10; s >= 0; --s) {
        int half = 1 << s;
        __syncthreads();
        for (int bi = tid; bi < 1024; bi += 256) {
            int j = bi & (half - 1);
            int i1 = ((bi >> s) << (s + 1)) | j;
            int i2 = i1 + half;
            int tj = j << (10 - s);
            float wr = twr[tj], wi = twi[tj];
            float ar = re[i1], ai = im[i1], br = re[i2], b2 = im[i2];
            re[i1] = ar + br; im[i1] = ai + b2;
            float dr = ar - br, di = ai - b2;
            re[i2] = dr * wr - di * wi;
            im[i2] = dr * wi + di * wr;
        }
    }
    __syncthreads();

    const float* fT0r = g_freT + n0 * 1025;
    const float* fT0i = g_fimT + n0 * 1025;
    const float* fT1r = fT0r + 1025;
    const float* fT1i = fT0i + 1025;
    for (int k = tid; k <= 1024; k += 256) {
        int km = (2048 - k) & 2047;
        int pk = __brev(k) >> 21;
        int pm = __brev(km) >> 21;
        float zr = re[pk], zi = im[pk];
        float yr = re[pm], yi = im[pm];
        float x1r = 0.5f * (zr + yr), x1i = 0.5f * (zi - yi);
        float x2r = 0.5f * (zi + yi), x2i = 0.5f * (yr - zr);
        float h1r = fT0r[k], h1i = fT0i[k];
        float h2r = fT1r[k], h2i = fT1i[k];
        float y1r = x1r * h1r - x1i * h1i, y1i = x1r * h1i + x1i * h1r;
        float y2r = x2r * h2r - x2i * h2i, y2i = x2r * h2i + x2i * h2r;
        if (k == 0 || k == 1024) { y1i = 0.f; y2i = 0.f; }
        re[pk] = y1r - y2i; im[pk] = y1i + y2r;
        if (k > 0 && k < 1024) { re[pm] = y1r + y2i; im[pm] = y2r - y1i; }
    }

    for (int s = 0; s <= 10; ++s) {
        int half = 1 << s;
        __syncthreads();
        for (int bi = tid; bi < 1024; bi += 256) {
            int j = bi & (half - 1);
            int i1 = ((bi >> s) << (s + 1)) | j;
            int i2 = i1 + half;
            int tj = j << (10 - s);
            float wr = twr[tj], wi = -twi[tj];
            float br = re[i2], b2 = im[i2];
            float tr = br * wr - b2 * wi, ti = br * wi + b2 * wr;
            float ar = re[i1], ai = im[i1];
            re[i1] = ar + tr; im[i1] = ai + ti;
            re[i2] = ar - tr; im[i2] = ai - ti;
        }
    }
    __syncthreads();

    float* dst = xfreq + (size_t)b * T_ * N_ + n0;
    const float scl = 1.0f / 2048.0f;
    for (int t = tid; t < 2048; t += 256) {
        float2 v; v.x = re[t] * scl; v.y = im[t] * scl;
        *(float2*)(dst + (size_t)t * N_) = v;
    }
}

// ---------------------------------------------------------------------------
// Kernel 3 v8: BOTH MLP layers on tensor pipe. 256-thr CTAs, 2/SM.
// Layer1: K=8 tf32 mma (4 folded dynamic features; bias=preb1 via acc init;
//         dynamic A rows alias hs rows 0-3 — per-warp columns, sequential use).
// Barriers: warp-pair bar.sync for phi->gcn only; __syncwarp elsewhere
//           (hs / dyn-A / sXg are warp-local by construction).
// ---------------------------------------------------------------------------
#define FTH 256
#define HS_S 264
#define W2_S 72
#define NTILES (B_ * T_ * N_ / FTH)   // 8192
#define PGRID 296
#define SMEM_BYTES (27588 * 4)

__global__ void __launch_bounds__(FTH, 2) fused_kernel(
    const float* __restrict__ seed, const float* __restrict__ mask,
    const float* __restrict__ xin, const float* __restrict__ xfreq,
    const float* __restrict__ gw1, const float* __restrict__ gw2,
    const float* __restrict__ gb2, const float* __restrict__ gw3,
    const float* __restrict__ gb3,
    const float* __restrict__ gcw1, const float* __restrict__ gcb1,
    const float* __restrict__ gcw2, const float* __restrict__ gcb2,
    float* __restrict__ out_gcn, float* __restrict__ out_imp,
    float* __restrict__ out_comp, float* __restrict__ out_gate)
{
    extern __shared__ float sm[];
    float* hs    = sm;                    // [64][264] tf32 bits; rows 0-3 = dyn A
    float* sW2   = hs    + 64 * HS_S;     // [64][72] tf32
    float* sA    = sW2   + 64 * W2_S;     // [64][66]
    float* w1t   = sA    + 64 * 66;       // [4][72] folded layer1 weights, tf32
    float* sW3e  = w1t   + 4 * 72;        // [32] float2
    float* sW3o  = sW3e  + 64;
    float* sB2   = sW3o  + 64;            // [64]
    float* sGc   = sB2   + 64;            // [96]
    float* sPm   = sGc   + 96;            // [4][64]
    float* sXg   = sPm   + FTH;
    float* sXf   = sXg   + FTH;
    float* sMm   = sXf   + FTH;
    float* sXi   = sMm   + FTH;
    float* sCst  = sXi   + FTH;           // [4]

    int tid = threadIdx.x;

    for (int i = tid; i < 4096; i += FTH) {
        int k = i >> 6, j = i & 63;
        ((u32*)sW2)[k * W2_S + j] = to_tf32(gw2[i]);
    }
    for (int i = tid; i < 4096; i += FTH) sA[(i >> 6) * 66 + (i & 63)] = g_adj[i];
    if (tid < 64) {
        // folded layer1 weights: s, mm, xg, xf
        u32* w1u = (u32*)w1t;
        w1u[0 * 72 + tid] = to_tf32(gw1[0 * 64 + tid] - gw1[4 * 64 + tid] - gw1[5 * 64 + tid]);
        w1u[1 * 72 + tid] = to_tf32(gw1[1 * 64 + tid]);
        w1u[2 * 72 + tid] = to_tf32(gw1[2 * 64 + tid] + gw1[4 * 64 + tid]);
        w1u[3 * 72 + tid] = to_tf32(gw1[3 * 64 + tid] + gw1[5 * 64 + tid]);
        sB2[tid] = gb2[tid];
    }
    if (tid < 32) {
        ((float2*)sW3e)[tid] = make_float2(gw3[4 * tid],     gw3[4 * tid + 2]);
        ((float2*)sW3o)[tid] = make_float2(gw3[4 * tid + 1], gw3[4 * tid + 3]);
        sGc[tid] = gcw1[tid]; sGc[32 + tid] = gcb1[tid]; sGc[64 + tid] = gcw2[tid];
    }
    if (tid == 0) { sCst[0] = gcb2[0]; sCst[1] = gb3[0]; sCst[2] = gb3[1]; }
    __syncthreads();

    int n    = tid & 63;
    int r    = tid >> 6;      // 0..3
    int lane = tid & 31;
    int warp = tid >> 5;      // 0..7
    int m0   = warp * 32;
    int qr   = lane >> 2;     // quad row 0..7
    int qc   = lane & 3;      // quad col 0..3
    int prId = 8 + (tid >> 6);  // named barrier per warp-pair

    u32* hsu = (u32*)hs;
    const u32* w1u = (const u32*)w1t;
    const u64* prebp = (const u64*)g_preb1p;

    for (int tile = blockIdx.x; tile < NTILES; tile += PGRID) {
        BARP(prId);   // partner finished reading sPm of previous tile

        int gidx = tile * FTH + tid;
        float s  = seed[gidx];
        float mm = mask[gidx];
        float xf = xfreq[gidx];
        float xi = xin[gidx];

        // ---- phi(s), packed pairs ----
        u64 sp = pk2(s, s);
        u64 accp = pk2(0.f, 0.f);
        const u64* gcW = (const u64*)sGc;
        const u64* gcB = (const u64*)(sGc + 32);
        const u64* gcV = (const u64*)(sGc + 64);
        #pragma unroll
        for (int hq = 0; hq < 16; ++hq) {
            u64 pre = ffma2(sp, gcW[hq], gcB[hq]);
            accp = ffma2(gelu2(pre), gcV[hq], accp);
        }
        float p0, p1; upk2(accp, p0, p1);
        sPm[r * 64 + n] = p0 + p1;
        BARP(prId);   // pair-wide phi visible

        // ---- x_gcn (packed matvec) ----
        u64 xgp = pk2(0.f, 0.f);
        const u64* arow = (const u64*)(sA + n * 66);
        const u64* prow = (const u64*)(sPm + r * 64);
        #pragma unroll 8
        for (int m2 = 0; m2 < 32; ++m2)
            xgp = ffma2(arow[m2], prow[m2], xgp);
        float xg0, xg1; upk2(xgp, xg0, xg1);
        float xg = xg0 + xg1 + sCst[0];

        sXg[tid] = xg; sXf[tid] = xf; sMm[tid] = mm; sXi[tid] = xi;
        out_gcn[gidx] = xg;

        // ---- dynamic A rows (tf32) into hs rows 0-3 ----
        hsu[0 * HS_S + tid] = to_tf32(s);
        hsu[1 * HS_S + tid] = to_tf32(mm);
        hsu[2 * HS_S + tid] = to_tf32(xg);
        hsu[3 * HS_S + tid] = to_tf32(xf);
        __syncwarp();

        // ---- layer1 via tf32 mma (K=8: 4 real + 4 zero) ----
        float accL[2][8][4];
        #pragma unroll
        for (int mt = 0; mt < 2; ++mt) {
            int rA = (m0 + qr + 16 * mt) & 63;
            int rB = (m0 + qr + 8 + 16 * mt) & 63;
            #pragma unroll
            for (int n8 = 0; n8 < 8; ++n8) {
                int j2 = n8 * 4 + qc;
                u64 pA = __ldg(prebp + j2 * 64 + rA);
                u64 pB = __ldg(prebp + j2 * 64 + rB);
                upk2(pA, accL[mt][n8][0], accL[mt][n8][1]);
                upk2(pB, accL[mt][n8][2], accL[mt][n8][3]);
            }
        }
        {
            int ar = m0 + qr;
            u32 a0_0 = hsu[qc * HS_S + ar],      a1_0 = hsu[qc * HS_S + ar + 8];
            u32 a0_1 = hsu[qc * HS_S + ar + 16], a1_1 = hsu[qc * HS_S + ar + 24];
            #pragma unroll
            for (int n8 = 0; n8 < 8; ++n8) {
                u32 b0 = w1u[qc * 72 + n8 * 8 + qr];
                mma_tf32(accL[0][n8], a0_0, a1_0, 0u, 0u, b0, 0u);
                mma_tf32(accL[1][n8], a0_1, a1_1, 0u, 0u, b0, 0u);
            }
        }
        // layer1 epilogue: gelu -> hs[j][row]
        #pragma unroll
        for (int mt = 0; mt < 2; ++mt)
            #pragma unroll
            for (int n8 = 0; n8 < 8; ++n8)
                #pragma unroll
                for (int half = 0; half < 2; ++half) {
                    u64 g = gelu2(pk2(accL[mt][n8][2 * half], accL[mt][n8][2 * half + 1]));
                    float v0, v1; upk2(g, v0, v1);
                    int j = n8 * 8 + qc * 2;
                    int row = m0 + qr + 8 * half + 16 * mt;
                    hsu[j * HS_S + row]       = to_tf32(v0);
                    hsu[(j + 1) * HS_S + row] = to_tf32(v1);
                }
        __syncwarp();

        // ---- Phase B: layer2 via tf32 mma ----
        float acc[2][8][4];
        #pragma unroll
        for (int n8 = 0; n8 < 8; ++n8) {
            int j0 = n8 * 8 + qc * 2;
            float2 bb = *(const float2*)(sB2 + j0);
            #pragma unroll
            for (int mt = 0; mt < 2; ++mt) {
                acc[mt][n8][0] = bb.x; acc[mt][n8][1] = bb.y;
                acc[mt][n8][2] = bb.x; acc[mt][n8][3] = bb.y;
            }
        }

        const u32* w2u = (const u32*)sW2;
        int ar = m0 + qr;
        #pragma unroll
        for (int k8 = 0; k8 < 8; ++k8) {
            int kb = k8 * 8 + qc;
            const u32* h0 = hsu + kb * HS_S;
            const u32* h4 = hsu + (kb + 4) * HS_S;
            u32 a00 = h0[ar],      a01 = h0[ar + 8],  a02 = h4[ar],      a03 = h4[ar + 8];
            u32 a10 = h0[ar + 16], a11 = h0[ar + 24], a12 = h4[ar + 16], a13 = h4[ar + 24];
            const u32* b0p = w2u + kb * W2_S + qr;
            const u32* b1p = w2u + (kb + 4) * W2_S + qr;
            #pragma unroll
            for (int n8 = 0; n8 < 8; ++n8) {
                u32 b0 = b0p[n8 * 8];
                u32 b1 = b1p[n8 * 8];
                mma_tf32(acc[0][n8], a00, a01, a02, a03, b0, b1);
                mma_tf32(acc[1][n8], a10, a11, a12, a13, b0, b1);
            }
        }

        // ---- epilogue ----
        const float2* w3e = (const float2*)sW3e;
        const float2* w3o = (const float2*)sW3o;
        #pragma unroll
        for (int mt = 0; mt < 2; ++mt) {
            #pragma unroll
            for (int half = 0; half < 2; ++half) {
                u64 lgP0 = pk2(0.f, 0.f), lgP1 = pk2(0.f, 0.f);
                #pragma unroll
                for (int n8 = 0; n8 < 8; ++n8) {
                    int j2 = n8 * 4 + qc;
                    u64 a = pk2(acc[mt][n8][2 * half], acc[mt][n8][2 * half + 1]);
                    u64 g = gelu2(a);
                    float2 we = w3e[j2], wo = w3o[j2];
                    lgP0 = ffma2(g, pk2(we.x, we.y), lgP0);
                    lgP1 = ffma2(g, pk2(wo.x, wo.y), lgP1);
                }
                float l0a, l0b, l1a, l1b;
                upk2(lgP0, l0a, l0b); upk2(lgP1, l1a, l1b);
                float lg0 = l0a + l0b, lg1 = l1a + l1b;
                lg0 += __shfl_xor_sync(0xffffffffu, lg0, 1);
                lg0 += __shfl_xor_sync(0xffffffffu, lg0, 2);
                lg1 += __shfl_xor_sync(0xffffffffu, lg1, 1);
                lg1 += __shfl_xor_sync(0xffffffffu, lg1, 2);

                if (qc == half + 2 * mt) {
                    int row = m0 + qr + 8 * half + 16 * mt;
                    int og  = tile * FTH + row;
                    lg0 += sCst[1]; lg1 += sCst[2];
                    float mxv = fmaxf(lg0, lg1);
                    float e0 = __expf(lg0 - mxv), e1 = __expf(lg1 - mxv);
                    float inv = __fdividef(1.0f, e0 + e1);
                    float g0 = e0 * inv, g1 = e1 * inv;
                    float xgr = sXg[row], xfr = sXf[row], mmr = sMm[row], xir = sXi[row];
                    float imputed  = fmaf(g0, xgr, g1 * xfr);
                    float complete = (mmr != 0.f) ? imputed : xir;
                    out_imp[og]  = imputed;
                    out_comp[og] = complete;
                    float2 gv; gv.x = g0; gv.y = g1;
                    *(float2*)(out_gate + (size_t)og * 2) = gv;
                }
            }
        }
        __syncwarp();
    }
}

// ---------------------------------------------------------------------------
extern "C" void kernel_launch(void* const* d_in, const int* in_sizes, int n_in,
                              void* d_out, int out_size)
{
    const float* x     = (const float*)d_in[0];
    const float* mask  = (const float*)d_in[1];
    const int*   rid   = (const int*)  d_in[2];
    const float* emb   = (const float*)d_in[3];
    const float* gcw1  = (const float*)d_in[4];
    const float* gcb1  = (const float*)d_in[5];
    const float* gcw2  = (const float*)d_in[6];
    const float* gcb2  = (const float*)d_in[7];
    const float* fre   = (const float*)d_in[8];
    const float* fim   = (const float*)d_in[9];
    const float* rtab  = (const float*)d_in[10];
    const float* gw1   = (const float*)d_in[11];
    const float* gb1   = (const float*)d_in[12];
    const float* gw2   = (const float*)d_in[13];
    const float* gb2   = (const float*)d_in[14];
    const float* gw3   = (const float*)d_in[15];
    const float* gb3   = (const float*)d_in[16];
    float* out = (float*)d_out;

    cudaFuncSetAttribute(fused_kernel, cudaFuncAttributeMaxDynamicSharedMemorySize, SMEM_BYTES);

    prep_kernel<<<321, 256>>>(x, mask, emb, rid, rtab, gw1, gb1, fre, fim, out + ADJ_OFF);
    fill_out_kernel<<<256, 256>>>(x, mask, out + SEED_OFF);
    fft_kernel<<<B_ * N_ / 2, 256>>>(out + FREQ_OFF);
    fused_kernel<<<PGRID, FTH, SMEM_BYTES>>>(
        out + SEED_OFF, mask, x, out + FREQ_OFF,
        gw1, gw2, gb2, gw3, gb3,
        gcw1, gcb1, gcw2, gcb2,
        out + GCN_OFF, out + IMP_OFF, out + COMP_OFF, out + GATE_OFF);
}

// round 12
// speedup vs baseline: 1.0428x; 1.0428x over previous
#include <cuda_runtime.h>
#include <cuda_bf16.h>
#include <math.h>

#define B_ 16
#define T_ 2048
#define N_ 64

// Output layout (flattened tuple in order)
#define SEED_OFF 0
#define GCN_OFF  2097152
#define FREQ_OFF 4194304
#define IMP_OFF  6291456
#define COMP_OFF 8388608
#define GATE_OFF 10485760
#define ADJ_OFF  14680064

typedef unsigned long long u64;
typedef unsigned int u32;

// Scratch (static device arrays: allowed)
// Chunk-summary scratch TRANSPOSED: s = (b*64 + n)*64 + c
__device__ float  g_adj[N_ * N_];
__device__ float2 g_preb1p[32 * N_];
__device__ float  g_first[65536], g_last[65536];
__device__ unsigned char g_has[65536];
__device__ float  g_seedT[B_ * N_ * T_];        // [b][n][t]
__device__ float  g_freT[N_ * 1025];            // [n][k]
__device__ float  g_fimT[N_ * 1025];

// ---- packed f32x2 helpers ---------------------------------------------------
__device__ __forceinline__ u64 pk2(float lo, float hi) {
    u64 r; asm("mov.b64 %0, {%1, %2};" : "=l"(r) : "f"(lo), "f"(hi)); return r;
}
__device__ __forceinline__ void upk2(u64 v, float& lo, float& hi) {
    asm("mov.b64 {%0, %1}, %2;" : "=f"(lo), "=f"(hi) : "l"(v));
}
__device__ __forceinline__ u64 ffma2(u64 a, u64 b, u64 c) {
    u64 d; asm("fma.rn.f32x2 %0, %1, %2, %3;" : "=l"(d) : "l"(a), "l"(b), "l"(c)); return d;
}
__device__ __forceinline__ u64 mul2(u64 a, u64 b) {
    u64 d; asm("mul.rn.f32x2 %0, %1, %2;" : "=l"(d) : "l"(a), "l"(b)); return d;
}

__device__ __forceinline__ float tanh_ap(float x) {
    float t; asm("tanh.approx.f32 %0, %1;" : "=f"(t) : "f"(x)); return t;
}

// packed pairwise gelu
__device__ __forceinline__ u64 gelu2(u64 x) {
    const u64 C1 = pk2(0.035677408136f, 0.035677408136f);
    const u64 C0 = pk2(0.7978845608028654f, 0.7978845608028654f);
    const u64 H  = pk2(0.5f, 0.5f);
    u64 x2 = mul2(x, x);
    u64 inner = ffma2(x2, C1, C0);
    u64 b = mul2(x, inner);
    float b0, b1; upk2(b, b0, b1);
    u64 t = pk2(tanh_ap(b0), tanh_ap(b1));
    u64 hx = mul2(x, H);
    return ffma2(hx, t, hx);
}

__device__ __forceinline__ u32 to_tf32(float v) {
    u32 r; asm("cvt.rna.tf32.f32 %0, %1;" : "=r"(r) : "f"(v)); return r;
}

__device__ __forceinline__ void mma_tf32(float* d,
    u32 a0, u32 a1, u32 a2, u32 a3, u32 b0, u32 b1)
{
    asm("mma.sync.aligned.m16n8k8.row.col.f32.tf32.tf32.f32 "
        "{%0,%1,%2,%3}, {%4,%5,%6,%7}, {%8,%9}, {%0,%1,%2,%3};"
        : "+f"(d[0]), "+f"(d[1]), "+f"(d[2]), "+f"(d[3])
        : "r"(a0), "r"(a1), "r"(a2), "r"(a3), "r"(b0), "r"(b1));
}

#define BARP(id) asm volatile("bar.sync %0, %1;" :: "r"(id), "r"(64) : "memory")

// ---------------------------------------------------------------------------
// Kernel 0: prep = fill_sum (blk<256) + filter transpose (blk 256-319)
//                + adjacency/preb1 (blk 320). All independent.
// ---------------------------------------------------------------------------
__global__ void __launch_bounds__(256) prep_kernel(
    const float* __restrict__ x, const float* __restrict__ mask,
    const float* __restrict__ emb, const int* __restrict__ rate_id,
    const float* __restrict__ rate_table, const float* __restrict__ gw1,
    const float* __restrict__ gb1,
    const float* __restrict__ fre, const float* __restrict__ fim,
    float* __restrict__ out_adj)
{
    int blk = blockIdx.x;
    int tid = threadIdx.x;

    if (blk < 256) {
        int g = blk * 256 + tid;
        int n = g & 63;
        int c = (g >> 6) & 63;
        int b = g >> 12;
        int base = ((b * T_) + c * 32) * N_ + n;
        float first = 0.f, last = 0.f; bool has = false;
        #pragma unroll
        for (int t = 0; t < 32; ++t) {
            int idx = base + t * N_;
            float v = x[idx];
            bool obs = (mask[idx] == 0.f);
            if (obs) { if (!has) first = v; last = v; has = true; }
        }
        int s = ((b << 6) + n) * 64 + c;
        g_first[s] = first; g_last[s] = last; g_has[s] = (unsigned char)has;
        return;
    }

    if (blk < 320) {
        int n = blk - 256;
        for (int k = tid; k < 1025; k += 256) {
            g_freT[n * 1025 + k] = fre[(size_t)k * N_ + n];
            g_fimT[n * 1025 + k] = fim[(size_t)k * N_ + n];
        }
        return;
    }

    // adjacency + rate-embed pre-bias (threads 0-63)
    __shared__ float sE[64 * 32];
    for (int i = tid; i < 64 * 32; i += 256) sE[i] = emb[i];
    __syncthreads();
    if (tid >= 64) return;

    float sc[64];
    float mx = -1e30f;
    #pragma unroll
    for (int m = 0; m < 64; ++m) {
        float d = 0.f;
        #pragma unroll
        for (int h = 0; h < 32; ++h) d = fmaf(sE[tid * 32 + h], sE[m * 32 + h], d);
        d = fmaxf(d, 0.f);
        sc[m] = d; mx = fmaxf(mx, d);
    }
    float sum = 0.f;
    #pragma unroll
    for (int m = 0; m < 64; ++m) { float e = __expf(sc[m] - mx); sc[m] = e; sum += e; }
    float inv = 1.0f / sum;
    #pragma unroll
    for (int m = 0; m < 64; ++m) {
        float a = sc[m] * inv;
        g_adj[tid * 64 + m] = a;
        out_adj[tid * 64 + m] = a;
    }
    int rid = rate_id[tid];
    for (int j2 = 0; j2 < 32; ++j2) {
        float v0 = gb1[2 * j2], v1 = gb1[2 * j2 + 1];
        #pragma unroll
        for (int e = 0; e < 16; ++e) {
            float rt = rate_table[rid * 16 + e];
            v0 = fmaf(rt, gw1[(6 + e) * 64 + 2 * j2], v0);
            v1 = fmaf(rt, gw1[(6 + e) * 64 + 2 * j2 + 1], v1);
        }
        g_preb1p[j2 * 64 + tid] = make_float2(v0, v1);
    }
}

// ---------------------------------------------------------------------------
// Kernel 1: fill_out v2 — in-block scan + fill phase.
// ---------------------------------------------------------------------------
__global__ void __launch_bounds__(256) fill_out_kernel(
    const float* __restrict__ x, const float* __restrict__ mask,
    float* __restrict__ seed)
{
    __shared__ float sPr[256], sSu[256];
    __shared__ unsigned char sPrh[256], sSuh[256];

    int blk = blockIdx.x;
    int b = blk >> 4;
    int c0 = (blk & 15) * 4;
    int tid = threadIdx.x;

    if (tid < 64) {
        int bn = (b << 6) + tid;
        const float* fp = g_first + bn * 64;
        const float* lp = g_last + bn * 64;
        const unsigned char* hp = g_has + bn * 64;
        float pv = 0.f; bool ph = false;
        #pragma unroll 8
        for (int c = 0; c < 64; ++c) {
            unsigned d = (unsigned)(c - c0);
            if (d < 4u) { sPr[d * 64 + tid] = pv; sPrh[d * 64 + tid] = (unsigned char)ph; }
            if (hp[c]) { pv = lp[c]; ph = true; }
        }
        float sv = 0.f; bool sh = false;
        #pragma unroll 8
        for (int c = 63; c >= 0; --c) {
            unsigned d = (unsigned)(c - c0);
            if (d < 4u) { sSu[d * 64 + tid] = sv; sSuh[d * 64 + tid] = (unsigned char)sh; }
            if (hp[c]) { sv = fp[c]; sh = true; }
        }
    }
    __syncthreads();

    int n = tid & 63;
    int cl = tid >> 6;
    int c = c0 + cl;
    int base = ((b * T_) + c * 32) * N_ + n;
    float* tdst = g_seedT + ((size_t)(b * 64 + n)) * T_ + c * 32;

    float fv = sPr[cl * 64 + n]; bool fh = (bool)sPrh[cl * 64 + n];
    float vals[32];
    unsigned obsm = 0u, fam = 0u;
    #pragma unroll
    for (int t = 0; t < 32; ++t) {
        int idx = base + t * N_;
        float v = x[idx];
        bool obs = (mask[idx] == 0.f);
        if (obs) { fv = v; fh = true; obsm |= (1u << t); }
        vals[t] = fv;
        if (fh) fam |= (1u << t);
    }
    float bv = sSu[cl * 64 + n]; bool bh = (bool)sSuh[cl * 64 + n];
    #pragma unroll
    for (int t = 31; t >= 0; --t) {
        bool obs = (obsm >> t) & 1u;
        bool fa  = (fam  >> t) & 1u;
        float v = vals[t];
        if (obs) { bv = v; bh = true; }
        float out;
        if (obs)            out = v;
        else if (fa && bh)  out = 0.5f * (v + bv);
        else if (fa)        out = v;
        else if (bh)        out = bv;
        else                out = 0.f;
        seed[base + t * N_] = out;
        tdst[t] = out;
    }
}

// ---------------------------------------------------------------------------
// Kernel 2: packed-pair radix-2 FFT filter; coalesced loads
// ---------------------------------------------------------------------------
__global__ void __launch_bounds__(256) fft_kernel(
    float* __restrict__ xfreq)
{
    __shared__ float re[2048], im[2048], twr[1024], twi[1024];
    int tid = threadIdx.x;
    int b = blockIdx.x >> 5;
    int p = blockIdx.x & 31;
    int n0 = p * 2;
    const float* src0 = g_seedT + ((size_t)(b * 64 + n0)) * T_;
    const float* src1 = src0 + T_;

    for (int j = tid; j < 1024; j += 256) {
        float s, c;
        sincosf(-6.28318530717958647692f * (float)j * (1.0f / 2048.0f), &s, &c);
        twr[j] = c; twi[j] = s;
    }
    for (int t = tid; t < 2048; t += 256) {
        re[t] = src0[t];
        im[t] = src1[t];
    }

    for (int s = 10; s >= 0; --s) {
        int half = 1 << s;
        __syncthreads();
        for (int bi = tid; bi < 1024; bi += 256) {
            int j = bi & (half - 1);
            int i1 = ((bi >> s) << (s + 1)) | j;
            int i2 = i1 + half;
            int tj = j << (10 - s);
            float wr = twr[tj], wi = twi[tj];
            float ar = re[i1], ai = im[i1], br = re[i2], b2 = im[i2];
            re[i1] = ar + br; im[i1] = ai + b2;
            float dr = ar - br, di = ai - b2;
            re[i2] = dr * wr - di * wi;
            im[i2] = dr * wi + di * wr;
        }
    }
    __syncthreads();

    const float* fT0r = g_freT + n0 * 1025;
    const float* fT0i = g_fimT + n0 * 1025;
    const float* fT1r = fT0r + 1025;
    const float* fT1i = fT0i + 1025;
    for (int k = tid; k <= 1024; k += 256) {
        int km = (2048 - k) & 2047;
        int pk = __brev(k) >> 21;
        int pm = __brev(km) >> 21;
        float zr = re[pk], zi = im[pk];
        float yr = re[pm], yi = im[pm];
        float x1r = 0.5f * (zr + yr), x1i = 0.5f * (zi - yi);
        float x2r = 0.5f * (zi + yi), x2i = 0.5f * (yr - zr);
        float h1r = fT0r[k], h1i = fT0i[k];
        float h2r = fT1r[k], h2i = fT1i[k];
        float y1r = x1r * h1r - x1i * h1i, y1i = x1r * h1i + x1i * h1r;
        float y2r = x2r * h2r - x2i * h2i, y2i = x2r * h2i + x2i * h2r;
        if (k == 0 || k == 1024) { y1i = 0.f; y2i = 0.f; }
        re[pk] = y1r - y2i; im[pk] = y1i + y2r;
        if (k > 0 && k < 1024) { re[pm] = y1r + y2i; im[pm] = y2r - y1i; }
    }

    for (int s = 0; s <= 10; ++s) {
        int half = 1 << s;
        __syncthreads();
        for (int bi = tid; bi < 1024; bi += 256) {
            int j = bi & (half - 1);
            int i1 = ((bi >> s) << (s + 1)) | j;
            int i2 = i1 + half;
            int tj = j << (10 - s);
            float wr = twr[tj], wi = -twi[tj];
            float br = re[i2], b2 = im[i2];
            float tr = br * wr - b2 * wi, ti = br * wi + b2 * wr;
            float ar = re[i1], ai = im[i1];
            re[i1] = ar + tr; im[i1] = ai + ti;
            re[i2] = ar - tr; im[i2] = ai - ti;
        }
    }
    __syncthreads();

    float* dst = xfreq + (size_t)b * T_ * N_ + n0;
    const float scl = 1.0f / 2048.0f;
    for (int t = tid; t < 2048; t += 256) {
        float2 v; v.x = re[t] * scl; v.y = im[t] * scl;
        *(float2*)(dst + (size_t)t * N_) = v;
    }
}

// ---------------------------------------------------------------------------
// Kernel 3 v9: FFMA2 layer1 with folded 4-feature weights + LDS.128 broadcast
// loads everywhere; tf32 mma layer2; pair-barriers.
// ---------------------------------------------------------------------------
#define FTH 256
#define HS_S 264
#define W2_S 72
#define NTILES (B_ * T_ * N_ / FTH)   // 8192
#define PGRID 296
// floats: hs 16896 + w2 4608 + adj 4224 + w1fA 128 + w1fB 128 + gcI 64
//         + gcV 32 + w34 128 + b2 64 + pm 256 + xg/xf/mm/xi 1024 + cst 4 = 27556
#define SMEM_BYTES (27556 * 4)

__global__ void __launch_bounds__(FTH, 2) fused_kernel(
    const float* __restrict__ seed, const float* __restrict__ mask,
    const float* __restrict__ xin, const float* __restrict__ xfreq,
    const float* __restrict__ gw1, const float* __restrict__ gw2,
    const float* __restrict__ gb2, const float* __restrict__ gw3,
    const float* __restrict__ gb3,
    const float* __restrict__ gcw1, const float* __restrict__ gcb1,
    const float* __restrict__ gcw2, const float* __restrict__ gcb2,
    float* __restrict__ out_gcn, float* __restrict__ out_imp,
    float* __restrict__ out_comp, float* __restrict__ out_gate)
{
    extern __shared__ float sm[];
    float* hs    = sm;                    // [64][264] tf32 bits
    float* sW2   = hs    + 64 * HS_S;     // [64][72] tf32
    float* sA    = sW2   + 64 * W2_S;     // [64][66]
    float* sW1fA = sA    + 64 * 66;       // [32]{f0pair,f1pair} = 128 floats
    float* sW1fB = sW1fA + 128;           // [32]{f2pair,f3pair}
    float* sGcI  = sW1fB + 128;           // [16]{w pair, b pair} = 64 floats
    float* sGcV  = sGcI  + 64;            // [32]
    float* sW34  = sGcV  + 32;            // [32]{we pair, wo pair} = 128 floats
    float* sB2   = sW34  + 128;           // [64]
    float* sPm   = sB2   + 64;            // [4][64]
    float* sXg   = sPm   + FTH;
    float* sXf   = sXg   + FTH;
    float* sMm   = sXf   + FTH;
    float* sXi   = sMm   + FTH;
    float* sCst  = sXi   + FTH;           // [4]

    int tid = threadIdx.x;

    // ---- stage weights once ----
    for (int i = tid; i < 4096; i += FTH) {
        int k = i >> 6, j = i & 63;
        ((u32*)sW2)[k * W2_S + j] = to_tf32(gw2[i]);
    }
    for (int i = tid; i < 4096; i += FTH) sA[(i >> 6) * 66 + (i & 63)] = g_adj[i];
    if (tid < 64) {
        int j = tid;
        float wf0 = gw1[0 * 64 + j] - gw1[4 * 64 + j] - gw1[5 * 64 + j];
        float wf1 = gw1[1 * 64 + j];
        float wf2 = gw1[2 * 64 + j] + gw1[4 * 64 + j];
        float wf3 = gw1[3 * 64 + j] + gw1[5 * 64 + j];
        int p = j >> 1, o = j & 1;
        sW1fA[p * 4 + o]     = wf0;
        sW1fA[p * 4 + 2 + o] = wf1;
        sW1fB[p * 4 + o]     = wf2;
        sW1fB[p * 4 + 2 + o] = wf3;
        sB2[j] = gb2[j];
    }
    if (tid < 16) {
        sGcI[tid * 4 + 0] = gcw1[2 * tid];
        sGcI[tid * 4 + 1] = gcw1[2 * tid + 1];
        sGcI[tid * 4 + 2] = gcb1[2 * tid];
        sGcI[tid * 4 + 3] = gcb1[2 * tid + 1];
    }
    if (tid < 32) {
        sGcV[tid] = gcw2[tid];
        sW34[tid * 4 + 0] = gw3[4 * tid];       // we.lo
        sW34[tid * 4 + 1] = gw3[4 * tid + 2];   // we.hi
        sW34[tid * 4 + 2] = gw3[4 * tid + 1];   // wo.lo
        sW34[tid * 4 + 3] = gw3[4 * tid + 3];   // wo.hi
    }
    if (tid == 0) { sCst[0] = gcb2[0]; sCst[1] = gb3[0]; sCst[2] = gb3[1]; }
    __syncthreads();

    int n    = tid & 63;
    int r    = tid >> 6;      // 0..3
    int lane = tid & 31;
    int warp = tid >> 5;      // 0..7
    int m0   = warp * 32;
    int qr   = lane >> 2;     // quad row 0..7
    int qc   = lane & 3;      // quad col 0..3
    int prId = 8 + (tid >> 6);  // named barrier per warp-pair

    u32* hsu = (u32*)hs;
    const u64* prebp = (const u64*)g_preb1p;
    const ulonglong2* WA = (const ulonglong2*)sW1fA;
    const ulonglong2* WB = (const ulonglong2*)sW1fB;
    const ulonglong2* gcWB = (const ulonglong2*)sGcI;
    const u64* gcV = (const u64*)sGcV;
    const ulonglong2* w34 = (const ulonglong2*)sW34;

    for (int tile = blockIdx.x; tile < NTILES; tile += PGRID) {
        BARP(prId);   // partner done reading previous tile's sPm

        int gidx = tile * FTH + tid;
        float s  = seed[gidx];
        float mm = mask[gidx];
        float xf = xfreq[gidx];
        float xi = xin[gidx];

        // ---- phi(s), packed pairs (LDS.128 merged w/b) ----
        u64 sp = pk2(s, s);
        u64 accp = pk2(0.f, 0.f);
        #pragma unroll
        for (int hq = 0; hq < 16; ++hq) {
            ulonglong2 wb = gcWB[hq];
            u64 pre = ffma2(sp, wb.x, wb.y);
            accp = ffma2(gelu2(pre), gcV[hq], accp);
        }
        float p0, p1; upk2(accp, p0, p1);
        sPm[r * 64 + n] = p0 + p1;
        BARP(prId);   // pair-wide phi visible

        // ---- x_gcn (packed matvec) ----
        u64 xgp = pk2(0.f, 0.f);
        const u64* arow = (const u64*)(sA + n * 66);
        const u64* prow = (const u64*)(sPm + r * 64);
        #pragma unroll 8
        for (int m2 = 0; m2 < 32; ++m2)
            xgp = ffma2(arow[m2], prow[m2], xgp);
        float xg0, xg1; upk2(xgp, xg0, xg1);
        float xg = xg0 + xg1 + sCst[0];

        sXg[tid] = xg; sXf[tid] = xf; sMm[tid] = mm; sXi[tid] = xi;
        out_gcn[gidx] = xg;

        // ---- layer1: folded 4 features, FFMA2, LDS.128 weights -> hs tf32 ----
        u64 u0 = pk2(s, s), u1 = pk2(mm, mm), u2 = pk2(xg, xg), u3 = pk2(xf, xf);
        #pragma unroll
        for (int p = 0; p < 32; ++p) {
            u64 a = __ldg(prebp + p * 64 + n);
            ulonglong2 wa = WA[p];
            ulonglong2 wb = WB[p];
            a = ffma2(u0, wa.x, a);
            a = ffma2(u1, wa.y, a);
            a = ffma2(u2, wb.x, a);
            a = ffma2(u3, wb.y, a);
            u64 g = gelu2(a);
            float v0, v1; upk2(g, v0, v1);
            hsu[(2 * p) * HS_S + tid]     = to_tf32(v0);
            hsu[(2 * p + 1) * HS_S + tid] = to_tf32(v1);
        }
        __syncwarp();   // hs columns are warp-local

        // ---- Phase B: layer2 via tf32 mma ----
        float acc[2][8][4];
        #pragma unroll
        for (int n8 = 0; n8 < 8; ++n8) {
            int j0 = n8 * 8 + qc * 2;
            float2 bb = *(const float2*)(sB2 + j0);
            #pragma unroll
            for (int mt = 0; mt < 2; ++mt) {
                acc[mt][n8][0] = bb.x; acc[mt][n8][1] = bb.y;
                acc[mt][n8][2] = bb.x; acc[mt][n8][3] = bb.y;
            }
        }

        const u32* w2u = (const u32*)sW2;
        int ar = m0 + qr;
        #pragma unroll
        for (int k8 = 0; k8 < 8; ++k8) {
            int kb = k8 * 8 + qc;
            const u32* h0 = hsu + kb * HS_S;
            const u32* h4 = hsu + (kb + 4) * HS_S;
            u32 a00 = h0[ar],      a01 = h0[ar + 8],  a02 = h4[ar],      a03 = h4[ar + 8];
            u32 a10 = h0[ar + 16], a11 = h0[ar + 24], a12 = h4[ar + 16], a13 = h4[ar + 24];
            const u32* b0p = w2u + kb * W2_S + qr;
            const u32* b1p = w2u + (kb + 4) * W2_S + qr;
            #pragma unroll
            for (int n8 = 0; n8 < 8; ++n8) {
                u32 b0 = b0p[n8 * 8];
                u32 b1 = b1p[n8 * 8];
                mma_tf32(acc[0][n8], a00, a01, a02, a03, b0, b1);
                mma_tf32(acc[1][n8], a10, a11, a12, a13, b0, b1);
            }
        }

        // ---- epilogue: gelu(h2) + layer3 (LDS.128 w3) + quad reduce ----
        #pragma unroll
        for (int mt = 0; mt < 2; ++mt) {
            #pragma unroll
            for (int half = 0; half < 2; ++half) {
                u64 lgP0 = pk2(0.f, 0.f), lgP1 = pk2(0.f, 0.f);
                #pragma unroll
                for (int n8 = 0; n8 < 8; ++n8) {
                    int j2 = n8 * 4 + qc;
                    u64 a = pk2(acc[mt][n8][2 * half], acc[mt][n8][2 * half + 1]);
                    u64 g = gelu2(a);
                    ulonglong2 w = w34[j2];
                    lgP0 = ffma2(g, w.x, lgP0);
                    lgP1 = ffma2(g, w.y, lgP1);
                }
                float l0a, l0b, l1a, l1b;
                upk2(lgP0, l0a, l0b); upk2(lgP1, l1a, l1b);
                float lg0 = l0a + l0b, lg1 = l1a + l1b;
                lg0 += __shfl_xor_sync(0xffffffffu, lg0, 1);
                lg0 += __shfl_xor_sync(0xffffffffu, lg0, 2);
                lg1 += __shfl_xor_sync(0xffffffffu, lg1, 1);
                lg1 += __shfl_xor_sync(0xffffffffu, lg1, 2);

                if (qc == half + 2 * mt) {
                    int row = m0 + qr + 8 * half + 16 * mt;
                    int og  = tile * FTH + row;
                    lg0 += sCst[1]; lg1 += sCst[2];
                    float mxv = fmaxf(lg0, lg1);
                    float e0 = __expf(lg0 - mxv), e1 = __expf(lg1 - mxv);
                    float inv = __fdividef(1.0f, e0 + e1);
                    float g0 = e0 * inv, g1 = e1 * inv;
                    float xgr = sXg[row], xfr = sXf[row], mmr = sMm[row], xir = sXi[row];
                    float imputed  = fmaf(g0, xgr, g1 * xfr);
                    float complete = (mmr != 0.f) ? imputed : xir;
                    out_imp[og]  = imputed;
                    out_comp[og] = complete;
                    float2 gv; gv.x = g0; gv.y = g1;
                    *(float2*)(out_gate + (size_t)og * 2) = gv;
                }
            }
        }
        __syncwarp();
    }
}

// ---------------------------------------------------------------------------
extern "C" void kernel_launch(void* const* d_in, const int* in_sizes, int n_in,
                              void* d_out, int out_size)
{
    const float* x     = (const float*)d_in[0];
    const float* mask  = (const float*)d_in[1];
    const int*   rid   = (const int*)  d_in[2];
    const float* emb   = (const float*)d_in[3];
    const float* gcw1  = (const float*)d_in[4];
    const float* gcb1  = (const float*)d_in[5];
    const float* gcw2  = (const float*)d_in[6];
    const float* gcb2  = (const float*)d_in[7];
    const float* fre   = (const float*)d_in[8];
    const float* fim   = (const float*)d_in[9];
    const float* rtab  = (const float*)d_in[10];
    const float* gw1   = (const float*)d_in[11];
    const float* gb1   = (const float*)d_in[12];
    const float* gw2   = (const float*)d_in[13];
    const float* gb2   = (const float*)d_in[14];
    const float* gw3   = (const float*)d_in[15];
    const float* gb3   = (const float*)d_in[16];
    float* out = (float*)d_out;

    cudaFuncSetAttribute(fused_kernel, cudaFuncAttributeMaxDynamicSharedMemorySize, SMEM_BYTES);

    prep_kernel<<<321, 256>>>(x, mask, emb, rid, rtab, gw1, gb1, fre, fim, out + ADJ_OFF);
    fill_out_kernel<<<256, 256>>>(x, mask, out + SEED_OFF);
    fft_kernel<<<B_ * N_ / 2, 256>>>(out + FREQ_OFF);
    fused_kernel<<<PGRID, FTH, SMEM_BYTES>>>(
        out + SEED_OFF, mask, x, out + FREQ_OFF,
        gw1, gw2, gb2, gw3, gb3,
        gcw1, gcb1, gcw2, gcb2,
        out + GCN_OFF, out + IMP_OFF, out + COMP_OFF, out + GATE_OFF);
}

// round 13
// speedup vs baseline: 1.2038x; 1.1544x over previous
#include <cuda_runtime.h>
#include <cuda_bf16.h>
#include <math.h>

#define B_ 16
#define T_ 2048
#define N_ 64

// Output layout (flattened tuple in order)
#define SEED_OFF 0
#define GCN_OFF  2097152
#define FREQ_OFF 4194304
#define IMP_OFF  6291456
#define COMP_OFF 8388608
#define GATE_OFF 10485760
#define ADJ_OFF  14680064

typedef unsigned long long u64;
typedef unsigned int u32;

// Scratch (static device arrays: allowed)
// Chunk-summary scratch TRANSPOSED: s = (b*64 + n)*64 + c
__device__ float  g_adj[N_ * N_];
__device__ float2 g_preb1p[32 * N_];
__device__ float  g_first[65536], g_last[65536];
__device__ unsigned char g_has[65536];
__device__ float  g_seedT[B_ * N_ * T_];        // [b][n][t]
__device__ float  g_freT[N_ * 1025];            // [n][k]
__device__ float  g_fimT[N_ * 1025];

// ---- packed f32x2 helpers ---------------------------------------------------
__device__ __forceinline__ u64 pk2(float lo, float hi) {
    u64 r; asm("mov.b64 %0, {%1, %2};" : "=l"(r) : "f"(lo), "f"(hi)); return r;
}
__device__ __forceinline__ void upk2(u64 v, float& lo, float& hi) {
    asm("mov.b64 {%0, %1}, %2;" : "=f"(lo), "=f"(hi) : "l"(v));
}
__device__ __forceinline__ u64 ffma2(u64 a, u64 b, u64 c) {
    u64 d; asm("fma.rn.f32x2 %0, %1, %2, %3;" : "=l"(d) : "l"(a), "l"(b), "l"(c)); return d;
}
__device__ __forceinline__ u64 mul2(u64 a, u64 b) {
    u64 d; asm("mul.rn.f32x2 %0, %1, %2;" : "=l"(d) : "l"(a), "l"(b)); return d;
}

__device__ __forceinline__ float tanh_ap(float x) {
    float t; asm("tanh.approx.f32 %0, %1;" : "=f"(t) : "f"(x)); return t;
}

// packed pairwise gelu
__device__ __forceinline__ u64 gelu2(u64 x) {
    const u64 C1 = pk2(0.035677408136f, 0.035677408136f);
    const u64 C0 = pk2(0.7978845608028654f, 0.7978845608028654f);
    const u64 H  = pk2(0.5f, 0.5f);
    u64 x2 = mul2(x, x);
    u64 inner = ffma2(x2, C1, C0);
    u64 b = mul2(x, inner);
    float b0, b1; upk2(b, b0, b1);
    u64 t = pk2(tanh_ap(b0), tanh_ap(b1));
    u64 hx = mul2(x, H);
    return ffma2(hx, t, hx);
}

// pack two f32 into bf16x2 (lo = first arg)
__device__ __forceinline__ u32 bfpack(float lo, float hi) {
    u32 d; asm("cvt.rn.bf16x2.f32 %0, %1, %2;" : "=r"(d) : "f"(hi), "f"(lo)); return d;
}

__device__ __forceinline__ void mma_bf16(float* d,
    u32 a0, u32 a1, u32 a2, u32 a3, u32 b0, u32 b1)
{
    asm("mma.sync.aligned.m16n8k16.row.col.f32.bf16.bf16.f32 "
        "{%0,%1,%2,%3}, {%4,%5,%6,%7}, {%8,%9}, {%0,%1,%2,%3};"
        : "+f"(d[0]), "+f"(d[1]), "+f"(d[2]), "+f"(d[3])
        : "r"(a0), "r"(a1), "r"(a2), "r"(a3), "r"(b0), "r"(b1));
}

#define BARP(id) asm volatile("bar.sync %0, %1;" :: "r"(id), "r"(64) : "memory")

// ---------------------------------------------------------------------------
// Kernel 0: prep = fill_sum (blk<256) + filter transpose (blk 256-319)
//                + adjacency/preb1 (blk 320). All independent.
// ---------------------------------------------------------------------------
__global__ void __launch_bounds__(256) prep_kernel(
    const float* __restrict__ x, const float* __restrict__ mask,
    const float* __restrict__ emb, const int* __restrict__ rate_id,
    const float* __restrict__ rate_table, const float* __restrict__ gw1,
    const float* __restrict__ gb1,
    const float* __restrict__ fre, const float* __restrict__ fim,
    float* __restrict__ out_adj)
{
    int blk = blockIdx.x;
    int tid = threadIdx.x;

    if (blk < 256) {
        int g = blk * 256 + tid;
        int n = g & 63;
        int c = (g >> 6) & 63;
        int b = g >> 12;
        int base = ((b * T_) + c * 32) * N_ + n;
        float first = 0.f, last = 0.f; bool has = false;
        #pragma unroll
        for (int t = 0; t < 32; ++t) {
            int idx = base + t * N_;
            float v = x[idx];
            bool obs = (mask[idx] == 0.f);
            if (obs) { if (!has) first = v; last = v; has = true; }
        }
        int s = ((b << 6) + n) * 64 + c;
        g_first[s] = first; g_last[s] = last; g_has[s] = (unsigned char)has;
        return;
    }

    if (blk < 320) {
        int n = blk - 256;
        for (int k = tid; k < 1025; k += 256) {
            g_freT[n * 1025 + k] = fre[(size_t)k * N_ + n];
            g_fimT[n * 1025 + k] = fim[(size_t)k * N_ + n];
        }
        return;
    }

    // adjacency + rate-embed pre-bias (threads 0-63)
    __shared__ float sE[64 * 32];
    for (int i = tid; i < 64 * 32; i += 256) sE[i] = emb[i];
    __syncthreads();
    if (tid >= 64) return;

    float sc[64];
    float mx = -1e30f;
    #pragma unroll
    for (int m = 0; m < 64; ++m) {
        float d = 0.f;
        #pragma unroll
        for (int h = 0; h < 32; ++h) d = fmaf(sE[tid * 32 + h], sE[m * 32 + h], d);
        d = fmaxf(d, 0.f);
        sc[m] = d; mx = fmaxf(mx, d);
    }
    float sum = 0.f;
    #pragma unroll
    for (int m = 0; m < 64; ++m) { float e = __expf(sc[m] - mx); sc[m] = e; sum += e; }
    float inv = 1.0f / sum;
    #pragma unroll
    for (int m = 0; m < 64; ++m) {
        float a = sc[m] * inv;
        g_adj[tid * 64 + m] = a;
        out_adj[tid * 64 + m] = a;
    }
    int rid = rate_id[tid];
    for (int j2 = 0; j2 < 32; ++j2) {
        float v0 = gb1[2 * j2], v1 = gb1[2 * j2 + 1];
        #pragma unroll
        for (int e = 0; e < 16; ++e) {
            float rt = rate_table[rid * 16 + e];
            v0 = fmaf(rt, gw1[(6 + e) * 64 + 2 * j2], v0);
            v1 = fmaf(rt, gw1[(6 + e) * 64 + 2 * j2 + 1], v1);
        }
        g_preb1p[j2 * 64 + tid] = make_float2(v0, v1);
    }
}

// ---------------------------------------------------------------------------
// Kernel 1: fill_out v2 — in-block scan + fill phase.
// ---------------------------------------------------------------------------
__global__ void __launch_bounds__(256) fill_out_kernel(
    const float* __restrict__ x, const float* __restrict__ mask,
    float* __restrict__ seed)
{
    __shared__ float sPr[256], sSu[256];
    __shared__ unsigned char sPrh[256], sSuh[256];

    int blk = blockIdx.x;
    int b = blk >> 4;
    int c0 = (blk & 15) * 4;
    int tid = threadIdx.x;

    if (tid < 64) {
        int bn = (b << 6) + tid;
        const float* fp = g_first + bn * 64;
        const float* lp = g_last + bn * 64;
        const unsigned char* hp = g_has + bn * 64;
        float pv = 0.f; bool ph = false;
        #pragma unroll 8
        for (int c = 0; c < 64; ++c) {
            unsigned d = (unsigned)(c - c0);
            if (d < 4u) { sPr[d * 64 + tid] = pv; sPrh[d * 64 + tid] = (unsigned char)ph; }
            if (hp[c]) { pv = lp[c]; ph = true; }
        }
        float sv = 0.f; bool sh = false;
        #pragma unroll 8
        for (int c = 63; c >= 0; --c) {
            unsigned d = (unsigned)(c - c0);
            if (d < 4u) { sSu[d * 64 + tid] = sv; sSuh[d * 64 + tid] = (unsigned char)sh; }
            if (hp[c]) { sv = fp[c]; sh = true; }
        }
    }
    __syncthreads();

    int n = tid & 63;
    int cl = tid >> 6;
    int c = c0 + cl;
    int base = ((b * T_) + c * 32) * N_ + n;
    float* tdst = g_seedT + ((size_t)(b * 64 + n)) * T_ + c * 32;

    float fv = sPr[cl * 64 + n]; bool fh = (bool)sPrh[cl * 64 + n];
    float vals[32];
    unsigned obsm = 0u, fam = 0u;
    #pragma unroll
    for (int t = 0; t < 32; ++t) {
        int idx = base + t * N_;
        float v = x[idx];
        bool obs = (mask[idx] == 0.f);
        if (obs) { fv = v; fh = true; obsm |= (1u << t); }
        vals[t] = fv;
        if (fh) fam |= (1u << t);
    }
    float bv = sSu[cl * 64 + n]; bool bh = (bool)sSuh[cl * 64 + n];
    #pragma unroll
    for (int t = 31; t >= 0; --t) {
        bool obs = (obsm >> t) & 1u;
        bool fa  = (fam  >> t) & 1u;
        float v = vals[t];
        if (obs) { bv = v; bh = true; }
        float out;
        if (obs)            out = v;
        else if (fa && bh)  out = 0.5f * (v + bv);
        else if (fa)        out = v;
        else if (bh)        out = bv;
        else                out = 0.f;
        seed[base + t * N_] = out;
        tdst[t] = out;
    }
}

// ---------------------------------------------------------------------------
// Kernel 2: packed-pair radix-2 FFT filter; coalesced loads
// ---------------------------------------------------------------------------
__global__ void __launch_bounds__(256) fft_kernel(
    float* __restrict__ xfreq)
{
    __shared__ float re[2048], im[2048], twr[1024], twi[1024];
    int tid = threadIdx.x;
    int b = blockIdx.x >> 5;
    int p = blockIdx.x & 31;
    int n0 = p * 2;
    const float* src0 = g_seedT + ((size_t)(b * 64 + n0)) * T_;
    const float* src1 = src0 + T_;

    for (int j = tid; j < 1024; j += 256) {
        float s, c;
        sincosf(-6.28318530717958647692f * (float)j * (1.0f / 2048.0f), &s, &c);
        twr[j] = c; twi[j] = s;
    }
    for (int t = tid; t < 2048; t += 256) {
        re[t] = src0[t];
        im[t] = src1[t];
    }

    for (int s = 10; s >= 0; --s) {
        int half = 1 << s;
        __syncthreads();
        for (int bi = tid; bi < 1024; bi += 256) {
            int j = bi & (half - 1);
            int i1 = ((bi >> s) << (s + 1)) | j;
            int i2 = i1 + half;
            int tj = j << (10 - s);
            float wr = twr[tj], wi = twi[tj];
            float ar = re[i1], ai = im[i1], br = re[i2], b2 = im[i2];
            re[i1] = ar + br; im[i1] = ai + b2;
            float dr = ar - br, di = ai - b2;
            re[i2] = dr * wr - di * wi;
            im[i2] = dr * wi + di * wr;
        }
    }
    __syncthreads();

    const float* fT0r = g_freT + n0 * 1025;
    const float* fT0i = g_fimT + n0 * 1025;
    const float* fT1r = fT0r + 1025;
    const float* fT1i = fT0i + 1025;
    for (int k = tid; k <= 1024; k += 256) {
        int km = (2048 - k) & 2047;
        int pk = __brev(k) >> 21;
        int pm = __brev(km) >> 21;
        float zr = re[pk], zi = im[pk];
        float yr = re[pm], yi = im[pm];
        float x1r = 0.5f * (zr + yr), x1i = 0.5f * (zi - yi);
        float x2r = 0.5f * (zi + yi), x2i = 0.5f * (yr - zr);
        float h1r = fT0r[k], h1i = fT0i[k];
        float h2r = fT1r[k], h2i = fT1i[k];
        float y1r = x1r * h1r - x1i * h1i, y1i = x1r * h1i + x1i * h1r;
        float y2r = x2r * h2r - x2i * h2i, y2i = x2r * h2i + x2i * h2r;
        if (k == 0 || k == 1024) { y1i = 0.f; y2i = 0.f; }
        re[pk] = y1r - y2i; im[pk] = y1i + y2r;
        if (k > 0 && k < 1024) { re[pm] = y1r + y2i; im[pm] = y2r - y1i; }
    }

    for (int s = 0; s <= 10; ++s) {
        int half = 1 << s;
        __syncthreads();
        for (int bi = tid; bi < 1024; bi += 256) {
            int j = bi & (half - 1);
            int i1 = ((bi >> s) << (s + 1)) | j;
            int i2 = i1 + half;
            int tj = j << (10 - s);
            float wr = twr[tj], wi = -twi[tj];
            float br = re[i2], b2 = im[i2];
            float tr = br * wr - b2 * wi, ti = br * wi + b2 * wr;
            float ar = re[i1], ai = im[i1];
            re[i1] = ar + tr; im[i1] = ai + ti;
            re[i2] = ar - tr; im[i2] = ai - ti;
        }
    }
    __syncthreads();

    float* dst = xfreq + (size_t)b * T_ * N_ + n0;
    const float scl = 1.0f / 2048.0f;
    for (int t = tid; t < 2048; t += 256) {
        float2 v; v.x = re[t] * scl; v.y = im[t] * scl;
        *(float2*)(dst + (size_t)t * N_) = v;
    }
}

// ---------------------------------------------------------------------------
// Kernel 3 v10: layer2 via bf16 m16n8k16 mma (half the mma/LDS/STS of tf32 k8).
// hs: [32 kpair][264] bf16x2. w2: [32 kpair][72] bf16x2. fp32 accum.
// ---------------------------------------------------------------------------
#define FTH 256
#define HS_S 264
#define W2_S 72
#define NTILES (B_ * T_ * N_ / FTH)   // 8192
#define PGRID 296
// floats: hs 8448 + w2p 2304 + adj 4224 + w1fA 128 + w1fB 128 + gcI 64
//         + gcV 32 + w34 128 + b2 64 + pm 256 + xg/xf/mm/xi 1024 + cst 4 = 16804
#define SMEM_BYTES (16804 * 4)

__global__ void __launch_bounds__(FTH, 2) fused_kernel(
    const float* __restrict__ seed, const float* __restrict__ mask,
    const float* __restrict__ xin, const float* __restrict__ xfreq,
    const float* __restrict__ gw1, const float* __restrict__ gw2,
    const float* __restrict__ gb2, const float* __restrict__ gw3,
    const float* __restrict__ gb3,
    const float* __restrict__ gcw1, const float* __restrict__ gcb1,
    const float* __restrict__ gcw2, const float* __restrict__ gcb2,
    float* __restrict__ out_gcn, float* __restrict__ out_imp,
    float* __restrict__ out_comp, float* __restrict__ out_gate)
{
    extern __shared__ float sm[];
    float* hs    = sm;                    // [32][264] bf16x2 (u32)
    float* sW2   = hs    + 32 * HS_S;     // [32][72] bf16x2
    float* sA    = sW2   + 32 * W2_S;     // [64][66]
    float* sW1fA = sA    + 64 * 66;       // [32]{f0pair,f1pair}
    float* sW1fB = sW1fA + 128;           // [32]{f2pair,f3pair}
    float* sGcI  = sW1fB + 128;           // [16]{w pair, b pair}
    float* sGcV  = sGcI  + 64;            // [32]
    float* sW34  = sGcV  + 32;            // [32]{we pair, wo pair}
    float* sB2   = sW34  + 128;           // [64]
    float* sPm   = sB2   + 64;            // [4][64]
    float* sXg   = sPm   + FTH;
    float* sXf   = sXg   + FTH;
    float* sMm   = sXf   + FTH;
    float* sXi   = sMm   + FTH;
    float* sCst  = sXi   + FTH;           // [4]

    int tid = threadIdx.x;

    // ---- stage weights once ----
    // w2 as bf16 k-pairs: w2p[kp][j] = {gw2[2kp][j], gw2[2kp+1][j]}
    for (int i = tid; i < 2048; i += FTH) {
        int kp = i >> 6, j = i & 63;
        ((u32*)sW2)[kp * W2_S + j] = bfpack(gw2[(2 * kp) * 64 + j], gw2[(2 * kp + 1) * 64 + j]);
    }
    for (int i = tid; i < 4096; i += FTH) sA[(i >> 6) * 66 + (i & 63)] = g_adj[i];
    if (tid < 64) {
        int j = tid;
        float wf0 = gw1[0 * 64 + j] - gw1[4 * 64 + j] - gw1[5 * 64 + j];
        float wf1 = gw1[1 * 64 + j];
        float wf2 = gw1[2 * 64 + j] + gw1[4 * 64 + j];
        float wf3 = gw1[3 * 64 + j] + gw1[5 * 64 + j];
        int p = j >> 1, o = j & 1;
        sW1fA[p * 4 + o]     = wf0;
        sW1fA[p * 4 + 2 + o] = wf1;
        sW1fB[p * 4 + o]     = wf2;
        sW1fB[p * 4 + 2 + o] = wf3;
        sB2[j] = gb2[j];
    }
    if (tid < 16) {
        sGcI[tid * 4 + 0] = gcw1[2 * tid];
        sGcI[tid * 4 + 1] = gcw1[2 * tid + 1];
        sGcI[tid * 4 + 2] = gcb1[2 * tid];
        sGcI[tid * 4 + 3] = gcb1[2 * tid + 1];
    }
    if (tid < 32) {
        sGcV[tid] = gcw2[tid];
        sW34[tid * 4 + 0] = gw3[4 * tid];
        sW34[tid * 4 + 1] = gw3[4 * tid + 2];
        sW34[tid * 4 + 2] = gw3[4 * tid + 1];
        sW34[tid * 4 + 3] = gw3[4 * tid + 3];
    }
    if (tid == 0) { sCst[0] = gcb2[0]; sCst[1] = gb3[0]; sCst[2] = gb3[1]; }
    __syncthreads();

    int n    = tid & 63;
    int r    = tid >> 6;      // 0..3
    int lane = tid & 31;
    int warp = tid >> 5;      // 0..7
    int m0   = warp * 32;
    int qr   = lane >> 2;     // quad row 0..7
    int qc   = lane & 3;      // quad col 0..3
    int prId = 8 + (tid >> 6);

    u32* hsu = (u32*)hs;
    const u64* prebp = (const u64*)g_preb1p;
    const ulonglong2* WA = (const ulonglong2*)sW1fA;
    const ulonglong2* WB = (const ulonglong2*)sW1fB;
    const ulonglong2* gcWB = (const ulonglong2*)sGcI;
    const u64* gcV = (const u64*)sGcV;
    const ulonglong2* w34 = (const ulonglong2*)sW34;

    for (int tile = blockIdx.x; tile < NTILES; tile += PGRID) {
        BARP(prId);

        int gidx = tile * FTH + tid;
        float s  = seed[gidx];
        float mm = mask[gidx];
        float xf = xfreq[gidx];
        float xi = xin[gidx];

        // ---- phi(s), packed pairs ----
        u64 sp = pk2(s, s);
        u64 accp = pk2(0.f, 0.f);
        #pragma unroll
        for (int hq = 0; hq < 16; ++hq) {
            ulonglong2 wb = gcWB[hq];
            u64 pre = ffma2(sp, wb.x, wb.y);
            accp = ffma2(gelu2(pre), gcV[hq], accp);
        }
        float p0, p1; upk2(accp, p0, p1);
        sPm[r * 64 + n] = p0 + p1;
        BARP(prId);

        // ---- x_gcn (packed matvec, 2 accumulators for ILP) ----
        u64 xgpA = pk2(0.f, 0.f), xgpB = pk2(0.f, 0.f);
        const u64* arow = (const u64*)(sA + n * 66);
        const u64* prow = (const u64*)(sPm + r * 64);
        #pragma unroll 8
        for (int m2 = 0; m2 < 32; m2 += 2) {
            xgpA = ffma2(arow[m2], prow[m2], xgpA);
            xgpB = ffma2(arow[m2 + 1], prow[m2 + 1], xgpB);
        }
        u64 xgp = ffma2(xgpA, pk2(1.f, 1.f), xgpB);
        float xg0, xg1; upk2(xgp, xg0, xg1);
        float xg = xg0 + xg1 + sCst[0];

        sXg[tid] = xg; sXf[tid] = xf; sMm[tid] = mm; sXi[tid] = xi;
        out_gcn[gidx] = xg;

        // ---- layer1: folded 4 features, FFMA2 -> hs bf16x2 k-pairs ----
        u64 u0 = pk2(s, s), u1 = pk2(mm, mm), u2 = pk2(xg, xg), u3 = pk2(xf, xf);
        #pragma unroll
        for (int p = 0; p < 32; ++p) {
            u64 a = __ldg(prebp + p * 64 + n);
            ulonglong2 wa = WA[p];
            ulonglong2 wb = WB[p];
            a = ffma2(u0, wa.x, a);
            a = ffma2(u1, wa.y, a);
            a = ffma2(u2, wb.x, a);
            a = ffma2(u3, wb.y, a);
            u64 g = gelu2(a);
            float v0, v1; upk2(g, v0, v1);
            hsu[p * HS_S + tid] = bfpack(v0, v1);   // kp = p (j-pair == k-pair)
        }
        __syncwarp();   // hs columns are warp-local

        // ---- Phase B: layer2 via bf16 m16n8k16 mma ----
        float acc[2][8][4];
        #pragma unroll
        for (int n8 = 0; n8 < 8; ++n8) {
            int j0 = n8 * 8 + qc * 2;
            float2 bb = *(const float2*)(sB2 + j0);
            #pragma unroll
            for (int mt = 0; mt < 2; ++mt) {
                acc[mt][n8][0] = bb.x; acc[mt][n8][1] = bb.y;
                acc[mt][n8][2] = bb.x; acc[mt][n8][3] = bb.y;
            }
        }

        const u32* w2u = (const u32*)sW2;
        int ar = m0 + qr;
        #pragma unroll
        for (int kt = 0; kt < 4; ++kt) {
            int kp0 = kt * 8 + qc;          // k pair index for a0/a1, b0
            int kp4 = kp0 + 4;              // for a2/a3, b1
            const u32* h0 = hsu + kp0 * HS_S;
            const u32* h4 = hsu + kp4 * HS_S;
            u32 a00 = h0[ar],      a01 = h0[ar + 8],  a02 = h4[ar],      a03 = h4[ar + 8];
            u32 a10 = h0[ar + 16], a11 = h0[ar + 24], a12 = h4[ar + 16], a13 = h4[ar + 24];
            const u32* b0p = w2u + kp0 * W2_S + qr;
            const u32* b1p = w2u + kp4 * W2_S + qr;
            #pragma unroll
            for (int n8 = 0; n8 < 8; ++n8) {
                u32 b0 = b0p[n8 * 8];
                u32 b1 = b1p[n8 * 8];
                mma_bf16(acc[0][n8], a00, a01, a02, a03, b0, b1);
                mma_bf16(acc[1][n8], a10, a11, a12, a13, b0, b1);
            }
        }

        // ---- epilogue: gelu(h2) + layer3 + quad reduce ----
        #pragma unroll
        for (int mt = 0; mt < 2; ++mt) {
            #pragma unroll
            for (int half = 0; half < 2; ++half) {
                u64 lgP0 = pk2(0.f, 0.f), lgP1 = pk2(0.f, 0.f);
                #pragma unroll
                for (int n8 = 0; n8 < 8; ++n8) {
                    int j2 = n8 * 4 + qc;
                    u64 a = pk2(acc[mt][n8][2 * half], acc[mt][n8][2 * half + 1]);
                    u64 g = gelu2(a);
                    ulonglong2 w = w34[j2];
                    lgP0 = ffma2(g, w.x, lgP0);
                    lgP1 = ffma2(g, w.y, lgP1);
                }
                float l0a, l0b, l1a, l1b;
                upk2(lgP0, l0a, l0b); upk2(lgP1, l1a, l1b);
                float lg0 = l0a + l0b, lg1 = l1a + l1b;
                lg0 += __shfl_xor_sync(0xffffffffu, lg0, 1);
                lg0 += __shfl_xor_sync(0xffffffffu, lg0, 2);
                lg1 += __shfl_xor_sync(0xffffffffu, lg1, 1);
                lg1 += __shfl_xor_sync(0xffffffffu, lg1, 2);

                if (qc == half + 2 * mt) {
                    int row = m0 + qr + 8 * half + 16 * mt;
                    int og  = tile * FTH + row;
                    lg0 += sCst[1]; lg1 += sCst[2];
                    float mxv = fmaxf(lg0, lg1);
                    float e0 = __expf(lg0 - mxv), e1 = __expf(lg1 - mxv);
                    float inv = __fdividef(1.0f, e0 + e1);
                    float g0 = e0 * inv, g1 = e1 * inv;
                    float xgr = sXg[row], xfr = sXf[row], mmr = sMm[row], xir = sXi[row];
                    float imputed  = fmaf(g0, xgr, g1 * xfr);
                    float complete = (mmr != 0.f) ? imputed : xir;
                    out_imp[og]  = imputed;
                    out_comp[og] = complete;
                    float2 gv; gv.x = g0; gv.y = g1;
                    *(float2*)(out_gate + (size_t)og * 2) = gv;
                }
            }
        }
        __syncwarp();
    }
}

// ---------------------------------------------------------------------------
extern "C" void kernel_launch(void* const* d_in, const int* in_sizes, int n_in,
                              void* d_out, int out_size)
{
    const float* x     = (const float*)d_in[0];
    const float* mask  = (const float*)d_in[1];
    const int*   rid   = (const int*)  d_in[2];
    const float* emb   = (const float*)d_in[3];
    const float* gcw1  = (const float*)d_in[4];
    const float* gcb1  = (const float*)d_in[5];
    const float* gcw2  = (const float*)d_in[6];
    const float* gcb2  = (const float*)d_in[7];
    const float* fre   = (const float*)d_in[8];
    const float* fim   = (const float*)d_in[9];
    const float* rtab  = (const float*)d_in[10];
    const float* gw1   = (const float*)d_in[11];
    const float* gb1   = (const float*)d_in[12];
    const float* gw2   = (const float*)d_in[13];
    const float* gb2   = (const float*)d_in[14];
    const float* gw3   = (const float*)d_in[15];
    const float* gb3   = (const float*)d_in[16];
    float* out = (float*)d_out;

    cudaFuncSetAttribute(fused_kernel, cudaFuncAttributeMaxDynamicSharedMemorySize, SMEM_BYTES);

    prep_kernel<<<321, 256>>>(x, mask, emb, rid, rtab, gw1, gb1, fre, fim, out + ADJ_OFF);
    fill_out_kernel<<<256, 256>>>(x, mask, out + SEED_OFF);
    fft_kernel<<<B_ * N_ / 2, 256>>>(out + FREQ_OFF);
    fused_kernel<<<PGRID, FTH, SMEM_BYTES>>>(
        out + SEED_OFF, mask, x, out + FREQ_OFF,
        gw1, gw2, gb2, gw3, gb3,
        gcw1, gcb1, gcw2, gcb2,
        out + GCN_OFF, out + IMP_OFF, out + COMP_OFF, out + GATE_OFF);
}

// round 14
// speedup vs baseline: 1.2569x; 1.0442x over previous
#include <cuda_runtime.h>
#include <cuda_bf16.h>
#include <math.h>

#define B_ 16
#define T_ 2048
#define N_ 64

// Output layout (flattened tuple in order)
#define SEED_OFF 0
#define GCN_OFF  2097152
#define FREQ_OFF 4194304
#define IMP_OFF  6291456
#define COMP_OFF 8388608
#define GATE_OFF 10485760
#define ADJ_OFF  14680064

typedef unsigned long long u64;
typedef unsigned int u32;

// Scratch (static device arrays: allowed)
// Chunk-summary scratch TRANSPOSED: s = (b*64 + n)*64 + c
__device__ float  g_adj[N_ * N_];
__device__ float2 g_preb1p[32 * N_];
__device__ float  g_first[65536], g_last[65536];
__device__ unsigned char g_has[65536];
__device__ float  g_seedT[B_ * N_ * T_];        // [b][n][t]
__device__ float  g_freT[N_ * 1025];            // [n][k]
__device__ float  g_fimT[N_ * 1025];

// ---- packed f32x2 helpers ---------------------------------------------------
__device__ __forceinline__ u64 pk2(float lo, float hi) {
    u64 r; asm("mov.b64 %0, {%1, %2};" : "=l"(r) : "f"(lo), "f"(hi)); return r;
}
__device__ __forceinline__ void upk2(u64 v, float& lo, float& hi) {
    asm("mov.b64 {%0, %1}, %2;" : "=f"(lo), "=f"(hi) : "l"(v));
}
__device__ __forceinline__ u64 ffma2(u64 a, u64 b, u64 c) {
    u64 d; asm("fma.rn.f32x2 %0, %1, %2, %3;" : "=l"(d) : "l"(a), "l"(b), "l"(c)); return d;
}
__device__ __forceinline__ u64 mul2(u64 a, u64 b) {
    u64 d; asm("mul.rn.f32x2 %0, %1, %2;" : "=l"(d) : "l"(a), "l"(b)); return d;
}

__device__ __forceinline__ float tanh_ap(float x) {
    float t; asm("tanh.approx.f32 %0, %1;" : "=f"(t) : "f"(x)); return t;
}

// packed pairwise gelu
__device__ __forceinline__ u64 gelu2(u64 x) {
    const u64 C1 = pk2(0.035677408136f, 0.035677408136f);
    const u64 C0 = pk2(0.7978845608028654f, 0.7978845608028654f);
    const u64 H  = pk2(0.5f, 0.5f);
    u64 x2 = mul2(x, x);
    u64 inner = ffma2(x2, C1, C0);
    u64 b = mul2(x, inner);
    float b0, b1; upk2(b, b0, b1);
    u64 t = pk2(tanh_ap(b0), tanh_ap(b1));
    u64 hx = mul2(x, H);
    return ffma2(hx, t, hx);
}

// pack two f32 into bf16x2 (lo = first arg)
__device__ __forceinline__ u32 bfpack(float lo, float hi) {
    u32 d; asm("cvt.rn.bf16x2.f32 %0, %1, %2;" : "=r"(d) : "f"(hi), "f"(lo)); return d;
}

__device__ __forceinline__ void mma_bf16(float* d,
    u32 a0, u32 a1, u32 a2, u32 a3, u32 b0, u32 b1)
{
    asm("mma.sync.aligned.m16n8k16.row.col.f32.bf16.bf16.f32 "
        "{%0,%1,%2,%3}, {%4,%5,%6,%7}, {%8,%9}, {%0,%1,%2,%3};"
        : "+f"(d[0]), "+f"(d[1]), "+f"(d[2]), "+f"(d[3])
        : "r"(a0), "r"(a1), "r"(a2), "r"(a3), "r"(b0), "r"(b1));
}

#define BARP(id) asm volatile("bar.sync %0, %1;" :: "r"(id), "r"(64) : "memory")

// ---------------------------------------------------------------------------
// Kernel 0: prep = fill_sum (blk<256) + filter transpose (blk 256-319)
//                + adjacency/preb1 (blk 320). All independent.
// ---------------------------------------------------------------------------
__global__ void __launch_bounds__(256) prep_kernel(
    const float* __restrict__ x, const float* __restrict__ mask,
    const float* __restrict__ emb, const int* __restrict__ rate_id,
    const float* __restrict__ rate_table, const float* __restrict__ gw1,
    const float* __restrict__ gb1,
    const float* __restrict__ fre, const float* __restrict__ fim,
    float* __restrict__ out_adj)
{
    int blk = blockIdx.x;
    int tid = threadIdx.x;

    if (blk < 256) {
        int g = blk * 256 + tid;
        int n = g & 63;
        int c = (g >> 6) & 63;
        int b = g >> 12;
        int base = ((b * T_) + c * 32) * N_ + n;
        float first = 0.f, last = 0.f; bool has = false;
        #pragma unroll
        for (int t = 0; t < 32; ++t) {
            int idx = base + t * N_;
            float v = x[idx];
            bool obs = (mask[idx] == 0.f);
            if (obs) { if (!has) first = v; last = v; has = true; }
        }
        int s = ((b << 6) + n) * 64 + c;
        g_first[s] = first; g_last[s] = last; g_has[s] = (unsigned char)has;
        return;
    }

    if (blk < 320) {
        int n = blk - 256;
        for (int k = tid; k < 1025; k += 256) {
            g_freT[n * 1025 + k] = fre[(size_t)k * N_ + n];
            g_fimT[n * 1025 + k] = fim[(size_t)k * N_ + n];
        }
        return;
    }

    // adjacency + rate-embed pre-bias (threads 0-63)
    __shared__ float sE[64 * 32];
    for (int i = tid; i < 64 * 32; i += 256) sE[i] = emb[i];
    __syncthreads();
    if (tid >= 64) return;

    float sc[64];
    float mx = -1e30f;
    #pragma unroll
    for (int m = 0; m < 64; ++m) {
        float d = 0.f;
        #pragma unroll
        for (int h = 0; h < 32; ++h) d = fmaf(sE[tid * 32 + h], sE[m * 32 + h], d);
        d = fmaxf(d, 0.f);
        sc[m] = d; mx = fmaxf(mx, d);
    }
    float sum = 0.f;
    #pragma unroll
    for (int m = 0; m < 64; ++m) { float e = __expf(sc[m] - mx); sc[m] = e; sum += e; }
    float inv = 1.0f / sum;
    #pragma unroll
    for (int m = 0; m < 64; ++m) {
        float a = sc[m] * inv;
        g_adj[tid * 64 + m] = a;
        out_adj[tid * 64 + m] = a;
    }
    int rid = rate_id[tid];
    for (int j2 = 0; j2 < 32; ++j2) {
        float v0 = gb1[2 * j2], v1 = gb1[2 * j2 + 1];
        #pragma unroll
        for (int e = 0; e < 16; ++e) {
            float rt = rate_table[rid * 16 + e];
            v0 = fmaf(rt, gw1[(6 + e) * 64 + 2 * j2], v0);
            v1 = fmaf(rt, gw1[(6 + e) * 64 + 2 * j2 + 1], v1);
        }
        g_preb1p[j2 * 64 + tid] = make_float2(v0, v1);
    }
}

// ---------------------------------------------------------------------------
// Kernel 1: fill_out v2 — in-block scan + fill phase.
// ---------------------------------------------------------------------------
__global__ void __launch_bounds__(256) fill_out_kernel(
    const float* __restrict__ x, const float* __restrict__ mask,
    float* __restrict__ seed)
{
    __shared__ float sPr[256], sSu[256];
    __shared__ unsigned char sPrh[256], sSuh[256];

    int blk = blockIdx.x;
    int b = blk >> 4;
    int c0 = (blk & 15) * 4;
    int tid = threadIdx.x;

    if (tid < 64) {
        int bn = (b << 6) + tid;
        const float* fp = g_first + bn * 64;
        const float* lp = g_last + bn * 64;
        const unsigned char* hp = g_has + bn * 64;
        float pv = 0.f; bool ph = false;
        #pragma unroll 8
        for (int c = 0; c < 64; ++c) {
            unsigned d = (unsigned)(c - c0);
            if (d < 4u) { sPr[d * 64 + tid] = pv; sPrh[d * 64 + tid] = (unsigned char)ph; }
            if (hp[c]) { pv = lp[c]; ph = true; }
        }
        float sv = 0.f; bool sh = false;
        #pragma unroll 8
        for (int c = 63; c >= 0; --c) {
            unsigned d = (unsigned)(c - c0);
            if (d < 4u) { sSu[d * 64 + tid] = sv; sSuh[d * 64 + tid] = (unsigned char)sh; }
            if (hp[c]) { sv = fp[c]; sh = true; }
        }
    }
    __syncthreads();

    int n = tid & 63;
    int cl = tid >> 6;
    int c = c0 + cl;
    int base = ((b * T_) + c * 32) * N_ + n;
    float* tdst = g_seedT + ((size_t)(b * 64 + n)) * T_ + c * 32;

    float fv = sPr[cl * 64 + n]; bool fh = (bool)sPrh[cl * 64 + n];
    float vals[32];
    unsigned obsm = 0u, fam = 0u;
    #pragma unroll
    for (int t = 0; t < 32; ++t) {
        int idx = base + t * N_;
        float v = x[idx];
        bool obs = (mask[idx] == 0.f);
        if (obs) { fv = v; fh = true; obsm |= (1u << t); }
        vals[t] = fv;
        if (fh) fam |= (1u << t);
    }
    float bv = sSu[cl * 64 + n]; bool bh = (bool)sSuh[cl * 64 + n];
    #pragma unroll
    for (int t = 31; t >= 0; --t) {
        bool obs = (obsm >> t) & 1u;
        bool fa  = (fam  >> t) & 1u;
        float v = vals[t];
        if (obs) { bv = v; bh = true; }
        float out;
        if (obs)            out = v;
        else if (fa && bh)  out = 0.5f * (v + bv);
        else if (fa)        out = v;
        else if (bh)        out = bv;
        else                out = 0.f;
        seed[base + t * N_] = out;
        tdst[t] = out;
    }
}

// ---------------------------------------------------------------------------
// Kernel 2: packed-pair radix-2 FFT filter; float2 data + interleaved
// twiddles (half the shared-memory instructions; bit-identical math).
// ---------------------------------------------------------------------------
__global__ void __launch_bounds__(256) fft_kernel(
    float* __restrict__ xfreq)
{
    __shared__ float2 cbuf[2048];
    __shared__ float2 tw[1024];
    int tid = threadIdx.x;
    int b = blockIdx.x >> 5;
    int p = blockIdx.x & 31;
    int n0 = p * 2;
    const float* src0 = g_seedT + ((size_t)(b * 64 + n0)) * T_;
    const float* src1 = src0 + T_;

    for (int j = tid; j < 1024; j += 256) {
        float s, c;
        sincosf(-6.28318530717958647692f * (float)j * (1.0f / 2048.0f), &s, &c);
        tw[j] = make_float2(c, s);
    }
    for (int t = tid; t < 2048; t += 256) {
        cbuf[t] = make_float2(src0[t], src1[t]);
    }

    for (int s = 10; s >= 0; --s) {
        int half = 1 << s;
        __syncthreads();
        for (int bi = tid; bi < 1024; bi += 256) {
            int j = bi & (half - 1);
            int i1 = ((bi >> s) << (s + 1)) | j;
            int i2 = i1 + half;
            int tj = j << (10 - s);
            float2 w = tw[tj];
            float2 a = cbuf[i1], bb = cbuf[i2];
            cbuf[i1] = make_float2(a.x + bb.x, a.y + bb.y);
            float dr = a.x - bb.x, di = a.y - bb.y;
            cbuf[i2] = make_float2(dr * w.x - di * w.y, dr * w.y + di * w.x);
        }
    }
    __syncthreads();

    const float* fT0r = g_freT + n0 * 1025;
    const float* fT0i = g_fimT + n0 * 1025;
    const float* fT1r = fT0r + 1025;
    const float* fT1i = fT0i + 1025;
    for (int k = tid; k <= 1024; k += 256) {
        int km = (2048 - k) & 2047;
        int pk = __brev(k) >> 21;
        int pm = __brev(km) >> 21;
        float2 z = cbuf[pk];
        float2 y = cbuf[pm];
        float x1r = 0.5f * (z.x + y.x), x1i = 0.5f * (z.y - y.y);
        float x2r = 0.5f * (z.y + y.y), x2i = 0.5f * (y.x - z.x);
        float h1r = fT0r[k], h1i = fT0i[k];
        float h2r = fT1r[k], h2i = fT1i[k];
        float y1r = x1r * h1r - x1i * h1i, y1i = x1r * h1i + x1i * h1r;
        float y2r = x2r * h2r - x2i * h2i, y2i = x2r * h2i + x2i * h2r;
        if (k == 0 || k == 1024) { y1i = 0.f; y2i = 0.f; }
        cbuf[pk] = make_float2(y1r - y2i, y1i + y2r);
        if (k > 0 && k < 1024) cbuf[pm] = make_float2(y1r + y2i, y2r - y1i);
    }

    for (int s = 0; s <= 10; ++s) {
        int half = 1 << s;
        __syncthreads();
        for (int bi = tid; bi < 1024; bi += 256) {
            int j = bi & (half - 1);
            int i1 = ((bi >> s) << (s + 1)) | j;
            int i2 = i1 + half;
            int tj = j << (10 - s);
            float2 w = tw[tj];            // conj applied inline: wi = -w.y
            float2 bb = cbuf[i2];
            float tr = bb.x * w.x + bb.y * w.y;
            float ti = bb.y * w.x - bb.x * w.y;
            float2 a = cbuf[i1];
            cbuf[i1] = make_float2(a.x + tr, a.y + ti);
            cbuf[i2] = make_float2(a.x - tr, a.y - ti);
        }
    }
    __syncthreads();

    float* dst = xfreq + (size_t)b * T_ * N_ + n0;
    const float scl = 1.0f / 2048.0f;
    for (int t = tid; t < 2048; t += 256) {
        float2 v; v.x = cbuf[t].x * scl; v.y = cbuf[t].y * scl;
        *(float2*)(dst + (size_t)t * N_) = v;
    }
}

// ---------------------------------------------------------------------------
// Kernel 3 v11: bf16 mma layer2; s-prefetch; w34-hoisted epilogue.
// ---------------------------------------------------------------------------
#define FTH 256
#define HS_S 264
#define W2_S 72
#define NTILES (B_ * T_ * N_ / FTH)   // 8192
#define PGRID 296
#define SMEM_BYTES (16804 * 4)

__global__ void __launch_bounds__(FTH, 2) fused_kernel(
    const float* __restrict__ seed, const float* __restrict__ mask,
    const float* __restrict__ xin, const float* __restrict__ xfreq,
    const float* __restrict__ gw1, const float* __restrict__ gw2,
    const float* __restrict__ gb2, const float* __restrict__ gw3,
    const float* __restrict__ gb3,
    const float* __restrict__ gcw1, const float* __restrict__ gcb1,
    const float* __restrict__ gcw2, const float* __restrict__ gcb2,
    float* __restrict__ out_gcn, float* __restrict__ out_imp,
    float* __restrict__ out_comp, float* __restrict__ out_gate)
{
    extern __shared__ float sm[];
    float* hs    = sm;                    // [32][264] bf16x2 (u32)
    float* sW2   = hs    + 32 * HS_S;     // [32][72] bf16x2
    float* sA    = sW2   + 32 * W2_S;     // [64][66]
    float* sW1fA = sA    + 64 * 66;       // [32]{f0pair,f1pair}
    float* sW1fB = sW1fA + 128;           // [32]{f2pair,f3pair}
    float* sGcI  = sW1fB + 128;           // [16]{w pair, b pair}
    float* sGcV  = sGcI  + 64;            // [32]
    float* sW34  = sGcV  + 32;            // [32]{we pair, wo pair}
    float* sB2   = sW34  + 128;           // [64]
    float* sPm   = sB2   + 64;            // [4][64]
    float* sXg   = sPm   + FTH;
    float* sXf   = sXg   + FTH;
    float* sMm   = sXf   + FTH;
    float* sXi   = sMm   + FTH;
    float* sCst  = sXi   + FTH;           // [4]

    int tid = threadIdx.x;

    // ---- stage weights once ----
    for (int i = tid; i < 2048; i += FTH) {
        int kp = i >> 6, j = i & 63;
        ((u32*)sW2)[kp * W2_S + j] = bfpack(gw2[(2 * kp) * 64 + j], gw2[(2 * kp + 1) * 64 + j]);
    }
    for (int i = tid; i < 4096; i += FTH) sA[(i >> 6) * 66 + (i & 63)] = g_adj[i];
    if (tid < 64) {
        int j = tid;
        float wf0 = gw1[0 * 64 + j] - gw1[4 * 64 + j] - gw1[5 * 64 + j];
        float wf1 = gw1[1 * 64 + j];
        float wf2 = gw1[2 * 64 + j] + gw1[4 * 64 + j];
        float wf3 = gw1[3 * 64 + j] + gw1[5 * 64 + j];
        int p = j >> 1, o = j & 1;
        sW1fA[p * 4 + o]     = wf0;
        sW1fA[p * 4 + 2 + o] = wf1;
        sW1fB[p * 4 + o]     = wf2;
        sW1fB[p * 4 + 2 + o] = wf3;
        sB2[j] = gb2[j];
    }
    if (tid < 16) {
        sGcI[tid * 4 + 0] = gcw1[2 * tid];
        sGcI[tid * 4 + 1] = gcw1[2 * tid + 1];
        sGcI[tid * 4 + 2] = gcb1[2 * tid];
        sGcI[tid * 4 + 3] = gcb1[2 * tid + 1];
    }
    if (tid < 32) {
        sGcV[tid] = gcw2[tid];
        sW34[tid * 4 + 0] = gw3[4 * tid];
        sW34[tid * 4 + 1] = gw3[4 * tid + 2];
        sW34[tid * 4 + 2] = gw3[4 * tid + 1];
        sW34[tid * 4 + 3] = gw3[4 * tid + 3];
    }
    if (tid == 0) { sCst[0] = gcb2[0]; sCst[1] = gb3[0]; sCst[2] = gb3[1]; }
    __syncthreads();

    int n    = tid & 63;
    int r    = tid >> 6;      // 0..3
    int lane = tid & 31;
    int warp = tid >> 5;      // 0..7
    int m0   = warp * 32;
    int qr   = lane >> 2;     // quad row 0..7
    int qc   = lane & 3;      // quad col 0..3
    int prId = 8 + (tid >> 6);

    u32* hsu = (u32*)hs;
    const u64* prebp = (const u64*)g_preb1p;
    const ulonglong2* WA = (const ulonglong2*)sW1fA;
    const ulonglong2* WB = (const ulonglong2*)sW1fB;
    const ulonglong2* gcWB = (const ulonglong2*)sGcI;
    const u64* gcV = (const u64*)sGcV;
    const ulonglong2* w34 = (const ulonglong2*)sW34;

    // prefetch first tile's seed value (phi consumes it immediately)
    float s_cur = seed[blockIdx.x * FTH + tid];

    for (int tile = blockIdx.x; tile < NTILES; tile += PGRID) {
        BARP(prId);

        int gidx = tile * FTH + tid;
        float s  = s_cur;
        float mm = mask[gidx];
        float xf = xfreq[gidx];
        float xi = xin[gidx];

        // ---- phi(s), packed pairs ----
        u64 sp = pk2(s, s);
        u64 accp = pk2(0.f, 0.f);
        #pragma unroll
        for (int hq = 0; hq < 16; ++hq) {
            ulonglong2 wb = gcWB[hq];
            u64 pre = ffma2(sp, wb.x, wb.y);
            accp = ffma2(gelu2(pre), gcV[hq], accp);
        }
        float p0, p1; upk2(accp, p0, p1);
        sPm[r * 64 + n] = p0 + p1;
        BARP(prId);

        // ---- x_gcn (packed matvec, 2 accumulators for ILP) ----
        u64 xgpA = pk2(0.f, 0.f), xgpB = pk2(0.f, 0.f);
        const u64* arow = (const u64*)(sA + n * 66);
        const u64* prow = (const u64*)(sPm + r * 64);
        #pragma unroll 8
        for (int m2 = 0; m2 < 32; m2 += 2) {
            xgpA = ffma2(arow[m2], prow[m2], xgpA);
            xgpB = ffma2(arow[m2 + 1], prow[m2 + 1], xgpB);
        }
        u64 xgp = ffma2(xgpA, pk2(1.f, 1.f), xgpB);
        float xg0, xg1; upk2(xgp, xg0, xg1);
        float xg = xg0 + xg1 + sCst[0];

        sXg[tid] = xg; sXf[tid] = xf; sMm[tid] = mm; sXi[tid] = xi;
        out_gcn[gidx] = xg;

        // ---- layer1: folded 4 features, FFMA2 -> hs bf16x2 k-pairs ----
        u64 u0 = pk2(s, s), u1 = pk2(mm, mm), u2 = pk2(xg, xg), u3 = pk2(xf, xf);
        #pragma unroll
        for (int p = 0; p < 32; ++p) {
            u64 a = __ldg(prebp + p * 64 + n);
            ulonglong2 wa = WA[p];
            ulonglong2 wb = WB[p];
            a = ffma2(u0, wa.x, a);
            a = ffma2(u1, wa.y, a);
            a = ffma2(u2, wb.x, a);
            a = ffma2(u3, wb.y, a);
            u64 g = gelu2(a);
            float v0, v1; upk2(g, v0, v1);
            hsu[p * HS_S + tid] = bfpack(v0, v1);
        }
        __syncwarp();

        // ---- prefetch next tile's seed (hidden under phase B) ----
        {
            int ntile = tile + PGRID;
            if (ntile < NTILES) s_cur = seed[ntile * FTH + tid];
        }

        // ---- Phase B: layer2 via bf16 m16n8k16 mma ----
        float acc[2][8][4];
        #pragma unroll
        for (int n8 = 0; n8 < 8; ++n8) {
            int j0 = n8 * 8 + qc * 2;
            float2 bb = *(const float2*)(sB2 + j0);
            #pragma unroll
            for (int mt = 0; mt < 2; ++mt) {
                acc[mt][n8][0] = bb.x; acc[mt][n8][1] = bb.y;
                acc[mt][n8][2] = bb.x; acc[mt][n8][3] = bb.y;
            }
        }

        const u32* w2u = (const u32*)sW2;
        int ar = m0 + qr;
        #pragma unroll
        for (int kt = 0; kt < 4; ++kt) {
            int kp0 = kt * 8 + qc;
            int kp4 = kp0 + 4;
            const u32* h0 = hsu + kp0 * HS_S;
            const u32* h4 = hsu + kp4 * HS_S;
            u32 a00 = h0[ar],      a01 = h0[ar + 8],  a02 = h4[ar],      a03 = h4[ar + 8];
            u32 a10 = h0[ar + 16], a11 = h0[ar + 24], a12 = h4[ar + 16], a13 = h4[ar + 24];
            const u32* b0p = w2u + kp0 * W2_S + qr;
            const u32* b1p = w2u + kp4 * W2_S + qr;
            #pragma unroll
            for (int n8 = 0; n8 < 8; ++n8) {
                u32 b0 = b0p[n8 * 8];
                u32 b1 = b1p[n8 * 8];
                mma_bf16(acc[0][n8], a00, a01, a02, a03, b0, b1);
                mma_bf16(acc[1][n8], a10, a11, a12, a13, b0, b1);
            }
        }

        // ---- epilogue: n8-outer, w34 loaded once and reused x4 ----
        u64 lg[2][2][2];
        #pragma unroll
        for (int mt = 0; mt < 2; ++mt)
            #pragma unroll
            for (int half = 0; half < 2; ++half) {
                lg[mt][half][0] = pk2(0.f, 0.f);
                lg[mt][half][1] = pk2(0.f, 0.f);
            }
        #pragma unroll
        for (int n8 = 0; n8 < 8; ++n8) {
            ulonglong2 w = w34[n8 * 4 + qc];
            #pragma unroll
            for (int mt = 0; mt < 2; ++mt)
                #pragma unroll
                for (int half = 0; half < 2; ++half) {
                    u64 a = pk2(acc[mt][n8][2 * half], acc[mt][n8][2 * half + 1]);
                    u64 g = gelu2(a);
                    lg[mt][half][0] = ffma2(g, w.x, lg[mt][half][0]);
                    lg[mt][half][1] = ffma2(g, w.y, lg[mt][half][1]);
                }
        }

        #pragma unroll
        for (int mt = 0; mt < 2; ++mt) {
            #pragma unroll
            for (int half = 0; half < 2; ++half) {
                float l0a, l0b, l1a, l1b;
                upk2(lg[mt][half][0], l0a, l0b);
                upk2(lg[mt][half][1], l1a, l1b);
                float lg0 = l0a + l0b, lg1 = l1a + l1b;
                lg0 += __shfl_xor_sync(0xffffffffu, lg0, 1);
                lg0 += __shfl_xor_sync(0xffffffffu, lg0, 2);
                lg1 += __shfl_xor_sync(0xffffffffu, lg1, 1);
                lg1 += __shfl_xor_sync(0xffffffffu, lg1, 2);

                if (qc == half + 2 * mt) {
                    int row = m0 + qr + 8 * half + 16 * mt;
                    int og  = tile * FTH + row;
                    lg0 += sCst[1]; lg1 += sCst[2];
                    float mxv = fmaxf(lg0, lg1);
                    float e0 = __expf(lg0 - mxv), e1 = __expf(lg1 - mxv);
                    float inv = __fdividef(1.0f, e0 + e1);
                    float g0 = e0 * inv, g1 = e1 * inv;
                    float xgr = sXg[row], xfr = sXf[row], mmr = sMm[row], xir = sXi[row];
                    float imputed  = fmaf(g0, xgr, g1 * xfr);
                    float complete = (mmr != 0.f) ? imputed : xir;
                    out_imp[og]  = imputed;
                    out_comp[og] = complete;
                    float2 gv; gv.x = g0; gv.y = g1;
                    *(float2*)(out_gate + (size_t)og * 2) = gv;
                }
            }
        }
        __syncwarp();
    }
}

// ---------------------------------------------------------------------------
extern "C" void kernel_launch(void* const* d_in, const int* in_sizes, int n_in,
                              void* d_out, int out_size)
{
    const float* x     = (const float*)d_in[0];
    const float* mask  = (const float*)d_in[1];
    const int*   rid   = (const int*)  d_in[2];
    const float* emb   = (const float*)d_in[3];
    const float* gcw1  = (const float*)d_in[4];
    const float* gcb1  = (const float*)d_in[5];
    const float* gcw2  = (const float*)d_in[6];
    const float* gcb2  = (const float*)d_in[7];
    const float* fre   = (const float*)d_in[8];
    const float* fim   = (const float*)d_in[9];
    const float* rtab  = (const float*)d_in[10];
    const float* gw1   = (const float*)d_in[11];
    const float* gb1   = (const float*)d_in[12];
    const float* gw2   = (const float*)d_in[13];
    const float* gb2   = (const float*)d_in[14];
    const float* gw3   = (const float*)d_in[15];
    const float* gb3   = (const float*)d_in[16];
    float* out = (float*)d_out;

    cudaFuncSetAttribute(fused_kernel, cudaFuncAttributeMaxDynamicSharedMemorySize, SMEM_BYTES);

    prep_kernel<<<321, 256>>>(x, mask, emb, rid, rtab, gw1, gb1, fre, fim, out + ADJ_OFF);
    fill_out_kernel<<<256, 256>>>(x, mask, out + SEED_OFF);
    fft_kernel<<<B_ * N_ / 2, 256>>>(out + FREQ_OFF);
    fused_kernel<<<PGRID, FTH, SMEM_BYTES>>>(
        out + SEED_OFF, mask, x, out + FREQ_OFF,
        gw1, gw2, gb2, gw3, gb3,
        gcw1, gcb1, gcw2, gcb2,
        out + GCN_OFF, out + IMP_OFF, out + COMP_OFF, out + GATE_OFF);
}

// round 15
// speedup vs baseline: 1.3139x; 1.0454x over previous
#include <cuda_runtime.h>
#include <cuda_bf16.h>
#include <math.h>

#define B_ 16
#define T_ 2048
#define N_ 64

// Output layout (flattened tuple in order)
#define SEED_OFF 0
#define GCN_OFF  2097152
#define FREQ_OFF 4194304
#define IMP_OFF  6291456
#define COMP_OFF 8388608
#define GATE_OFF 10485760
#define ADJ_OFF  14680064

typedef unsigned long long u64;
typedef unsigned int u32;

// Scratch (static device arrays: allowed)
// Chunk-summary scratch TRANSPOSED: s = (b*64 + n)*64 + c
__device__ float  g_adj[N_ * N_];
__device__ float2 g_preb1p[32 * N_];
__device__ float  g_first[65536], g_last[65536];
__device__ unsigned char g_has[65536];
__device__ float  g_seedT[B_ * N_ * T_];        // [b][n][t]
__device__ float  g_freT[N_ * 1025];            // [n][k]
__device__ float  g_fimT[N_ * 1025];

// ---- packed f32x2 helpers ---------------------------------------------------
__device__ __forceinline__ u64 pk2(float lo, float hi) {
    u64 r; asm("mov.b64 %0, {%1, %2};" : "=l"(r) : "f"(lo), "f"(hi)); return r;
}
__device__ __forceinline__ void upk2(u64 v, float& lo, float& hi) {
    asm("mov.b64 {%0, %1}, %2;" : "=f"(lo), "=f"(hi) : "l"(v));
}
__device__ __forceinline__ u64 ffma2(u64 a, u64 b, u64 c) {
    u64 d; asm("fma.rn.f32x2 %0, %1, %2, %3;" : "=l"(d) : "l"(a), "l"(b), "l"(c)); return d;
}
__device__ __forceinline__ u64 mul2(u64 a, u64 b) {
    u64 d; asm("mul.rn.f32x2 %0, %1, %2;" : "=l"(d) : "l"(a), "l"(b)); return d;
}

__device__ __forceinline__ float tanh_ap(float x) {
    float t; asm("tanh.approx.f32 %0, %1;" : "=f"(t) : "f"(x)); return t;
}

// packed pairwise gelu
__device__ __forceinline__ u64 gelu2(u64 x) {
    const u64 C1 = pk2(0.035677408136f, 0.035677408136f);
    const u64 C0 = pk2(0.7978845608028654f, 0.7978845608028654f);
    const u64 H  = pk2(0.5f, 0.5f);
    u64 x2 = mul2(x, x);
    u64 inner = ffma2(x2, C1, C0);
    u64 b = mul2(x, inner);
    float b0, b1; upk2(b, b0, b1);
    u64 t = pk2(tanh_ap(b0), tanh_ap(b1));
    u64 hx = mul2(x, H);
    return ffma2(hx, t, hx);
}

// pack two f32 into bf16x2 (lo = first arg)
__device__ __forceinline__ u32 bfpack(float lo, float hi) {
    u32 d; asm("cvt.rn.bf16x2.f32 %0, %1, %2;" : "=r"(d) : "f"(hi), "f"(lo)); return d;
}

__device__ __forceinline__ void mma_bf16(float* d,
    u32 a0, u32 a1, u32 a2, u32 a3, u32 b0, u32 b1)
{
    asm("mma.sync.aligned.m16n8k16.row.col.f32.bf16.bf16.f32 "
        "{%0,%1,%2,%3}, {%4,%5,%6,%7}, {%8,%9}, {%0,%1,%2,%3};"
        : "+f"(d[0]), "+f"(d[1]), "+f"(d[2]), "+f"(d[3])
        : "r"(a0), "r"(a1), "r"(a2), "r"(a3), "r"(b0), "r"(b1));
}

#define BARP(id) asm volatile("bar.sync %0, %1;" :: "r"(id), "r"(64) : "memory")

// complex helpers matching the exact scalar formulas used previously
__device__ __forceinline__ float2 cadd(float2 a, float2 b) { return make_float2(a.x + b.x, a.y + b.y); }
__device__ __forceinline__ float2 csub(float2 a, float2 b) { return make_float2(a.x - b.x, a.y - b.y); }
// forward:  (d) * w   with  re = dr*wx - di*wy ; im = dr*wy + di*wx
__device__ __forceinline__ float2 cmulf(float2 d, float2 w) {
    return make_float2(d.x * w.x - d.y * w.y, d.x * w.y + d.y * w.x);
}
// inverse:  (b) * conj(w)  with  tr = bx*wx + by*wy ; ti = by*wx - bx*wy
__device__ __forceinline__ float2 cmulc(float2 b, float2 w) {
    return make_float2(b.x * w.x + b.y * w.y, b.y * w.x - b.x * w.y);
}

// ---------------------------------------------------------------------------
// Kernel 0: prep = fill_sum (blk<256) + filter transpose (blk 256-319)
//                + adjacency/preb1 (blk 320). All independent.
// ---------------------------------------------------------------------------
__global__ void __launch_bounds__(256) prep_kernel(
    const float* __restrict__ x, const float* __restrict__ mask,
    const float* __restrict__ emb, const int* __restrict__ rate_id,
    const float* __restrict__ rate_table, const float* __restrict__ gw1,
    const float* __restrict__ gb1,
    const float* __restrict__ fre, const float* __restrict__ fim,
    float* __restrict__ out_adj)
{
    int blk = blockIdx.x;
    int tid = threadIdx.x;

    if (blk < 256) {
        int g = blk * 256 + tid;
        int n = g & 63;
        int c = (g >> 6) & 63;
        int b = g >> 12;
        int base = ((b * T_) + c * 32) * N_ + n;
        float first = 0.f, last = 0.f; bool has = false;
        #pragma unroll
        for (int t = 0; t < 32; ++t) {
            int idx = base + t * N_;
            float v = x[idx];
            bool obs = (mask[idx] == 0.f);
            if (obs) { if (!has) first = v; last = v; has = true; }
        }
        int s = ((b << 6) + n) * 64 + c;
        g_first[s] = first; g_last[s] = last; g_has[s] = (unsigned char)has;
        return;
    }

    if (blk < 320) {
        int n = blk - 256;
        for (int k = tid; k < 1025; k += 256) {
            g_freT[n * 1025 + k] = fre[(size_t)k * N_ + n];
            g_fimT[n * 1025 + k] = fim[(size_t)k * N_ + n];
        }
        return;
    }

    // adjacency + rate-embed pre-bias (threads 0-63)
    __shared__ float sE[64 * 32];
    for (int i = tid; i < 64 * 32; i += 256) sE[i] = emb[i];
    __syncthreads();
    if (tid >= 64) return;

    float sc[64];
    float mx = -1e30f;
    #pragma unroll
    for (int m = 0; m < 64; ++m) {
        float d = 0.f;
        #pragma unroll
        for (int h = 0; h < 32; ++h) d = fmaf(sE[tid * 32 + h], sE[m * 32 + h], d);
        d = fmaxf(d, 0.f);
        sc[m] = d; mx = fmaxf(mx, d);
    }
    float sum = 0.f;
    #pragma unroll
    for (int m = 0; m < 64; ++m) { float e = __expf(sc[m] - mx); sc[m] = e; sum += e; }
    float inv = 1.0f / sum;
    #pragma unroll
    for (int m = 0; m < 64; ++m) {
        float a = sc[m] * inv;
        g_adj[tid * 64 + m] = a;
        out_adj[tid * 64 + m] = a;
    }
    int rid = rate_id[tid];
    for (int j2 = 0; j2 < 32; ++j2) {
        float v0 = gb1[2 * j2], v1 = gb1[2 * j2 + 1];
        #pragma unroll
        for (int e = 0; e < 16; ++e) {
            float rt = rate_table[rid * 16 + e];
            v0 = fmaf(rt, gw1[(6 + e) * 64 + 2 * j2], v0);
            v1 = fmaf(rt, gw1[(6 + e) * 64 + 2 * j2 + 1], v1);
        }
        g_preb1p[j2 * 64 + tid] = make_float2(v0, v1);
    }
}

// ---------------------------------------------------------------------------
// Kernel 1: fill_out v2 — in-block scan + fill phase.
// ---------------------------------------------------------------------------
__global__ void __launch_bounds__(256) fill_out_kernel(
    const float* __restrict__ x, const float* __restrict__ mask,
    float* __restrict__ seed)
{
    __shared__ float sPr[256], sSu[256];
    __shared__ unsigned char sPrh[256], sSuh[256];

    int blk = blockIdx.x;
    int b = blk >> 4;
    int c0 = (blk & 15) * 4;
    int tid = threadIdx.x;

    if (tid < 64) {
        int bn = (b << 6) + tid;
        const float* fp = g_first + bn * 64;
        const float* lp = g_last + bn * 64;
        const unsigned char* hp = g_has + bn * 64;
        float pv = 0.f; bool ph = false;
        #pragma unroll 8
        for (int c = 0; c < 64; ++c) {
            unsigned d = (unsigned)(c - c0);
            if (d < 4u) { sPr[d * 64 + tid] = pv; sPrh[d * 64 + tid] = (unsigned char)ph; }
            if (hp[c]) { pv = lp[c]; ph = true; }
        }
        float sv = 0.f; bool sh = false;
        #pragma unroll 8
        for (int c = 63; c >= 0; --c) {
            unsigned d = (unsigned)(c - c0);
            if (d < 4u) { sSu[d * 64 + tid] = sv; sSuh[d * 64 + tid] = (unsigned char)sh; }
            if (hp[c]) { sv = fp[c]; sh = true; }
        }
    }
    __syncthreads();

    int n = tid & 63;
    int cl = tid >> 6;
    int c = c0 + cl;
    int base = ((b * T_) + c * 32) * N_ + n;
    float* tdst = g_seedT + ((size_t)(b * 64 + n)) * T_ + c * 32;

    float fv = sPr[cl * 64 + n]; bool fh = (bool)sPrh[cl * 64 + n];
    float vals[32];
    unsigned obsm = 0u, fam = 0u;
    #pragma unroll
    for (int t = 0; t < 32; ++t) {
        int idx = base + t * N_;
        float v = x[idx];
        bool obs = (mask[idx] == 0.f);
        if (obs) { fv = v; fh = true; obsm |= (1u << t); }
        vals[t] = fv;
        if (fh) fam |= (1u << t);
    }
    float bv = sSu[cl * 64 + n]; bool bh = (bool)sSuh[cl * 64 + n];
    #pragma unroll
    for (int t = 31; t >= 0; --t) {
        bool obs = (obsm >> t) & 1u;
        bool fa  = (fam  >> t) & 1u;
        float v = vals[t];
        if (obs) { bv = v; bh = true; }
        float out;
        if (obs)            out = v;
        else if (fa && bh)  out = 0.5f * (v + bv);
        else if (fa)        out = v;
        else if (bh)        out = bv;
        else                out = 0.f;
        seed[base + t * N_] = out;
        tdst[t] = out;
    }
}

// ---------------------------------------------------------------------------
// Kernel 2: FFT filter with MERGED radix-2 stage pairs (half the passes,
// bit-identical butterflies). float2 data + interleaved twiddles.
// ---------------------------------------------------------------------------
__global__ void __launch_bounds__(256) fft_kernel(
    float* __restrict__ xfreq)
{
    __shared__ float2 cbuf[2048];
    __shared__ float2 tw[1024];
    int tid = threadIdx.x;
    int b = blockIdx.x >> 5;
    int p = blockIdx.x & 31;
    int n0 = p * 2;
    const float* src0 = g_seedT + ((size_t)(b * 64 + n0)) * T_;
    const float* src1 = src0 + T_;

    for (int j = tid; j < 1024; j += 256) {
        float s, c;
        sincosf(-6.28318530717958647692f * (float)j * (1.0f / 2048.0f), &s, &c);
        tw[j] = make_float2(c, s);
    }
    for (int t = tid; t < 2048; t += 256) {
        cbuf[t] = make_float2(src0[t], src1[t]);
    }

    // ---- Forward DIF: merged pairs (10,9)(8,7)(6,5)(4,3)(2,1), single 0 ----
    #pragma unroll
    for (int s = 10; s >= 2; s -= 2) {
        int h = 1 << s, h2 = h >> 1;
        __syncthreads();
        for (int g = tid; g < 512; g += 256) {
            int j = g & (h2 - 1);
            int blk = g >> (s - 1);
            int i = blk * (h << 1) + j;
            float2 a0 = cbuf[i], a1 = cbuf[i + h2], a2 = cbuf[i + h], a3 = cbuf[i + h + h2];
            float2 w0 = tw[j << (10 - s)];
            float2 w1 = tw[(j + h2) << (10 - s)];
            float2 v  = tw[j << (11 - s)];
            // stage s
            float2 s0 = cadd(a0, a2), p2 = cmulf(csub(a0, a2), w0);
            float2 s1 = cadd(a1, a3), p3 = cmulf(csub(a1, a3), w1);
            // stage s-1
            cbuf[i]          = cadd(s0, s1);
            cbuf[i + h2]     = cmulf(csub(s0, s1), v);
            cbuf[i + h]      = cadd(p2, p3);
            cbuf[i + h + h2] = cmulf(csub(p2, p3), v);
        }
    }
    // single stage 0
    __syncthreads();
    for (int bi = tid; bi < 1024; bi += 256) {
        int i1 = bi << 1;
        int i2 = i1 + 1;
        float2 a = cbuf[i1], bb = cbuf[i2];
        cbuf[i1] = cadd(a, bb);
        cbuf[i2] = csub(a, bb);   // tw[0] = (1,0)
    }
    __syncthreads();

    // ---- filter in bit-reversed domain (unchanged) ----
    const float* fT0r = g_freT + n0 * 1025;
    const float* fT0i = g_fimT + n0 * 1025;
    const float* fT1r = fT0r + 1025;
    const float* fT1i = fT0i + 1025;
    for (int k = tid; k <= 1024; k += 256) {
        int km = (2048 - k) & 2047;
        int pk = __brev(k) >> 21;
        int pm = __brev(km) >> 21;
        float2 z = cbuf[pk];
        float2 y = cbuf[pm];
        float x1r = 0.5f * (z.x + y.x), x1i = 0.5f * (z.y - y.y);
        float x2r = 0.5f * (z.y + y.y), x2i = 0.5f * (y.x - z.x);
        float h1r = fT0r[k], h1i = fT0i[k];
        float h2r = fT1r[k], h2i = fT1i[k];
        float y1r = x1r * h1r - x1i * h1i, y1i = x1r * h1i + x1i * h1r;
        float y2r = x2r * h2r - x2i * h2i, y2i = x2r * h2i + x2i * h2r;
        if (k == 0 || k == 1024) { y1i = 0.f; y2i = 0.f; }
        cbuf[pk] = make_float2(y1r - y2i, y1i + y2r);
        if (k > 0 && k < 1024) cbuf[pm] = make_float2(y1r + y2i, y2r - y1i);
    }

    // ---- Inverse DIT: merged pairs (0,1)(2,3)(4,5)(6,7)(8,9), single 10 ----
    #pragma unroll
    for (int s = 0; s <= 8; s += 2) {
        int h = 1 << s, H = h << 1;
        __syncthreads();
        for (int g = tid; g < 512; g += 256) {
            int j = g & (h - 1);
            int blk = g >> s;
            int i = blk * (H << 1) + j;
            float2 e0 = cbuf[i], e1 = cbuf[i + h], e2 = cbuf[i + H], e3 = cbuf[i + H + h];
            float2 w  = tw[j << (10 - s)];
            float2 w0 = tw[j << (9 - s)];
            float2 w1 = tw[(j + h) << (9 - s)];
            // stage s (conj twiddle)
            float2 t  = cmulc(e1, w);
            float2 t2 = cmulc(e3, w);
            float2 f0 = cadd(e0, t),  f1 = csub(e0, t);
            float2 f2 = cadd(e2, t2), f3 = csub(e2, t2);
            // stage s+1
            float2 u0 = cmulc(f2, w0);
            float2 u1 = cmulc(f3, w1);
            cbuf[i]         = cadd(f0, u0);
            cbuf[i + H]     = csub(f0, u0);
            cbuf[i + h]     = cadd(f1, u1);
            cbuf[i + H + h] = csub(f1, u1);
        }
    }
    // single stage 10
    __syncthreads();
    for (int j = tid; j < 1024; j += 256) {
        float2 w = tw[j];
        float2 bb = cbuf[j + 1024];
        float2 t = cmulc(bb, w);
        float2 a = cbuf[j];
        cbuf[j]        = cadd(a, t);
        cbuf[j + 1024] = csub(a, t);
    }
    __syncthreads();

    float* dst = xfreq + (size_t)b * T_ * N_ + n0;
    const float scl = 1.0f / 2048.0f;
    for (int t = tid; t < 2048; t += 256) {
        float2 v; v.x = cbuf[t].x * scl; v.y = cbuf[t].y * scl;
        *(float2*)(dst + (size_t)t * N_) = v;
    }
}

// ---------------------------------------------------------------------------
// Kernel 3 v12: bf16 mma layer2; preb1 in smem; s-prefetch; hoisted epilogue.
// ---------------------------------------------------------------------------
#define FTH 256
#define HS_S 264
#define W2_S 72
#define NTILES (B_ * T_ * N_ / FTH)   // 8192
#define PGRID 296
// floats: 16804 + preb 4096 = 20900
#define SMEM_BYTES (20900 * 4)

__global__ void __launch_bounds__(FTH, 2) fused_kernel(
    const float* __restrict__ seed, const float* __restrict__ mask,
    const float* __restrict__ xin, const float* __restrict__ xfreq,
    const float* __restrict__ gw1, const float* __restrict__ gw2,
    const float* __restrict__ gb2, const float* __restrict__ gw3,
    const float* __restrict__ gb3,
    const float* __restrict__ gcw1, const float* __restrict__ gcb1,
    const float* __restrict__ gcw2, const float* __restrict__ gcb2,
    float* __restrict__ out_gcn, float* __restrict__ out_imp,
    float* __restrict__ out_comp, float* __restrict__ out_gate)
{
    extern __shared__ float sm[];
    float* hs    = sm;                    // [32][264] bf16x2 (u32)
    float* sW2   = hs    + 32 * HS_S;     // [32][72] bf16x2
    float* sA    = sW2   + 32 * W2_S;     // [64][66]
    float* sW1fA = sA    + 64 * 66;       // [32]{f0pair,f1pair}
    float* sW1fB = sW1fA + 128;           // [32]{f2pair,f3pair}
    float* sGcI  = sW1fB + 128;           // [16]{w pair, b pair}
    float* sGcV  = sGcI  + 64;            // [32]
    float* sW34  = sGcV  + 32;            // [32]{we pair, wo pair}
    float* sB2   = sW34  + 128;           // [64]
    float* sPm   = sB2   + 64;            // [4][64]
    float* sXg   = sPm   + FTH;
    float* sXf   = sXg   + FTH;
    float* sMm   = sXf   + FTH;
    float* sXi   = sMm   + FTH;
    float* sCst  = sXi   + FTH;           // [4]
    float* sPreb = sCst  + 4;             // [32][64] float2 = 4096

    int tid = threadIdx.x;

    // ---- stage weights once ----
    for (int i = tid; i < 2048; i += FTH) {
        int kp = i >> 6, j = i & 63;
        ((u32*)sW2)[kp * W2_S + j] = bfpack(gw2[(2 * kp) * 64 + j], gw2[(2 * kp + 1) * 64 + j]);
    }
    for (int i = tid; i < 4096; i += FTH) sA[(i >> 6) * 66 + (i & 63)] = g_adj[i];
    for (int i = tid; i < 2048; i += FTH) ((float2*)sPreb)[i] = g_preb1p[i];
    if (tid < 64) {
        int j = tid;
        float wf0 = gw1[0 * 64 + j] - gw1[4 * 64 + j] - gw1[5 * 64 + j];
        float wf1 = gw1[1 * 64 + j];
        float wf2 = gw1[2 * 64 + j] + gw1[4 * 64 + j];
        float wf3 = gw1[3 * 64 + j] + gw1[5 * 64 + j];
        int p = j >> 1, o = j & 1;
        sW1fA[p * 4 + o]     = wf0;
        sW1fA[p * 4 + 2 + o] = wf1;
        sW1fB[p * 4 + o]     = wf2;
        sW1fB[p * 4 + 2 + o] = wf3;
        sB2[j] = gb2[j];
    }
    if (tid < 16) {
        sGcI[tid * 4 + 0] = gcw1[2 * tid];
        sGcI[tid * 4 + 1] = gcw1[2 * tid + 1];
        sGcI[tid * 4 + 2] = gcb1[2 * tid];
        sGcI[tid * 4 + 3] = gcb1[2 * tid + 1];
    }
    if (tid < 32) {
        sGcV[tid] = gcw2[tid];
        sW34[tid * 4 + 0] = gw3[4 * tid];
        sW34[tid * 4 + 1] = gw3[4 * tid + 2];
        sW34[tid * 4 + 2] = gw3[4 * tid + 1];
        sW34[tid * 4 + 3] = gw3[4 * tid + 3];
    }
    if (tid == 0) { sCst[0] = gcb2[0]; sCst[1] = gb3[0]; sCst[2] = gb3[1]; }
    __syncthreads();

    int n    = tid & 63;
    int r    = tid >> 6;      // 0..3
    int lane = tid & 31;
    int warp = tid >> 5;      // 0..7
    int m0   = warp * 32;
    int qr   = lane >> 2;     // quad row 0..7
    int qc   = lane & 3;      // quad col 0..3
    int prId = 8 + (tid >> 6);

    u32* hsu = (u32*)hs;
    const u64* prebp = (const u64*)sPreb;
    const ulonglong2* WA = (const ulonglong2*)sW1fA;
    const ulonglong2* WB = (const ulonglong2*)sW1fB;
    const ulonglong2* gcWB = (const ulonglong2*)sGcI;
    const u64* gcV = (const u64*)sGcV;
    const ulonglong2* w34 = (const ulonglong2*)sW34;

    // prefetch first tile's seed value (phi consumes it immediately)
    float s_cur = seed[blockIdx.x * FTH + tid];

    for (int tile = blockIdx.x; tile < NTILES; tile += PGRID) {
        BARP(prId);

        int gidx = tile * FTH + tid;
        float s  = s_cur;
        float mm = mask[gidx];
        float xf = xfreq[gidx];
        float xi = xin[gidx];

        // ---- phi(s), packed pairs ----
        u64 sp = pk2(s, s);
        u64 accp = pk2(0.f, 0.f);
        #pragma unroll
        for (int hq = 0; hq < 16; ++hq) {
            ulonglong2 wb = gcWB[hq];
            u64 pre = ffma2(sp, wb.x, wb.y);
            accp = ffma2(gelu2(pre), gcV[hq], accp);
        }
        float p0, p1; upk2(accp, p0, p1);
        sPm[r * 64 + n] = p0 + p1;
        BARP(prId);

        // ---- x_gcn (packed matvec, 2 accumulators for ILP) ----
        u64 xgpA = pk2(0.f, 0.f), xgpB = pk2(0.f, 0.f);
        const u64* arow = (const u64*)(sA + n * 66);
        const u64* prow = (const u64*)(sPm + r * 64);
        #pragma unroll 8
        for (int m2 = 0; m2 < 32; m2 += 2) {
            xgpA = ffma2(arow[m2], prow[m2], xgpA);
            xgpB = ffma2(arow[m2 + 1], prow[m2 + 1], xgpB);
        }
        u64 xgp = ffma2(xgpA, pk2(1.f, 1.f), xgpB);
        float xg0, xg1; upk2(xgp, xg0, xg1);
        float xg = xg0 + xg1 + sCst[0];

        sXg[tid] = xg; sXf[tid] = xf; sMm[tid] = mm; sXi[tid] = xi;
        out_gcn[gidx] = xg;

        // ---- layer1: folded 4 features, FFMA2 -> hs bf16x2 k-pairs ----
        u64 u0 = pk2(s, s), u1 = pk2(mm, mm), u2 = pk2(xg, xg), u3 = pk2(xf, xf);
        #pragma unroll
        for (int p = 0; p < 32; ++p) {
            u64 a = prebp[p * 64 + n];
            ulonglong2 wa = WA[p];
            ulonglong2 wb = WB[p];
            a = ffma2(u0, wa.x, a);
            a = ffma2(u1, wa.y, a);
            a = ffma2(u2, wb.x, a);
            a = ffma2(u3, wb.y, a);
            u64 g = gelu2(a);
            float v0, v1; upk2(g, v0, v1);
            hsu[p * HS_S + tid] = bfpack(v0, v1);
        }
        __syncwarp();

        // ---- prefetch next tile's seed (hidden under phase B) ----
        {
            int ntile = tile + PGRID;
            if (ntile < NTILES) s_cur = seed[ntile * FTH + tid];
        }

        // ---- Phase B: layer2 via bf16 m16n8k16 mma ----
        float acc[2][8][4];
        #pragma unroll
        for (int n8 = 0; n8 < 8; ++n8) {
            int j0 = n8 * 8 + qc * 2;
            float2 bb = *(const float2*)(sB2 + j0);
            #pragma unroll
            for (int mt = 0; mt < 2; ++mt) {
                acc[mt][n8][0] = bb.x; acc[mt][n8][1] = bb.y;
                acc[mt][n8][2] = bb.x; acc[mt][n8][3] = bb.y;
            }
        }

        const u32* w2u = (const u32*)sW2;
        int ar = m0 + qr;
        #pragma unroll
        for (int kt = 0; kt < 4; ++kt) {
            int kp0 = kt * 8 + qc;
            int kp4 = kp0 + 4;
            const u32* h0 = hsu + kp0 * HS_S;
            const u32* h4 = hsu + kp4 * HS_S;
            u32 a00 = h0[ar],      a01 = h0[ar + 8],  a02 = h4[ar],      a03 = h4[ar + 8];
            u32 a10 = h0[ar + 16], a11 = h0[ar + 24], a12 = h4[ar + 16], a13 = h4[ar + 24];
            const u32* b0p = w2u + kp0 * W2_S + qr;
            const u32* b1p = w2u + kp4 * W2_S + qr;
            #pragma unroll
            for (int n8 = 0; n8 < 8; ++n8) {
                u32 b0 = b0p[n8 * 8];
                u32 b1 = b1p[n8 * 8];
                mma_bf16(acc[0][n8], a00, a01, a02, a03, b0, b1);
                mma_bf16(acc[1][n8], a10, a11, a12, a13, b0, b1);
            }
        }

        // ---- epilogue: n8-outer, w34 loaded once and reused x4 ----
        u64 lg[2][2][2];
        #pragma unroll
        for (int mt = 0; mt < 2; ++mt)
            #pragma unroll
            for (int half = 0; half < 2; ++half) {
                lg[mt][half][0] = pk2(0.f, 0.f);
                lg[mt][half][1] = pk2(0.f, 0.f);
            }
        #pragma unroll
        for (int n8 = 0; n8 < 8; ++n8) {
            ulonglong2 w = w34[n8 * 4 + qc];
            #pragma unroll
            for (int mt = 0; mt < 2; ++mt)
                #pragma unroll
                for (int half = 0; half < 2; ++half) {
                    u64 a = pk2(acc[mt][n8][2 * half], acc[mt][n8][2 * half + 1]);
                    u64 g = gelu2(a);
                    lg[mt][half][0] = ffma2(g, w.x, lg[mt][half][0]);
                    lg[mt][half][1] = ffma2(g, w.y, lg[mt][half][1]);
                }
        }

        #pragma unroll
        for (int mt = 0; mt < 2; ++mt) {
            #pragma unroll
            for (int half = 0; half < 2; ++half) {
                float l0a, l0b, l1a, l1b;
                upk2(lg[mt][half][0], l0a, l0b);
                upk2(lg[mt][half][1], l1a, l1b);
                float lg0 = l0a + l0b, lg1 = l1a + l1b;
                lg0 += __shfl_xor_sync(0xffffffffu, lg0, 1);
                lg0 += __shfl_xor_sync(0xffffffffu, lg0, 2);
                lg1 += __shfl_xor_sync(0xffffffffu, lg1, 1);
                lg1 += __shfl_xor_sync(0xffffffffu, lg1, 2);

                if (qc == half + 2 * mt) {
                    int row = m0 + qr + 8 * half + 16 * mt;
                    int og  = tile * FTH + row;
                    lg0 += sCst[1]; lg1 += sCst[2];
                    float mxv = fmaxf(lg0, lg1);
                    float e0 = __expf(lg0 - mxv), e1 = __expf(lg1 - mxv);
                    float inv = __fdividef(1.0f, e0 + e1);
                    float g0 = e0 * inv, g1 = e1 * inv;
                    float xgr = sXg[row], xfr = sXf[row], mmr = sMm[row], xir = sXi[row];
                    float imputed  = fmaf(g0, xgr, g1 * xfr);
                    float complete = (mmr != 0.f) ? imputed : xir;
                    out_imp[og]  = imputed;
                    out_comp[og] = complete;
                    float2 gv; gv.x = g0; gv.y = g1;
                    *(float2*)(out_gate + (size_t)og * 2) = gv;
                }
            }
        }
        __syncwarp();
    }
}

// ---------------------------------------------------------------------------
extern "C" void kernel_launch(void* const* d_in, const int* in_sizes, int n_in,
                              void* d_out, int out_size)
{
    const float* x     = (const float*)d_in[0];
    const float* mask  = (const float*)d_in[1];
    const int*   rid   = (const int*)  d_in[2];
    const float* emb   = (const float*)d_in[3];
    const float* gcw1  = (const float*)d_in[4];
    const float* gcb1  = (const float*)d_in[5];
    const float* gcw2  = (const float*)d_in[6];
    const float* gcb2  = (const float*)d_in[7];
    const float* fre   = (const float*)d_in[8];
    const float* fim   = (const float*)d_in[9];
    const float* rtab  = (const float*)d_in[10];
    const float* gw1   = (const float*)d_in[11];
    const float* gb1   = (const float*)d_in[12];
    const float* gw2   = (const float*)d_in[13];
    const float* gb2   = (const float*)d_in[14];
    const float* gw3   = (const float*)d_in[15];
    const float* gb3   = (const float*)d_in[16];
    float* out = (float*)d_out;

    cudaFuncSetAttribute(fused_kernel, cudaFuncAttributeMaxDynamicSharedMemorySize, SMEM_BYTES);

    prep_kernel<<<321, 256>>>(x, mask, emb, rid, rtab, gw1, gb1, fre, fim, out + ADJ_OFF);
    fill_out_kernel<<<256, 256>>>(x, mask, out + SEED_OFF);
    fft_kernel<<<B_ * N_ / 2, 256>>>(out + FREQ_OFF);
    fused_kernel<<<PGRID, FTH, SMEM_BYTES>>>(
        out + SEED_OFF, mask, x, out + FREQ_OFF,
        gw1, gw2, gb2, gw3, gb3,
        gcw1, gcb1, gcw2, gcb2,
        out + GCN_OFF, out + IMP_OFF, out + COMP_OFF, out + GATE_OFF);
}

// round 16
// speedup vs baseline: 1.3225x; 1.0065x over previous
#include <cuda_runtime.h>
#include <cuda_bf16.h>
#include <math.h>

#define B_ 16
#define T_ 2048
#define N_ 64

// Output layout (flattened tuple in order)
#define SEED_OFF 0
#define GCN_OFF  2097152
#define FREQ_OFF 4194304
#define IMP_OFF  6291456
#define COMP_OFF 8388608
#define GATE_OFF 10485760
#define ADJ_OFF  14680064

typedef unsigned long long u64;
typedef unsigned int u32;

// Scratch (static device arrays: allowed)
__device__ float  g_adj[N_ * N_];
__device__ float2 g_preb1p[32 * N_];
__device__ float  g_first[65536], g_last[65536];
__device__ unsigned char g_has[65536];
__device__ float  g_seedT[B_ * N_ * T_];        // [b][n][t]
__device__ float  g_freT[N_ * 1025];            // [n][k]
__device__ float  g_fimT[N_ * 1025];
__device__ int    g_tileCtr;                    // dynamic task counter

// ---- packed f32x2 helpers ---------------------------------------------------
__device__ __forceinline__ u64 pk2(float lo, float hi) {
    u64 r; asm("mov.b64 %0, {%1, %2};" : "=l"(r) : "f"(lo), "f"(hi)); return r;
}
__device__ __forceinline__ void upk2(u64 v, float& lo, float& hi) {
    asm("mov.b64 {%0, %1}, %2;" : "=f"(lo), "=f"(hi) : "l"(v));
}
__device__ __forceinline__ u64 ffma2(u64 a, u64 b, u64 c) {
    u64 d; asm("fma.rn.f32x2 %0, %1, %2, %3;" : "=l"(d) : "l"(a), "l"(b), "l"(c)); return d;
}
__device__ __forceinline__ u64 mul2(u64 a, u64 b) {
    u64 d; asm("mul.rn.f32x2 %0, %1, %2;" : "=l"(d) : "l"(a), "l"(b)); return d;
}

__device__ __forceinline__ float tanh_ap(float x) {
    float t; asm("tanh.approx.f32 %0, %1;" : "=f"(t) : "f"(x)); return t;
}

// packed pairwise gelu
__device__ __forceinline__ u64 gelu2(u64 x) {
    const u64 C1 = pk2(0.035677408136f, 0.035677408136f);
    const u64 C0 = pk2(0.7978845608028654f, 0.7978845608028654f);
    const u64 H  = pk2(0.5f, 0.5f);
    u64 x2 = mul2(x, x);
    u64 inner = ffma2(x2, C1, C0);
    u64 b = mul2(x, inner);
    float b0, b1; upk2(b, b0, b1);
    u64 t = pk2(tanh_ap(b0), tanh_ap(b1));
    u64 hx = mul2(x, H);
    return ffma2(hx, t, hx);
}

// pack two f32 into bf16x2 (lo = first arg)
__device__ __forceinline__ u32 bfpack(float lo, float hi) {
    u32 d; asm("cvt.rn.bf16x2.f32 %0, %1, %2;" : "=r"(d) : "f"(hi), "f"(lo)); return d;
}

__device__ __forceinline__ u32 to_tf32(float v) {
    u32 r; asm("cvt.rna.tf32.f32 %0, %1;" : "=r"(r) : "f"(v)); return r;
}

__device__ __forceinline__ void mma_bf16(float* d,
    u32 a0, u32 a1, u32 a2, u32 a3, u32 b0, u32 b1)
{
    asm("mma.sync.aligned.m16n8k16.row.col.f32.bf16.bf16.f32 "
        "{%0,%1,%2,%3}, {%4,%5,%6,%7}, {%8,%9}, {%0,%1,%2,%3};"
        : "+f"(d[0]), "+f"(d[1]), "+f"(d[2]), "+f"(d[3])
        : "r"(a0), "r"(a1), "r"(a2), "r"(a3), "r"(b0), "r"(b1));
}

__device__ __forceinline__ void mma_tf32(float* d,
    u32 a0, u32 a1, u32 a2, u32 a3, u32 b0, u32 b1)
{
    asm("mma.sync.aligned.m16n8k8.row.col.f32.tf32.tf32.f32 "
        "{%0,%1,%2,%3}, {%4,%5,%6,%7}, {%8,%9}, {%0,%1,%2,%3};"
        : "+f"(d[0]), "+f"(d[1]), "+f"(d[2]), "+f"(d[3])
        : "r"(a0), "r"(a1), "r"(a2), "r"(a3), "r"(b0), "r"(b1));
}

#define BARP(id) asm volatile("bar.sync %0, %1;" :: "r"(id), "r"(64) : "memory")

// complex helpers
__device__ __forceinline__ float2 cadd(float2 a, float2 b) { return make_float2(a.x + b.x, a.y + b.y); }
__device__ __forceinline__ float2 csub(float2 a, float2 b) { return make_float2(a.x - b.x, a.y - b.y); }
__device__ __forceinline__ float2 cmulf(float2 d, float2 w) {
    return make_float2(d.x * w.x - d.y * w.y, d.x * w.y + d.y * w.x);
}
__device__ __forceinline__ float2 cmulc(float2 b, float2 w) {
    return make_float2(b.x * w.x + b.y * w.y, b.y * w.x - b.x * w.y);
}

// ---------------------------------------------------------------------------
// Kernel 0: prep (fill_sum / filter transpose / adjacency+preb1 / ctr reset)
// ---------------------------------------------------------------------------
#define PGRID 296

__global__ void __launch_bounds__(256) prep_kernel(
    const float* __restrict__ x, const float* __restrict__ mask,
    const float* __restrict__ emb, const int* __restrict__ rate_id,
    const float* __restrict__ rate_table, const float* __restrict__ gw1,
    const float* __restrict__ gb1,
    const float* __restrict__ fre, const float* __restrict__ fim,
    float* __restrict__ out_adj)
{
    int blk = blockIdx.x;
    int tid = threadIdx.x;

    if (blk < 256) {
        int g = blk * 256 + tid;
        int n = g & 63;
        int c = (g >> 6) & 63;
        int b = g >> 12;
        int base = ((b * T_) + c * 32) * N_ + n;
        float first = 0.f, last = 0.f; bool has = false;
        #pragma unroll
        for (int t = 0; t < 32; ++t) {
            int idx = base + t * N_;
            float v = x[idx];
            bool obs = (mask[idx] == 0.f);
            if (obs) { if (!has) first = v; last = v; has = true; }
        }
        int s = ((b << 6) + n) * 64 + c;
        g_first[s] = first; g_last[s] = last; g_has[s] = (unsigned char)has;
        return;
    }

    if (blk < 320) {
        int n = blk - 256;
        for (int k = tid; k < 1025; k += 256) {
            g_freT[n * 1025 + k] = fre[(size_t)k * N_ + n];
            g_fimT[n * 1025 + k] = fim[(size_t)k * N_ + n];
        }
        return;
    }

    // reset dynamic scheduler counter (every launch)
    if (tid == 255) g_tileCtr = 4 * PGRID;

    // adjacency + rate-embed pre-bias (threads 0-63)
    __shared__ float sE[64 * 32];
    for (int i = tid; i < 64 * 32; i += 256) sE[i] = emb[i];
    __syncthreads();
    if (tid >= 64) return;

    float sc[64];
    float mx = -1e30f;
    #pragma unroll
    for (int m = 0; m < 64; ++m) {
        float d = 0.f;
        #pragma unroll
        for (int h = 0; h < 32; ++h) d = fmaf(sE[tid * 32 + h], sE[m * 32 + h], d);
        d = fmaxf(d, 0.f);
        sc[m] = d; mx = fmaxf(mx, d);
    }
    float sum = 0.f;
    #pragma unroll
    for (int m = 0; m < 64; ++m) { float e = __expf(sc[m] - mx); sc[m] = e; sum += e; }
    float inv = 1.0f / sum;
    #pragma unroll
    for (int m = 0; m < 64; ++m) {
        float a = sc[m] * inv;
        g_adj[tid * 64 + m] = a;
        out_adj[tid * 64 + m] = a;
    }
    int rid = rate_id[tid];
    for (int j2 = 0; j2 < 32; ++j2) {
        float v0 = gb1[2 * j2], v1 = gb1[2 * j2 + 1];
        #pragma unroll
        for (int e = 0; e < 16; ++e) {
            float rt = rate_table[rid * 16 + e];
            v0 = fmaf(rt, gw1[(6 + e) * 64 + 2 * j2], v0);
            v1 = fmaf(rt, gw1[(6 + e) * 64 + 2 * j2 + 1], v1);
        }
        g_preb1p[j2 * 64 + tid] = make_float2(v0, v1);
    }
}

// ---------------------------------------------------------------------------
// Kernel 1: fill_out v2 — in-block scan + fill phase.
// ---------------------------------------------------------------------------
__global__ void __launch_bounds__(256) fill_out_kernel(
    const float* __restrict__ x, const float* __restrict__ mask,
    float* __restrict__ seed)
{
    __shared__ float sPr[256], sSu[256];
    __shared__ unsigned char sPrh[256], sSuh[256];

    int blk = blockIdx.x;
    int b = blk >> 4;
    int c0 = (blk & 15) * 4;
    int tid = threadIdx.x;

    if (tid < 64) {
        int bn = (b << 6) + tid;
        const float* fp = g_first + bn * 64;
        const float* lp = g_last + bn * 64;
        const unsigned char* hp = g_has + bn * 64;
        float pv = 0.f; bool ph = false;
        #pragma unroll 8
        for (int c = 0; c < 64; ++c) {
            unsigned d = (unsigned)(c - c0);
            if (d < 4u) { sPr[d * 64 + tid] = pv; sPrh[d * 64 + tid] = (unsigned char)ph; }
            if (hp[c]) { pv = lp[c]; ph = true; }
        }
        float sv = 0.f; bool sh = false;
        #pragma unroll 8
        for (int c = 63; c >= 0; --c) {
            unsigned d = (unsigned)(c - c0);
            if (d < 4u) { sSu[d * 64 + tid] = sv; sSuh[d * 64 + tid] = (unsigned char)sh; }
            if (hp[c]) { sv = fp[c]; sh = true; }
        }
    }
    __syncthreads();

    int n = tid & 63;
    int cl = tid >> 6;
    int c = c0 + cl;
    int base = ((b * T_) + c * 32) * N_ + n;
    float* tdst = g_seedT + ((size_t)(b * 64 + n)) * T_ + c * 32;

    float fv = sPr[cl * 64 + n]; bool fh = (bool)sPrh[cl * 64 + n];
    float vals[32];
    unsigned obsm = 0u, fam = 0u;
    #pragma unroll
    for (int t = 0; t < 32; ++t) {
        int idx = base + t * N_;
        float v = x[idx];
        bool obs = (mask[idx] == 0.f);
        if (obs) { fv = v; fh = true; obsm |= (1u << t); }
        vals[t] = fv;
        if (fh) fam |= (1u << t);
    }
    float bv = sSu[cl * 64 + n]; bool bh = (bool)sSuh[cl * 64 + n];
    #pragma unroll
    for (int t = 31; t >= 0; --t) {
        bool obs = (obsm >> t) & 1u;
        bool fa  = (fam  >> t) & 1u;
        float v = vals[t];
        if (obs) { bv = v; bh = true; }
        float out;
        if (obs)            out = v;
        else if (fa && bh)  out = 0.5f * (v + bv);
        else if (fa)        out = v;
        else if (bh)        out = bv;
        else                out = 0.f;
        seed[base + t * N_] = out;
        tdst[t] = out;
    }
}

// ---------------------------------------------------------------------------
// Kernel 2: FFT filter with merged radix-2 stage pairs (bit-identical).
// ---------------------------------------------------------------------------
__global__ void __launch_bounds__(256) fft_kernel(
    float* __restrict__ xfreq)
{
    __shared__ float2 cbuf[2048];
    __shared__ float2 tw[1024];
    int tid = threadIdx.x;
    int b = blockIdx.x >> 5;
    int p = blockIdx.x & 31;
    int n0 = p * 2;
    const float* src0 = g_seedT + ((size_t)(b * 64 + n0)) * T_;
    const float* src1 = src0 + T_;

    for (int j = tid; j < 1024; j += 256) {
        float s, c;
        sincosf(-6.28318530717958647692f * (float)j * (1.0f / 2048.0f), &s, &c);
        tw[j] = make_float2(c, s);
    }
    for (int t = tid; t < 2048; t += 256) {
        cbuf[t] = make_float2(src0[t], src1[t]);
    }

    #pragma unroll
    for (int s = 10; s >= 2; s -= 2) {
        int h = 1 << s, h2 = h >> 1;
        __syncthreads();
        for (int g = tid; g < 512; g += 256) {
            int j = g & (h2 - 1);
            int blk = g >> (s - 1);
            int i = blk * (h << 1) + j;
            float2 a0 = cbuf[i], a1 = cbuf[i + h2], a2 = cbuf[i + h], a3 = cbuf[i + h + h2];
            float2 w0 = tw[j << (10 - s)];
            float2 w1 = tw[(j + h2) << (10 - s)];
            float2 v  = tw[j << (11 - s)];
            float2 s0 = cadd(a0, a2), p2 = cmulf(csub(a0, a2), w0);
            float2 s1 = cadd(a1, a3), p3 = cmulf(csub(a1, a3), w1);
            cbuf[i]          = cadd(s0, s1);
            cbuf[i + h2]     = cmulf(csub(s0, s1), v);
            cbuf[i + h]      = cadd(p2, p3);
            cbuf[i + h + h2] = cmulf(csub(p2, p3), v);
        }
    }
    __syncthreads();
    for (int bi = tid; bi < 1024; bi += 256) {
        int i1 = bi << 1;
        int i2 = i1 + 1;
        float2 a = cbuf[i1], bb = cbuf[i2];
        cbuf[i1] = cadd(a, bb);
        cbuf[i2] = csub(a, bb);
    }
    __syncthreads();

    const float* fT0r = g_freT + n0 * 1025;
    const float* fT0i = g_fimT + n0 * 1025;
    const float* fT1r = fT0r + 1025;
    const float* fT1i = fT0i + 1025;
    for (int k = tid; k <= 1024; k += 256) {
        int km = (2048 - k) & 2047;
        int pk = __brev(k) >> 21;
        int pm = __brev(km) >> 21;
        float2 z = cbuf[pk];
        float2 y = cbuf[pm];
        float x1r = 0.5f * (z.x + y.x), x1i = 0.5f * (z.y - y.y);
        float x2r = 0.5f * (z.y + y.y), x2i = 0.5f * (y.x - z.x);
        float h1r = fT0r[k], h1i = fT0i[k];
        float h2r = fT1r[k], h2i = fT1i[k];
        float y1r = x1r * h1r - x1i * h1i, y1i = x1r * h1i + x1i * h1r;
        float y2r = x2r * h2r - x2i * h2i, y2i = x2r * h2i + x2i * h2r;
        if (k == 0 || k == 1024) { y1i = 0.f; y2i = 0.f; }
        cbuf[pk] = make_float2(y1r - y2i, y1i + y2r);
        if (k > 0 && k < 1024) cbuf[pm] = make_float2(y1r + y2i, y2r - y1i);
    }

    #pragma unroll
    for (int s = 0; s <= 8; s += 2) {
        int h = 1 << s, H = h << 1;
        __syncthreads();
        for (int g = tid; g < 512; g += 256) {
            int j = g & (h - 1);
            int blk = g >> s;
            int i = blk * (H << 1) + j;
            float2 e0 = cbuf[i], e1 = cbuf[i + h], e2 = cbuf[i + H], e3 = cbuf[i + H + h];
            float2 w  = tw[j << (10 - s)];
            float2 w0 = tw[j << (9 - s)];
            float2 w1 = tw[(j + h) << (9 - s)];
            float2 t  = cmulc(e1, w);
            float2 t2 = cmulc(e3, w);
            float2 f0 = cadd(e0, t),  f1 = csub(e0, t);
            float2 f2 = cadd(e2, t2), f3 = csub(e2, t2);
            float2 u0 = cmulc(f2, w0);
            float2 u1 = cmulc(f3, w1);
            cbuf[i]         = cadd(f0, u0);
            cbuf[i + H]     = csub(f0, u0);
            cbuf[i + h]     = cadd(f1, u1);
            cbuf[i + H + h] = csub(f1, u1);
        }
    }
    __syncthreads();
    for (int j = tid; j < 1024; j += 256) {
        float2 w = tw[j];
        float2 bb = cbuf[j + 1024];
        float2 t = cmulc(bb, w);
        float2 a = cbuf[j];
        cbuf[j]        = cadd(a, t);
        cbuf[j + 1024] = csub(a, t);
    }
    __syncthreads();

    float* dst = xfreq + (size_t)b * T_ * N_ + n0;
    const float scl = 1.0f / 2048.0f;
    for (int t = tid; t < 2048; t += 256) {
        float2 v; v.x = cbuf[t].x * scl; v.y = cbuf[t].y * scl;
        *(float2*)(dst + (size_t)t * N_) = v;
    }
}

// ---------------------------------------------------------------------------
// Kernel 3 v13: layer1 tf32 mma + layer2 bf16 mma; per-pair dynamic tasks.
// ---------------------------------------------------------------------------
#define FTH 256
#define HS_S 264
#define W2_S 72
#define NT 32768                      // 64-element pair tasks
// floats: hs 8448 + w2p 2304 + adj 4224 + wft 288 + sF 1152 + gcI 64
//   + gcV 32 + w34 128 + b2 64 + pm 256 + xg/xf/mm/xi 1024 + cst 4
//   + preb 4096 + task 4 = 22088
#define SMEM_BYTES (22088 * 4)

__global__ void __launch_bounds__(FTH, 2) fused_kernel(
    const float* __restrict__ seed, const float* __restrict__ mask,
    const float* __restrict__ xin, const float* __restrict__ xfreq,
    const float* __restrict__ gw1, const float* __restrict__ gw2,
    const float* __restrict__ gb2, const float* __restrict__ gw3,
    const float* __restrict__ gb3,
    const float* __restrict__ gcw1, const float* __restrict__ gcb1,
    const float* __restrict__ gcw2, const float* __restrict__ gcb2,
    float* __restrict__ out_gcn, float* __restrict__ out_imp,
    float* __restrict__ out_comp, float* __restrict__ out_gate)
{
    extern __shared__ float sm[];
    float* hs    = sm;                    // [32][264] bf16x2 (u32)
    float* sW2   = hs    + 32 * HS_S;     // [32][72] bf16x2
    float* sA    = sW2   + 32 * W2_S;     // [64][66]
    float* sWft  = sA    + 64 * 66;       // [4][72] folded layer1 weights tf32
    float* sF    = sWft  + 4 * 72;        // [4 pair][4 feat][72] tf32
    float* sGcI  = sF    + 16 * 72;       // [16]{w pair, b pair}
    float* sGcV  = sGcI  + 64;            // [32]
    float* sW34  = sGcV  + 32;            // [32]{we pair, wo pair}
    float* sB2   = sW34  + 128;           // [64]
    float* sPm   = sB2   + 64;            // [4][64]
    float* sXg   = sPm   + FTH;
    float* sXf   = sXg   + FTH;
    float* sMm   = sXf   + FTH;
    float* sXi   = sMm   + FTH;
    float* sCst  = sXi   + FTH;           // [4]
    float* sPreb = sCst  + 4;             // [32][64] float2 = 4096
    int*   sTask = (int*)(sPreb + 4096);  // [4]

    int tid = threadIdx.x;

    // ---- stage weights once ----
    for (int i = tid; i < 2048; i += FTH) {
        int kp = i >> 6, j = i & 63;
        ((u32*)sW2)[kp * W2_S + j] = bfpack(gw2[(2 * kp) * 64 + j], gw2[(2 * kp + 1) * 64 + j]);
    }
    for (int i = tid; i < 4096; i += FTH) sA[(i >> 6) * 66 + (i & 63)] = g_adj[i];
    for (int i = tid; i < 2048; i += FTH) ((float2*)sPreb)[i] = g_preb1p[i];
    if (tid < 64) {
        int j = tid;
        u32* wftu = (u32*)sWft;
        wftu[0 * 72 + j] = to_tf32(gw1[0 * 64 + j] - gw1[4 * 64 + j] - gw1[5 * 64 + j]);
        wftu[1 * 72 + j] = to_tf32(gw1[1 * 64 + j]);
        wftu[2 * 72 + j] = to_tf32(gw1[2 * 64 + j] + gw1[4 * 64 + j]);
        wftu[3 * 72 + j] = to_tf32(gw1[3 * 64 + j] + gw1[5 * 64 + j]);
        sB2[j] = gb2[j];
    }
    if (tid < 16) {
        sGcI[tid * 4 + 0] = gcw1[2 * tid];
        sGcI[tid * 4 + 1] = gcw1[2 * tid + 1];
        sGcI[tid * 4 + 2] = gcb1[2 * tid];
        sGcI[tid * 4 + 3] = gcb1[2 * tid + 1];
    }
    if (tid < 32) {
        sGcV[tid] = gcw2[tid];
        sW34[tid * 4 + 0] = gw3[4 * tid];
        sW34[tid * 4 + 1] = gw3[4 * tid + 2];
        sW34[tid * 4 + 2] = gw3[4 * tid + 1];
        sW34[tid * 4 + 3] = gw3[4 * tid + 3];
    }
    if (tid == 0) { sCst[0] = gcb2[0]; sCst[1] = gb3[0]; sCst[2] = gb3[1]; }
    __syncthreads();

    int el   = tid & 63;      // element within pair task
    int pr   = tid >> 6;      // pair 0..3
    int lane = tid & 31;
    int warp = tid >> 5;      // 0..7
    int wi   = warp & 1;      // warp within pair
    int m0   = warp * 32;     // global hs column base
    int m0p  = wi * 32;       // row base within pair
    int qr   = lane >> 2;
    int qc   = lane & 3;
    int prId = 8 + pr;

    u32* hsu = (u32*)hs;
    const float2* prebF = (const float2*)sPreb;
    const ulonglong2* gcWB = (const ulonglong2*)sGcI;
    const u64* gcV = (const u64*)sGcV;
    const ulonglong2* w34 = (const ulonglong2*)sW34;
    const u32* wftu = (const u32*)sWft;
    u32* sFu = (u32*)sF;
    const u32* fbase = sFu + pr * 4 * 72;

    int task = blockIdx.x * 4 + pr;
    float s_cur = (task < NT) ? seed[task * 64 + el] : 0.f;

    while (task < NT) {
        BARP(prId);   // prev sPm reads done; sTask write visibility next iter

        // pair leader grabs next task (latency hidden under phi)
        if ((tid & 63) == 0) sTask[pr] = atomicAdd(&g_tileCtr, 1);

        int gidx = task * 64 + el;
        float s  = s_cur;
        float mm = mask[gidx];
        float xf = xfreq[gidx];
        float xi = xin[gidx];

        // ---- phi(s), packed pairs ----
        u64 sp = pk2(s, s);
        u64 accp = pk2(0.f, 0.f);
        #pragma unroll
        for (int hq = 0; hq < 16; ++hq) {
            ulonglong2 wb = gcWB[hq];
            u64 pre = ffma2(sp, wb.x, wb.y);
            accp = ffma2(gelu2(pre), gcV[hq], accp);
        }
        float p0, p1; upk2(accp, p0, p1);
        sPm[pr * 64 + el] = p0 + p1;
        BARP(prId);

        // next task + s prefetch (hidden under remaining phases)
        int ntask = sTask[pr];
        float s_n = (ntask < NT) ? seed[ntask * 64 + el] : 0.f;

        // ---- x_gcn (packed matvec) ----
        u64 xgpA = pk2(0.f, 0.f), xgpB = pk2(0.f, 0.f);
        const u64* arow = (const u64*)(sA + el * 66);
        const u64* prow = (const u64*)(sPm + pr * 64);
        #pragma unroll 8
        for (int m2 = 0; m2 < 32; m2 += 2) {
            xgpA = ffma2(arow[m2], prow[m2], xgpA);
            xgpB = ffma2(arow[m2 + 1], prow[m2 + 1], xgpB);
        }
        u64 xgp = ffma2(xgpA, pk2(1.f, 1.f), xgpB);
        float xg0, xg1; upk2(xgp, xg0, xg1);
        float xg = xg0 + xg1 + sCst[0];

        sXg[tid] = xg; sXf[tid] = xf; sMm[tid] = mm; sXi[tid] = xi;
        out_gcn[gidx] = xg;

        // stage features as tf32 for layer1 A
        sFu[(pr * 4 + 0) * 72 + el] = to_tf32(s);
        sFu[(pr * 4 + 1) * 72 + el] = to_tf32(mm);
        sFu[(pr * 4 + 2) * 72 + el] = to_tf32(xg);
        sFu[(pr * 4 + 3) * 72 + el] = to_tf32(xf);
        __syncwarp();

        // ---- layer1 via tf32 m16n8k8 mma (K=4 real), preb in acc ----
        {
            float accL[2][8][4];
            #pragma unroll
            for (int mt = 0; mt < 2; ++mt) {
                int rowA = m0p + 16 * mt + qr;
                #pragma unroll
                for (int n8 = 0; n8 < 8; ++n8) {
                    int pp = n8 * 4 + qc;
                    float2 pa = prebF[pp * 64 + rowA];
                    float2 pb = prebF[pp * 64 + rowA + 8];
                    accL[mt][n8][0] = pa.x; accL[mt][n8][1] = pa.y;
                    accL[mt][n8][2] = pb.x; accL[mt][n8][3] = pb.y;
                }
            }
            u32 bb[8];
            #pragma unroll
            for (int n8 = 0; n8 < 8; ++n8) bb[n8] = wftu[qc * 72 + n8 * 8 + qr];
            #pragma unroll
            for (int mt = 0; mt < 2; ++mt) {
                u32 a0 = fbase[qc * 72 + m0p + 16 * mt + qr];
                u32 a1 = fbase[qc * 72 + m0p + 16 * mt + qr + 8];
                #pragma unroll
                for (int n8 = 0; n8 < 8; ++n8)
                    mma_tf32(accL[mt][n8], a0, a1, 0u, 0u, bb[n8], 0u);
            }
            // gelu + store as bf16 pairs (conflict-free: bank = 8qc+qr+...)
            #pragma unroll
            for (int mt = 0; mt < 2; ++mt) {
                int colA = m0 + 16 * mt + qr;   // global hs column
                #pragma unroll
                for (int n8 = 0; n8 < 8; ++n8) {
                    int pp = n8 * 4 + qc;
                    u64 g01 = gelu2(pk2(accL[mt][n8][0], accL[mt][n8][1]));
                    u64 g23 = gelu2(pk2(accL[mt][n8][2], accL[mt][n8][3]));
                    float v0, v1, v2, v3;
                    upk2(g01, v0, v1); upk2(g23, v2, v3);
                    hsu[pp * HS_S + colA]     = bfpack(v0, v1);
                    hsu[pp * HS_S + colA + 8] = bfpack(v2, v3);
                }
            }
        }
        __syncwarp();

        // ---- Phase B: layer2 via bf16 m16n8k16 mma ----
        float acc[2][8][4];
        #pragma unroll
        for (int n8 = 0; n8 < 8; ++n8) {
            int j0 = n8 * 8 + qc * 2;
            float2 bb2 = *(const float2*)(sB2 + j0);
            #pragma unroll
            for (int mt = 0; mt < 2; ++mt) {
                acc[mt][n8][0] = bb2.x; acc[mt][n8][1] = bb2.y;
                acc[mt][n8][2] = bb2.x; acc[mt][n8][3] = bb2.y;
            }
        }

        const u32* w2u = (const u32*)sW2;
        int ar = m0 + qr;
        #pragma unroll
        for (int kt = 0; kt < 4; ++kt) {
            int kp0 = kt * 8 + qc;
            int kp4 = kp0 + 4;
            const u32* h0 = hsu + kp0 * HS_S;
            const u32* h4 = hsu + kp4 * HS_S;
            u32 a00 = h0[ar],      a01 = h0[ar + 8],  a02 = h4[ar],      a03 = h4[ar + 8];
            u32 a10 = h0[ar + 16], a11 = h0[ar + 24], a12 = h4[ar + 16], a13 = h4[ar + 24];
            const u32* b0p = w2u + kp0 * W2_S + qr;
            const u32* b1p = w2u + kp4 * W2_S + qr;
            #pragma unroll
            for (int n8 = 0; n8 < 8; ++n8) {
                u32 b0 = b0p[n8 * 8];
                u32 b1 = b1p[n8 * 8];
                mma_bf16(acc[0][n8], a00, a01, a02, a03, b0, b1);
                mma_bf16(acc[1][n8], a10, a11, a12, a13, b0, b1);
            }
        }

        // ---- epilogue ----
        u64 lg[2][2][2];
        #pragma unroll
        for (int mt = 0; mt < 2; ++mt)
            #pragma unroll
            for (int half = 0; half < 2; ++half) {
                lg[mt][half][0] = pk2(0.f, 0.f);
                lg[mt][half][1] = pk2(0.f, 0.f);
            }
        #pragma unroll
        for (int n8 = 0; n8 < 8; ++n8) {
            ulonglong2 w = w34[n8 * 4 + qc];
            #pragma unroll
            for (int mt = 0; mt < 2; ++mt)
                #pragma unroll
                for (int half = 0; half < 2; ++half) {
                    u64 a = pk2(acc[mt][n8][2 * half], acc[mt][n8][2 * half + 1]);
                    u64 g = gelu2(a);
                    lg[mt][half][0] = ffma2(g, w.x, lg[mt][half][0]);
                    lg[mt][half][1] = ffma2(g, w.y, lg[mt][half][1]);
                }
        }

        #pragma unroll
        for (int mt = 0; mt < 2; ++mt) {
            #pragma unroll
            for (int half = 0; half < 2; ++half) {
                float l0a, l0b, l1a, l1b;
                upk2(lg[mt][half][0], l0a, l0b);
                upk2(lg[mt][half][1], l1a, l1b);
                float lg0 = l0a + l0b, lg1 = l1a + l1b;
                lg0 += __shfl_xor_sync(0xffffffffu, lg0, 1);
                lg0 += __shfl_xor_sync(0xffffffffu, lg0, 2);
                lg1 += __shfl_xor_sync(0xffffffffu, lg1, 1);
                lg1 += __shfl_xor_sync(0xffffffffu, lg1, 2);

                if (qc == half + 2 * mt) {
                    int row = m0 + qr + 8 * half + 16 * mt;   // global tid-space row
                    int og  = task * 64 + (row & 63);
                    lg0 += sCst[1]; lg1 += sCst[2];
                    float mxv = fmaxf(lg0, lg1);
                    float e0 = __expf(lg0 - mxv), e1 = __expf(lg1 - mxv);
                    float inv = __fdividef(1.0f, e0 + e1);
                    float g0 = e0 * inv, g1 = e1 * inv;
                    float xgr = sXg[row], xfr = sXf[row], mmr = sMm[row], xir = sXi[row];
                    float imputed  = fmaf(g0, xgr, g1 * xfr);
                    float complete = (mmr != 0.f) ? imputed : xir;
                    out_imp[og]  = imputed;
                    out_comp[og] = complete;
                    float2 gv; gv.x = g0; gv.y = g1;
                    *(float2*)(out_gate + (size_t)og * 2) = gv;
                }
            }
        }
        __syncwarp();

        task = ntask;
        s_cur = s_n;
    }
}

// ---------------------------------------------------------------------------
extern "C" void kernel_launch(void* const* d_in, const int* in_sizes, int n_in,
                              void* d_out, int out_size)
{
    const float* x     = (const float*)d_in[0];
    const float* mask  = (const float*)d_in[1];
    const int*   rid   = (const int*)  d_in[2];
    const float* emb   = (const float*)d_in[3];
    const float* gcw1  = (const float*)d_in[4];
    const float* gcb1  = (const float*)d_in[5];
    const float* gcw2  = (const float*)d_in[6];
    const float* gcb2  = (const float*)d_in[7];
    const float* fre   = (const float*)d_in[8];
    const float* fim   = (const float*)d_in[9];
    const float* rtab  = (const float*)d_in[10];
    const float* gw1   = (const float*)d_in[11];
    const float* gb1   = (const float*)d_in[12];
    const float* gw2   = (const float*)d_in[13];
    const float* gb2   = (const float*)d_in[14];
    const float* gw3   = (const float*)d_in[15];
    const float* gb3   = (const float*)d_in[16];
    float* out = (float*)d_out;

    cudaFuncSetAttribute(fused_kernel, cudaFuncAttributeMaxDynamicSharedMemorySize, SMEM_BYTES);

    prep_kernel<<<321, 256>>>(x, mask, emb, rid, rtab, gw1, gb1, fre, fim, out + ADJ_OFF);
    fill_out_kernel<<<256, 256>>>(x, mask, out + SEED_OFF);
    fft_kernel<<<B_ * N_ / 2, 256>>>(out + FREQ_OFF);
    fused_kernel<<<PGRID, FTH, SMEM_BYTES>>>(
        out + SEED_OFF, mask, x, out + FREQ_OFF,
        gw1, gw2, gb2, gw3, gb3,
        gcw1, gcb1, gcw2, gcb2,
        out + GCN_OFF, out + IMP_OFF, out + COMP_OFF, out + GATE_OFF);
}

// round 17
// speedup vs baseline: 1.3292x; 1.0050x over previous
#include <cuda_runtime.h>
#include <cuda_bf16.h>
#include <math.h>

#define B_ 16
#define T_ 2048
#define N_ 64

// Output layout (flattened tuple in order)
#define SEED_OFF 0
#define GCN_OFF  2097152
#define FREQ_OFF 4194304
#define IMP_OFF  6291456
#define COMP_OFF 8388608
#define GATE_OFF 10485760
#define ADJ_OFF  14680064

typedef unsigned long long u64;
typedef unsigned int u32;

// Scratch (static device arrays: allowed)
__device__ float  g_adj[N_ * N_];
__device__ float2 g_preb1p[32 * N_];
__device__ float  g_first[65536], g_last[65536];
__device__ unsigned char g_has[65536];
__device__ float  g_seedT[B_ * N_ * T_];        // [b][n][t]
__device__ float  g_freT[N_ * 1025];            // [n][k]
__device__ float  g_fimT[N_ * 1025];
__device__ int    g_tileCtr;                    // dynamic task counter

// ---- packed f32x2 helpers ---------------------------------------------------
__device__ __forceinline__ u64 pk2(float lo, float hi) {
    u64 r; asm("mov.b64 %0, {%1, %2};" : "=l"(r) : "f"(lo), "f"(hi)); return r;
}
__device__ __forceinline__ void upk2(u64 v, float& lo, float& hi) {
    asm("mov.b64 {%0, %1}, %2;" : "=f"(lo), "=f"(hi) : "l"(v));
}
__device__ __forceinline__ u64 ffma2(u64 a, u64 b, u64 c) {
    u64 d; asm("fma.rn.f32x2 %0, %1, %2, %3;" : "=l"(d) : "l"(a), "l"(b), "l"(c)); return d;
}
__device__ __forceinline__ u64 mul2(u64 a, u64 b) {
    u64 d; asm("mul.rn.f32x2 %0, %1, %2;" : "=l"(d) : "l"(a), "l"(b)); return d;
}

__device__ __forceinline__ float tanh_ap(float x) {
    float t; asm("tanh.approx.f32 %0, %1;" : "=f"(t) : "f"(x)); return t;
}

// packed pairwise gelu
__device__ __forceinline__ u64 gelu2(u64 x) {
    const u64 C1 = pk2(0.035677408136f, 0.035677408136f);
    const u64 C0 = pk2(0.7978845608028654f, 0.7978845608028654f);
    const u64 H  = pk2(0.5f, 0.5f);
    u64 x2 = mul2(x, x);
    u64 inner = ffma2(x2, C1, C0);
    u64 b = mul2(x, inner);
    float b0, b1; upk2(b, b0, b1);
    u64 t = pk2(tanh_ap(b0), tanh_ap(b1));
    u64 hx = mul2(x, H);
    return ffma2(hx, t, hx);
}

// pack two f32 into bf16x2 (lo = first arg)
__device__ __forceinline__ u32 bfpack(float lo, float hi) {
    u32 d; asm("cvt.rn.bf16x2.f32 %0, %1, %2;" : "=r"(d) : "f"(hi), "f"(lo)); return d;
}

__device__ __forceinline__ void mma_bf16(float* d,
    u32 a0, u32 a1, u32 a2, u32 a3, u32 b0, u32 b1)
{
    asm("mma.sync.aligned.m16n8k16.row.col.f32.bf16.bf16.f32 "
        "{%0,%1,%2,%3}, {%4,%5,%6,%7}, {%8,%9}, {%0,%1,%2,%3};"
        : "+f"(d[0]), "+f"(d[1]), "+f"(d[2]), "+f"(d[3])
        : "r"(a0), "r"(a1), "r"(a2), "r"(a3), "r"(b0), "r"(b1));
}

#define BARP(id) asm volatile("bar.sync %0, %1;" :: "r"(id), "r"(64) : "memory")

// complex helpers
__device__ __forceinline__ float2 cadd(float2 a, float2 b) { return make_float2(a.x + b.x, a.y + b.y); }
__device__ __forceinline__ float2 csub(float2 a, float2 b) { return make_float2(a.x - b.x, a.y - b.y); }
__device__ __forceinline__ float2 cmulf(float2 d, float2 w) {
    return make_float2(d.x * w.x - d.y * w.y, d.x * w.y + d.y * w.x);
}
__device__ __forceinline__ float2 cmulc(float2 b, float2 w) {
    return make_float2(b.x * w.x + b.y * w.y, b.y * w.x - b.x * w.y);
}

// ---------------------------------------------------------------------------
// Kernel 0: prep (fill_sum / filter transpose / adjacency+preb1 / ctr reset)
// ---------------------------------------------------------------------------
#define PGRID 296

__global__ void __launch_bounds__(256) prep_kernel(
    const float* __restrict__ x, const float* __restrict__ mask,
    const float* __restrict__ emb, const int* __restrict__ rate_id,
    const float* __restrict__ rate_table, const float* __restrict__ gw1,
    const float* __restrict__ gb1,
    const float* __restrict__ fre, const float* __restrict__ fim,
    float* __restrict__ out_adj)
{
    int blk = blockIdx.x;
    int tid = threadIdx.x;

    if (blk < 256) {
        int g = blk * 256 + tid;
        int n = g & 63;
        int c = (g >> 6) & 63;
        int b = g >> 12;
        int base = ((b * T_) + c * 32) * N_ + n;
        float first = 0.f, last = 0.f; bool has = false;
        #pragma unroll
        for (int t = 0; t < 32; ++t) {
            int idx = base + t * N_;
            float v = x[idx];
            bool obs = (mask[idx] == 0.f);
            if (obs) { if (!has) first = v; last = v; has = true; }
        }
        int s = ((b << 6) + n) * 64 + c;
        g_first[s] = first; g_last[s] = last; g_has[s] = (unsigned char)has;
        return;
    }

    if (blk < 320) {
        int n = blk - 256;
        for (int k = tid; k < 1025; k += 256) {
            g_freT[n * 1025 + k] = fre[(size_t)k * N_ + n];
            g_fimT[n * 1025 + k] = fim[(size_t)k * N_ + n];
        }
        return;
    }

    // reset dynamic scheduler counter (every launch)
    if (tid == 255) g_tileCtr = 4 * PGRID;

    // adjacency + rate-embed pre-bias (threads 0-63)
    __shared__ float sE[64 * 32];
    for (int i = tid; i < 64 * 32; i += 256) sE[i] = emb[i];
    __syncthreads();
    if (tid >= 64) return;

    float sc[64];
    float mx = -1e30f;
    #pragma unroll
    for (int m = 0; m < 64; ++m) {
        float d = 0.f;
        #pragma unroll
        for (int h = 0; h < 32; ++h) d = fmaf(sE[tid * 32 + h], sE[m * 32 + h], d);
        d = fmaxf(d, 0.f);
        sc[m] = d; mx = fmaxf(mx, d);
    }
    float sum = 0.f;
    #pragma unroll
    for (int m = 0; m < 64; ++m) { float e = __expf(sc[m] - mx); sc[m] = e; sum += e; }
    float inv = 1.0f / sum;
    #pragma unroll
    for (int m = 0; m < 64; ++m) {
        float a = sc[m] * inv;
        g_adj[tid * 64 + m] = a;
        out_adj[tid * 64 + m] = a;
    }
    int rid = rate_id[tid];
    for (int j2 = 0; j2 < 32; ++j2) {
        float v0 = gb1[2 * j2], v1 = gb1[2 * j2 + 1];
        #pragma unroll
        for (int e = 0; e < 16; ++e) {
            float rt = rate_table[rid * 16 + e];
            v0 = fmaf(rt, gw1[(6 + e) * 64 + 2 * j2], v0);
            v1 = fmaf(rt, gw1[(6 + e) * 64 + 2 * j2 + 1], v1);
        }
        g_preb1p[j2 * 64 + tid] = make_float2(v0, v1);
    }
}

// ---------------------------------------------------------------------------
// Kernel 1: fill_out v2 — in-block scan + fill phase.
// ---------------------------------------------------------------------------
__global__ void __launch_bounds__(256) fill_out_kernel(
    const float* __restrict__ x, const float* __restrict__ mask,
    float* __restrict__ seed)
{
    __shared__ float sPr[256], sSu[256];
    __shared__ unsigned char sPrh[256], sSuh[256];

    int blk = blockIdx.x;
    int b = blk >> 4;
    int c0 = (blk & 15) * 4;
    int tid = threadIdx.x;

    if (tid < 64) {
        int bn = (b << 6) + tid;
        const float* fp = g_first + bn * 64;
        const float* lp = g_last + bn * 64;
        const unsigned char* hp = g_has + bn * 64;
        float pv = 0.f; bool ph = false;
        #pragma unroll 8
        for (int c = 0; c < 64; ++c) {
            unsigned d = (unsigned)(c - c0);
            if (d < 4u) { sPr[d * 64 + tid] = pv; sPrh[d * 64 + tid] = (unsigned char)ph; }
            if (hp[c]) { pv = lp[c]; ph = true; }
        }
        float sv = 0.f; bool sh = false;
        #pragma unroll 8
        for (int c = 63; c >= 0; --c) {
            unsigned d = (unsigned)(c - c0);
            if (d < 4u) { sSu[d * 64 + tid] = sv; sSuh[d * 64 + tid] = (unsigned char)sh; }
            if (hp[c]) { sv = fp[c]; sh = true; }
        }
    }
    __syncthreads();

    int n = tid & 63;
    int cl = tid >> 6;
    int c = c0 + cl;
    int base = ((b * T_) + c * 32) * N_ + n;
    float* tdst = g_seedT + ((size_t)(b * 64 + n)) * T_ + c * 32;

    float fv = sPr[cl * 64 + n]; bool fh = (bool)sPrh[cl * 64 + n];
    float vals[32];
    unsigned obsm = 0u, fam = 0u;
    #pragma unroll
    for (int t = 0; t < 32; ++t) {
        int idx = base + t * N_;
        float v = x[idx];
        bool obs = (mask[idx] == 0.f);
        if (obs) { fv = v; fh = true; obsm |= (1u << t); }
        vals[t] = fv;
        if (fh) fam |= (1u << t);
    }
    float bv = sSu[cl * 64 + n]; bool bh = (bool)sSuh[cl * 64 + n];
    #pragma unroll
    for (int t = 31; t >= 0; --t) {
        bool obs = (obsm >> t) & 1u;
        bool fa  = (fam  >> t) & 1u;
        float v = vals[t];
        if (obs) { bv = v; bh = true; }
        float out;
        if (obs)            out = v;
        else if (fa && bh)  out = 0.5f * (v + bv);
        else if (fa)        out = v;
        else if (bh)        out = bv;
        else                out = 0.f;
        seed[base + t * N_] = out;
        tdst[t] = out;
    }
}

// ---------------------------------------------------------------------------
// Kernel 2: FFT filter with merged radix-2 stage pairs (bit-identical).
// ---------------------------------------------------------------------------
__global__ void __launch_bounds__(256) fft_kernel(
    float* __restrict__ xfreq)
{
    __shared__ float2 cbuf[2048];
    __shared__ float2 tw[1024];
    int tid = threadIdx.x;
    int b = blockIdx.x >> 5;
    int p = blockIdx.x & 31;
    int n0 = p * 2;
    const float* src0 = g_seedT + ((size_t)(b * 64 + n0)) * T_;
    const float* src1 = src0 + T_;

    for (int j = tid; j < 1024; j += 256) {
        float s, c;
        sincosf(-6.28318530717958647692f * (float)j * (1.0f / 2048.0f), &s, &c);
        tw[j] = make_float2(c, s);
    }
    for (int t = tid; t < 2048; t += 256) {
        cbuf[t] = make_float2(src0[t], src1[t]);
    }

    #pragma unroll
    for (int s = 10; s >= 2; s -= 2) {
        int h = 1 << s, h2 = h >> 1;
        __syncthreads();
        for (int g = tid; g < 512; g += 256) {
            int j = g & (h2 - 1);
            int blk = g >> (s - 1);
            int i = blk * (h << 1) + j;
            float2 a0 = cbuf[i], a1 = cbuf[i + h2], a2 = cbuf[i + h], a3 = cbuf[i + h + h2];
            float2 w0 = tw[j << (10 - s)];
            float2 w1 = tw[(j + h2) << (10 - s)];
            float2 v  = tw[j << (11 - s)];
            float2 s0 = cadd(a0, a2), p2 = cmulf(csub(a0, a2), w0);
            float2 s1 = cadd(a1, a3), p3 = cmulf(csub(a1, a3), w1);
            cbuf[i]          = cadd(s0, s1);
            cbuf[i + h2]     = cmulf(csub(s0, s1), v);
            cbuf[i + h]      = cadd(p2, p3);
            cbuf[i + h + h2] = cmulf(csub(p2, p3), v);
        }
    }
    __syncthreads();
    for (int bi = tid; bi < 1024; bi += 256) {
        int i1 = bi << 1;
        int i2 = i1 + 1;
        float2 a = cbuf[i1], bb = cbuf[i2];
        cbuf[i1] = cadd(a, bb);
        cbuf[i2] = csub(a, bb);
    }
    __syncthreads();

    const float* fT0r = g_freT + n0 * 1025;
    const float* fT0i = g_fimT + n0 * 1025;
    const float* fT1r = fT0r + 1025;
    const float* fT1i = fT0i + 1025;
    for (int k = tid; k <= 1024; k += 256) {
        int km = (2048 - k) & 2047;
        int pk = __brev(k) >> 21;
        int pm = __brev(km) >> 21;
        float2 z = cbuf[pk];
        float2 y = cbuf[pm];
        float x1r = 0.5f * (z.x + y.x), x1i = 0.5f * (z.y - y.y);
        float x2r = 0.5f * (z.y + y.y), x2i = 0.5f * (y.x - z.x);
        float h1r = fT0r[k], h1i = fT0i[k];
        float h2r = fT1r[k], h2i = fT1i[k];
        float y1r = x1r * h1r - x1i * h1i, y1i = x1r * h1i + x1i * h1r;
        float y2r = x2r * h2r - x2i * h2i, y2i = x2r * h2i + x2i * h2r;
        if (k == 0 || k == 1024) { y1i = 0.f; y2i = 0.f; }
        cbuf[pk] = make_float2(y1r - y2i, y1i + y2r);
        if (k > 0 && k < 1024) cbuf[pm] = make_float2(y1r + y2i, y2r - y1i);
    }

    #pragma unroll
    for (int s = 0; s <= 8; s += 2) {
        int h = 1 << s, H = h << 1;
        __syncthreads();
        for (int g = tid; g < 512; g += 256) {
            int j = g & (h - 1);
            int blk = g >> s;
            int i = blk * (H << 1) + j;
            float2 e0 = cbuf[i], e1 = cbuf[i + h], e2 = cbuf[i + H], e3 = cbuf[i + H + h];
            float2 w  = tw[j << (10 - s)];
            float2 w0 = tw[j << (9 - s)];
            float2 w1 = tw[(j + h) << (9 - s)];
            float2 t  = cmulc(e1, w);
            float2 t2 = cmulc(e3, w);
            float2 f0 = cadd(e0, t),  f1 = csub(e0, t);
            float2 f2 = cadd(e2, t2), f3 = csub(e2, t2);
            float2 u0 = cmulc(f2, w0);
            float2 u1 = cmulc(f3, w1);
            cbuf[i]         = cadd(f0, u0);
            cbuf[i + H]     = csub(f0, u0);
            cbuf[i + h]     = cadd(f1, u1);
            cbuf[i + H + h] = csub(f1, u1);
        }
    }
    __syncthreads();
    for (int j = tid; j < 1024; j += 256) {
        float2 w = tw[j];
        float2 bb = cbuf[j + 1024];
        float2 t = cmulc(bb, w);
        float2 a = cbuf[j];
        cbuf[j]        = cadd(a, t);
        cbuf[j + 1024] = csub(a, t);
    }
    __syncthreads();

    float* dst = xfreq + (size_t)b * T_ * N_ + n0;
    const float scl = 1.0f / 2048.0f;
    for (int t = tid; t < 2048; t += 256) {
        float2 v; v.x = cbuf[t].x * scl; v.y = cbuf[t].y * scl;
        *(float2*)(dst + (size_t)t * N_) = v;
    }
}

// ---------------------------------------------------------------------------
// Kernel 3 v14: FFMA2 layer1 (v12 form) + bf16 mma layer2 + per-pair dynamic
// scheduler; x_gcn with LDS.128 operand loads (sA padded to stride 68).
// ---------------------------------------------------------------------------
#define FTH 256
#define HS_S 264
#define W2_S 72
#define NT 32768
// floats: hs 8448 + w2p 2304 + sA 4352 + w1fA 128 + w1fB 128 + gcI 64
//   + gcV 32 + w34 128 + b2 64 + pm 256 + xg/xf/mm/xi 1024 + cst 4
//   + preb 4096 + task 4 = 21032
#define SMEM_BYTES (21032 * 4)

__global__ void __launch_bounds__(FTH, 2) fused_kernel(
    const float* __restrict__ seed, const float* __restrict__ mask,
    const float* __restrict__ xin, const float* __restrict__ xfreq,
    const float* __restrict__ gw1, const float* __restrict__ gw2,
    const float* __restrict__ gb2, const float* __restrict__ gw3,
    const float* __restrict__ gb3,
    const float* __restrict__ gcw1, const float* __restrict__ gcb1,
    const float* __restrict__ gcw2, const float* __restrict__ gcb2,
    float* __restrict__ out_gcn, float* __restrict__ out_imp,
    float* __restrict__ out_comp, float* __restrict__ out_gate)
{
    extern __shared__ float sm[];
    float* hs    = sm;                    // [32][264] bf16x2 (u32)
    float* sW2   = hs    + 32 * HS_S;     // [32][72] bf16x2
    float* sA    = sW2   + 32 * W2_S;     // [64][68] (16B-aligned rows)
    float* sW1fA = sA    + 64 * 68;       // [32]{f0pair,f1pair}
    float* sW1fB = sW1fA + 128;           // [32]{f2pair,f3pair}
    float* sGcI  = sW1fB + 128;           // [16]{w pair, b pair}
    float* sGcV  = sGcI  + 64;            // [32]
    float* sW34  = sGcV  + 32;            // [32]{we pair, wo pair}
    float* sB2   = sW34  + 128;           // [64]
    float* sPm   = sB2   + 64;            // [4][64]
    float* sXg   = sPm   + FTH;
    float* sXf   = sXg   + FTH;
    float* sMm   = sXf   + FTH;
    float* sXi   = sMm   + FTH;
    float* sCst  = sXi   + FTH;           // [4]
    float* sPreb = sCst  + 4;             // [32][64] float2 = 4096
    int*   sTask = (int*)(sPreb + 4096);  // [4]

    int tid = threadIdx.x;

    // ---- stage weights once ----
    for (int i = tid; i < 2048; i += FTH) {
        int kp = i >> 6, j = i & 63;
        ((u32*)sW2)[kp * W2_S + j] = bfpack(gw2[(2 * kp) * 64 + j], gw2[(2 * kp + 1) * 64 + j]);
    }
    for (int i = tid; i < 4096; i += FTH) sA[(i >> 6) * 68 + (i & 63)] = g_adj[i];
    for (int i = tid; i < 2048; i += FTH) ((float2*)sPreb)[i] = g_preb1p[i];
    if (tid < 64) {
        int j = tid;
        float wf0 = gw1[0 * 64 + j] - gw1[4 * 64 + j] - gw1[5 * 64 + j];
        float wf1 = gw1[1 * 64 + j];
        float wf2 = gw1[2 * 64 + j] + gw1[4 * 64 + j];
        float wf3 = gw1[3 * 64 + j] + gw1[5 * 64 + j];
        int p = j >> 1, o = j & 1;
        sW1fA[p * 4 + o]     = wf0;
        sW1fA[p * 4 + 2 + o] = wf1;
        sW1fB[p * 4 + o]     = wf2;
        sW1fB[p * 4 + 2 + o] = wf3;
        sB2[j] = gb2[j];
    }
    if (tid < 16) {
        sGcI[tid * 4 + 0] = gcw1[2 * tid];
        sGcI[tid * 4 + 1] = gcw1[2 * tid + 1];
        sGcI[tid * 4 + 2] = gcb1[2 * tid];
        sGcI[tid * 4 + 3] = gcb1[2 * tid + 1];
    }
    if (tid < 32) {
        sGcV[tid] = gcw2[tid];
        sW34[tid * 4 + 0] = gw3[4 * tid];
        sW34[tid * 4 + 1] = gw3[4 * tid + 2];
        sW34[tid * 4 + 2] = gw3[4 * tid + 1];
        sW34[tid * 4 + 3] = gw3[4 * tid + 3];
    }
    if (tid == 0) { sCst[0] = gcb2[0]; sCst[1] = gb3[0]; sCst[2] = gb3[1]; }
    __syncthreads();

    int el   = tid & 63;
    int pr   = tid >> 6;
    int lane = tid & 31;
    int warp = tid >> 5;
    int m0   = warp * 32;
    int qr   = lane >> 2;
    int qc   = lane & 3;
    int prId = 8 + pr;

    u32* hsu = (u32*)hs;
    const u64* prebp = (const u64*)sPreb;
    const ulonglong2* WA = (const ulonglong2*)sW1fA;
    const ulonglong2* WB = (const ulonglong2*)sW1fB;
    const ulonglong2* gcWB = (const ulonglong2*)sGcI;
    const u64* gcV = (const u64*)sGcV;
    const ulonglong2* w34 = (const ulonglong2*)sW34;

    int task = blockIdx.x * 4 + pr;
    float s_cur = (task < NT) ? seed[task * 64 + el] : 0.f;

    while (task < NT) {
        BARP(prId);

        if ((tid & 63) == 0) sTask[pr] = atomicAdd(&g_tileCtr, 1);

        int gidx = task * 64 + el;
        float s  = s_cur;
        float mm = mask[gidx];
        float xf = xfreq[gidx];
        float xi = xin[gidx];

        // ---- phi(s), packed pairs ----
        u64 sp = pk2(s, s);
        u64 accp = pk2(0.f, 0.f);
        #pragma unroll
        for (int hq = 0; hq < 16; ++hq) {
            ulonglong2 wb = gcWB[hq];
            u64 pre = ffma2(sp, wb.x, wb.y);
            accp = ffma2(gelu2(pre), gcV[hq], accp);
        }
        float p0, p1; upk2(accp, p0, p1);
        sPm[pr * 64 + el] = p0 + p1;
        BARP(prId);

        int ntask = sTask[pr];
        float s_n = (ntask < NT) ? seed[ntask * 64 + el] : 0.f;

        // ---- x_gcn (packed matvec, LDS.128 operands) ----
        u64 xgpA = pk2(0.f, 0.f), xgpB = pk2(0.f, 0.f);
        const ulonglong2* arow2 = (const ulonglong2*)(sA + el * 68);
        const ulonglong2* prow2 = (const ulonglong2*)(sPm + pr * 64);
        #pragma unroll 8
        for (int q = 0; q < 16; ++q) {
            ulonglong2 av = arow2[q];
            ulonglong2 pv = prow2[q];
            xgpA = ffma2(av.x, pv.x, xgpA);
            xgpB = ffma2(av.y, pv.y, xgpB);
        }
        u64 xgp = ffma2(xgpA, pk2(1.f, 1.f), xgpB);
        float xg0, xg1; upk2(xgp, xg0, xg1);
        float xg = xg0 + xg1 + sCst[0];

        sXg[tid] = xg; sXf[tid] = xf; sMm[tid] = mm; sXi[tid] = xi;
        out_gcn[gidx] = xg;

        // ---- layer1: folded 4 features, FFMA2 -> hs bf16x2 k-pairs ----
        u64 u0 = pk2(s, s), u1 = pk2(mm, mm), u2 = pk2(xg, xg), u3 = pk2(xf, xf);
        #pragma unroll
        for (int p = 0; p < 32; ++p) {
            u64 a = prebp[p * 64 + el];
            ulonglong2 wa = WA[p];
            ulonglong2 wb = WB[p];
            a = ffma2(u0, wa.x, a);
            a = ffma2(u1, wa.y, a);
            a = ffma2(u2, wb.x, a);
            a = ffma2(u3, wb.y, a);
            u64 g = gelu2(a);
            float v0, v1; upk2(g, v0, v1);
            hsu[p * HS_S + tid] = bfpack(v0, v1);
        }
        __syncwarp();

        // ---- Phase B: layer2 via bf16 m16n8k16 mma ----
        float acc[2][8][4];
        #pragma unroll
        for (int n8 = 0; n8 < 8; ++n8) {
            int j0 = n8 * 8 + qc * 2;
            float2 bb2 = *(const float2*)(sB2 + j0);
            #pragma unroll
            for (int mt = 0; mt < 2; ++mt) {
                acc[mt][n8][0] = bb2.x; acc[mt][n8][1] = bb2.y;
                acc[mt][n8][2] = bb2.x; acc[mt][n8][3] = bb2.y;
            }
        }

        const u32* w2u = (const u32*)sW2;
        int ar = m0 + qr;
        #pragma unroll
        for (int kt = 0; kt < 4; ++kt) {
            int kp0 = kt * 8 + qc;
            int kp4 = kp0 + 4;
            const u32* h0 = hsu + kp0 * HS_S;
            const u32* h4 = hsu + kp4 * HS_S;
            u32 a00 = h0[ar],      a01 = h0[ar + 8],  a02 = h4[ar],      a03 = h4[ar + 8];
            u32 a10 = h0[ar + 16], a11 = h0[ar + 24], a12 = h4[ar + 16], a13 = h4[ar + 24];
            const u32* b0p = w2u + kp0 * W2_S + qr;
            const u32* b1p = w2u + kp4 * W2_S + qr;
            #pragma unroll
            for (int n8 = 0; n8 < 8; ++n8) {
                u32 b0 = b0p[n8 * 8];
                u32 b1 = b1p[n8 * 8];
                mma_bf16(acc[0][n8], a00, a01, a02, a03, b0, b1);
                mma_bf16(acc[1][n8], a10, a11, a12, a13, b0, b1);
            }
        }

        // ---- epilogue: n8-outer, w34 reused x4 ----
        u64 lg[2][2][2];
        #pragma unroll
        for (int mt = 0; mt < 2; ++mt)
            #pragma unroll
            for (int half = 0; half < 2; ++half) {
                lg[mt][half][0] = pk2(0.f, 0.f);
                lg[mt][half][1] = pk2(0.f, 0.f);
            }
        #pragma unroll
        for (int n8 = 0; n8 < 8; ++n8) {
            ulonglong2 w = w34[n8 * 4 + qc];
            #pragma unroll
            for (int mt = 0; mt < 2; ++mt)
                #pragma unroll
                for (int half = 0; half < 2; ++half) {
                    u64 a = pk2(acc[mt][n8][2 * half], acc[mt][n8][2 * half + 1]);
                    u64 g = gelu2(a);
                    lg[mt][half][0] = ffma2(g, w.x, lg[mt][half][0]);
                    lg[mt][half][1] = ffma2(g, w.y, lg[mt][half][1]);
                }
        }

        #pragma unroll
        for (int mt = 0; mt < 2; ++mt) {
            #pragma unroll
            for (int half = 0; half < 2; ++half) {
                float l0a, l0b, l1a, l1b;
                upk2(lg[mt][half][0], l0a, l0b);
                upk2(lg[mt][half][1], l1a, l1b);
                float lg0 = l0a + l0b, lg1 = l1a + l1b;
                lg0 += __shfl_xor_sync(0xffffffffu, lg0, 1);
                lg0 += __shfl_xor_sync(0xffffffffu, lg0, 2);
                lg1 += __shfl_xor_sync(0xffffffffu, lg1, 1);
                lg1 += __shfl_xor_sync(0xffffffffu, lg1, 2);

                if (qc == half + 2 * mt) {
                    int row = m0 + qr + 8 * half + 16 * mt;
                    int og  = task * 64 + (row & 63);
                    lg0 += sCst[1]; lg1 += sCst[2];
                    float mxv = fmaxf(lg0, lg1);
                    float e0 = __expf(lg0 - mxv), e1 = __expf(lg1 - mxv);
                    float inv = __fdividef(1.0f, e0 + e1);
                    float g0 = e0 * inv, g1 = e1 * inv;
                    float xgr = sXg[row], xfr = sXf[row], mmr = sMm[row], xir = sXi[row];
                    float imputed  = fmaf(g0, xgr, g1 * xfr);
                    float complete = (mmr != 0.f) ? imputed : xir;
                    out_imp[og]  = imputed;
                    out_comp[og] = complete;
                    float2 gv; gv.x = g0; gv.y = g1;
                    *(float2*)(out_gate + (size_t)og * 2) = gv;
                }
            }
        }
        __syncwarp();

        task = ntask;
        s_cur = s_n;
    }
}

// ---------------------------------------------------------------------------
extern "C" void kernel_launch(void* const* d_in, const int* in_sizes, int n_in,
                              void* d_out, int out_size)
{
    const float* x     = (const float*)d_in[0];
    const float* mask  = (const float*)d_in[1];
    const int*   rid   = (const int*)  d_in[2];
    const float* emb   = (const float*)d_in[3];
    const float* gcw1  = (const float*)d_in[4];
    const float* gcb1  = (const float*)d_in[5];
    const float* gcw2  = (const float*)d_in[6];
    const float* gcb2  = (const float*)d_in[7];
    const float* fre   = (const float*)d_in[8];
    const float* fim   = (const float*)d_in[9];
    const float* rtab  = (const float*)d_in[10];
    const float* gw1   = (const float*)d_in[11];
    const float* gb1   = (const float*)d_in[12];
    const float* gw2   = (const float*)d_in[13];
    const float* gb2   = (const float*)d_in[14];
    const float* gw3   = (const float*)d_in[15];
    const float* gb3   = (const float*)d_in[16];
    float* out = (float*)d_out;

    cudaFuncSetAttribute(fused_kernel, cudaFuncAttributeMaxDynamicSharedMemorySize, SMEM_BYTES);

    prep_kernel<<<321, 256>>>(x, mask, emb, rid, rtab, gw1, gb1, fre, fim, out + ADJ_OFF);
    fill_out_kernel<<<256, 256>>>(x, mask, out + SEED_OFF);
    fft_kernel<<<B_ * N_ / 2, 256>>>(out + FREQ_OFF);
    fused_kernel<<<PGRID, FTH, SMEM_BYTES>>>(
        out + SEED_OFF, mask, x, out + FREQ_OFF,
        gw1, gw2, gb2, gw3, gb3,
        gcw1, gcb1, gcw2, gcb2,
        out + GCN_OFF, out + IMP_OFF, out + COMP_OFF, out + GATE_OFF);
}